// round 1
// baseline (speedup 1.0000x reference)
#include <cuda_runtime.h>
#include <cuda_bf16.h>

// Problem constants (fixed shapes for this bench)
#define Cdim 1024
#define Hn   16
#define En   64
#define Mtok 25088          // B*N = 128*196
#define Lseq 3136           // f*N  = 16*196
#define NBGRP 8             // B/f
#define SCALE_Q 0.125f      // e^-0.5 = 64^-0.5
#define EPS_V   1e-6f

// Scratch (static device memory; no runtime allocation)
__device__ float g_q   [(size_t)Mtok * Cdim];
__device__ float g_k   [(size_t)Mtok * Cdim];
__device__ float g_v   [(size_t)Mtok * Cdim];
__device__ float g_attn[(size_t)Mtok * Cdim];
__device__ float g_kv  [NBGRP * Hn * En * En];
__device__ float g_ksum[NBGRP * Hn * En];

// ---------------------------------------------------------------------------
// NT SGEMM: C[m,n] = sum_k A[m,k] * W[n,k], M multiple of 128, N mult of 128,
// K = Cdim. Block tile 128x128, K-tile 8, 256 threads, 8x8 per thread.
// Inner product uses packed fma.rn.f32x2 (FFMA2) for 2x fp32 rate.
// MODE 0: A = x, W = w_qkv (N=3072). Epilogue splits q/k/v, applies relu+scale.
// MODE 1: A = g_attn, W = w_proj (N=1024). Epilogue adds bias, writes out.
// ---------------------------------------------------------------------------
template<int MODE>
__global__ __launch_bounds__(256, 2)
void gemm_nt_kernel(const float* __restrict__ A,
                    const float* __restrict__ W,
                    const float* __restrict__ bias,
                    float* __restrict__ out)
{
    __shared__ float As[8][128];
    __shared__ float Bs[8][128];

    const int tid = threadIdx.x;
    const int tx  = tid & 15;        // 0..15 -> output col group
    const int ty  = tid >> 4;        // 0..15 -> output row group
    const int m0  = blockIdx.y * 128;
    const int n0  = blockIdx.x * 128;

    const int lr = tid >> 1;         // 0..127 load row
    const int lc = (tid & 1) << 2;   // 0 or 4 load col

    const float* Abase = (MODE == 0) ? A : g_attn;
    const float* Ap = Abase + (size_t)(m0 + lr) * Cdim + lc;
    const float* Wp = W     + (size_t)(n0 + lr) * Cdim + lc;

    unsigned long long acc[8][4];
    #pragma unroll
    for (int i = 0; i < 8; i++)
        #pragma unroll
        for (int j = 0; j < 4; j++) acc[i][j] = 0ull;

    // prefetch first tile
    float4 a4 = *(const float4*)(Ap);
    float4 b4 = *(const float4*)(Wp);

    for (int k0 = 0; k0 < Cdim; k0 += 8) {
        __syncthreads();
        As[lc + 0][lr] = a4.x; As[lc + 1][lr] = a4.y;
        As[lc + 2][lr] = a4.z; As[lc + 3][lr] = a4.w;
        Bs[lc + 0][lr] = b4.x; Bs[lc + 1][lr] = b4.y;
        Bs[lc + 2][lr] = b4.z; Bs[lc + 3][lr] = b4.w;
        __syncthreads();

        if (k0 + 8 < Cdim) {   // prefetch next tile (overlap with compute)
            a4 = *(const float4*)(Ap + k0 + 8);
            b4 = *(const float4*)(Wp + k0 + 8);
        }

        #pragma unroll
        for (int k = 0; k < 8; k++) {
            float af[8];
            *(float4*)&af[0] = *(const float4*)&As[k][ty * 8];
            *(float4*)&af[4] = *(const float4*)&As[k][ty * 8 + 4];
            unsigned long long b2[4];
            #pragma unroll
            for (int j = 0; j < 4; j++)
                b2[j] = *(const unsigned long long*)&Bs[k][tx * 8 + j * 2];
            #pragma unroll
            for (int i = 0; i < 8; i++) {
                unsigned long long a2;
                asm("mov.b64 %0, {%1, %1};" : "=l"(a2) : "f"(af[i]));
                #pragma unroll
                for (int j = 0; j < 4; j++)
                    asm("fma.rn.f32x2 %0, %1, %2, %0;"
                        : "+l"(acc[i][j]) : "l"(a2), "l"(b2[j]));
            }
        }
    }

    // unpack accumulators
    float res[8][8];
    #pragma unroll
    for (int i = 0; i < 8; i++)
        #pragma unroll
        for (int j = 0; j < 4; j++) {
            res[i][2 * j]     = __uint_as_float((unsigned)(acc[i][j] & 0xffffffffull));
            res[i][2 * j + 1] = __uint_as_float((unsigned)(acc[i][j] >> 32));
        }

    if (MODE == 0) {
        // qkv split: whole 128-wide tile lies in one of q/k/v (3072 = 3*1024,
        // 1024 % 128 == 0). relu+scale for q,k; raw for v.
        const int s  = n0 >> 10;                 // 0:q 1:k 2:v
        float* dst   = (s == 0) ? g_q : (s == 1) ? g_k : g_v;
        const int r0 = (n0 & 1023) + tx * 8;
        #pragma unroll
        for (int i = 0; i < 8; i++) {
            float v[8];
            #pragma unroll
            for (int j = 0; j < 8; j++) {
                float t = res[i][j];
                if (s < 2) t = fmaxf(t, 0.0f) + SCALE_Q;
                v[j] = t;
            }
            float* p = dst + (size_t)(m0 + ty * 8 + i) * Cdim + r0;
            *(float4*)(p)     = make_float4(v[0], v[1], v[2], v[3]);
            *(float4*)(p + 4) = make_float4(v[4], v[5], v[6], v[7]);
        }
    } else {
        const int nb = n0 + tx * 8;
        float bj[8];
        #pragma unroll
        for (int j = 0; j < 8; j++) bj[j] = bias[nb + j];
        #pragma unroll
        for (int i = 0; i < 8; i++) {
            float* p = out + (size_t)(m0 + ty * 8 + i) * Cdim + nb;
            *(float4*)(p)     = make_float4(res[i][0] + bj[0], res[i][1] + bj[1],
                                            res[i][2] + bj[2], res[i][3] + bj[3]);
            *(float4*)(p + 4) = make_float4(res[i][4] + bj[4], res[i][5] + bj[5],
                                            res[i][6] + bj[6], res[i][7] + bj[7]);
        }
    }
}

// ---------------------------------------------------------------------------
// k_sum[bh][e] = sum over n of k_[bb, n, h, e]
// grid: 128 blocks (one per (b,h)), 256 threads
// ---------------------------------------------------------------------------
__global__ __launch_bounds__(256)
void ksum_kernel()
{
    const int bh = blockIdx.x;
    const int bb = bh >> 4, h = bh & 15;
    const int e    = threadIdx.x & 63;
    const int part = threadIdx.x >> 6;     // 0..3
    float s = 0.0f;
    const size_t base = (size_t)bb * Lseq * Cdim + h * En + e;
    for (int n = part; n < Lseq; n += 4)
        s += g_k[base + (size_t)n * Cdim];
    __shared__ float red[4][64];
    red[part][e] = s;
    __syncthreads();
    if (part == 0)
        g_ksum[bh * En + e] = red[0][e] + red[1][e] + red[2][e] + red[3][e];
}

// ---------------------------------------------------------------------------
// kv[bh][e][d] = sum over n of k_[bb,n,h,e] * v[bb,n,h,d]
// grid: 128 blocks (one per (b,h)), 256 threads, 4x4 per thread
// ---------------------------------------------------------------------------
__global__ __launch_bounds__(256)
void kv_kernel()
{
    __shared__ float sk[64][68];
    __shared__ float sv[64][68];
    const int bh = blockIdx.x;
    const int bb = bh >> 4, h = bh & 15;
    const int tid = threadIdx.x;
    const int tx = tid & 15, ty = tid >> 4;
    float acc[4][4] = {};
    const size_t base = (size_t)bb * Lseq * Cdim + h * En;

    for (int n0 = 0; n0 < Lseq; n0 += 64) {
        __syncthreads();
        #pragma unroll
        for (int i = 0; i < 4; i++) {
            int lin = tid + i * 256;
            int row = lin >> 4;
            int c4  = (lin & 15) << 2;
            size_t g = base + (size_t)(n0 + row) * Cdim + c4;
            *(float4*)&sk[row][c4] = *(const float4*)&g_k[g];
            *(float4*)&sv[row][c4] = *(const float4*)&g_v[g];
        }
        __syncthreads();
        #pragma unroll 4
        for (int n = 0; n < 64; n++) {
            float4 a = *(const float4*)&sk[n][ty * 4];
            float4 b = *(const float4*)&sv[n][tx * 4];
            float av[4] = {a.x, a.y, a.z, a.w};
            float bv[4] = {b.x, b.y, b.z, b.w};
            #pragma unroll
            for (int i = 0; i < 4; i++)
                #pragma unroll
                for (int j = 0; j < 4; j++)
                    acc[i][j] += av[i] * bv[j];
        }
    }
    float* dst = g_kv + bh * (En * En);
    #pragma unroll
    for (int i = 0; i < 4; i++)
        *(float4*)&dst[(ty * 4 + i) * En + tx * 4] =
            make_float4(acc[i][0], acc[i][1], acc[i][2], acc[i][3]);
}

// ---------------------------------------------------------------------------
// out[bb,n,h,d] = (sum_e q_[bb,n,h,e] * kv[bh][e][d]) * z[n]
// z[n] = 1/(dot(q_[n], k_sum) + eps)
// grid: (49 n-tiles of 64, 128 bh), 256 threads, 4x4 per thread
// ---------------------------------------------------------------------------
__global__ __launch_bounds__(256)
void attn_kernel()
{
    __shared__ float sq [64][68];
    __shared__ float skv[64][68];
    __shared__ float sks[64];
    __shared__ float sz [64];
    const int bh = blockIdx.y;
    const int bb = bh >> 4, h = bh & 15;
    const int n0 = blockIdx.x * 64;
    const int tid = threadIdx.x;
    const int tx = tid & 15, ty = tid >> 4;

    #pragma unroll
    for (int i = 0; i < 4; i++) {
        int lin = tid + i * 256;
        int row = lin >> 4;
        int c4  = (lin & 15) << 2;
        *(float4*)&skv[row][c4] = *(const float4*)&g_kv[bh * (En * En) + row * En + c4];
        size_t g = ((size_t)bb * Lseq + n0 + row) * Cdim + h * En + c4;
        *(float4*)&sq[row][c4] = *(const float4*)&g_q[g];
    }
    if (tid < 16)
        *(float4*)&sks[tid * 4] = *(const float4*)&g_ksum[bh * En + tid * 4];
    __syncthreads();

    if (tid < 64) {
        float d = 0.0f;
        #pragma unroll
        for (int e = 0; e < 64; e++) d += sq[tid][e] * sks[e];
        sz[tid] = 1.0f / (d + EPS_V);
    }
    __syncthreads();

    float acc[4][4] = {};
    #pragma unroll 4
    for (int e = 0; e < 64; e++) {
        float a0 = sq[ty * 4 + 0][e];
        float a1 = sq[ty * 4 + 1][e];
        float a2 = sq[ty * 4 + 2][e];
        float a3 = sq[ty * 4 + 3][e];
        float4 b = *(const float4*)&skv[e][tx * 4];
        acc[0][0] += a0 * b.x; acc[0][1] += a0 * b.y; acc[0][2] += a0 * b.z; acc[0][3] += a0 * b.w;
        acc[1][0] += a1 * b.x; acc[1][1] += a1 * b.y; acc[1][2] += a1 * b.z; acc[1][3] += a1 * b.w;
        acc[2][0] += a2 * b.x; acc[2][1] += a2 * b.y; acc[2][2] += a2 * b.z; acc[2][3] += a2 * b.w;
        acc[3][0] += a3 * b.x; acc[3][1] += a3 * b.y; acc[3][2] += a3 * b.z; acc[3][3] += a3 * b.w;
    }

    #pragma unroll
    for (int i = 0; i < 4; i++) {
        float z = sz[ty * 4 + i];
        size_t g = ((size_t)bb * Lseq + n0 + ty * 4 + i) * Cdim + h * En + tx * 4;
        *(float4*)&g_attn[g] =
            make_float4(acc[i][0] * z, acc[i][1] * z, acc[i][2] * z, acc[i][3] * z);
    }
}

// ---------------------------------------------------------------------------
extern "C" void kernel_launch(void* const* d_in, const int* in_sizes, int n_in,
                              void* d_out, int out_size)
{
    const float* x      = (const float*)d_in[0];
    const float* w_qkv  = (const float*)d_in[1];
    const float* w_proj = (const float*)d_in[2];
    const float* b_proj = (const float*)d_in[3];
    // d_in[4] = num_frames (fixed at 16 for this problem)
    float* out = (float*)d_out;

    // 1) qkv = x @ w_qkv^T, split into q_/k_/v with relu+scale fused
    gemm_nt_kernel<0><<<dim3(24, 196), 256>>>(x, w_qkv, nullptr, nullptr);
    // 2) k_sum reduction
    ksum_kernel<<<128, 256>>>();
    // 3) kv = k_^T @ v per (b,h)
    kv_kernel<<<128, 256>>>();
    // 4) out = (q_ @ kv) * z
    attn_kernel<<<dim3(49, 128), 256>>>();
    // 5) final = attn @ w_proj^T + b_proj
    gemm_nt_kernel<1><<<dim3(8, 196), 256>>>(nullptr, w_proj, b_proj, out);
}

// round 3
// speedup vs baseline: 1.7486x; 1.7486x over previous
#include <cuda_runtime.h>
#include <cuda_bf16.h>
#include <cstdint>

// Problem constants
#define Cdim 1024
#define Hn   16
#define En   64
#define Mtok 25088          // B*N
#define Lseq 3136           // f*N
#define NBGRP 8
#define SCALE_Q 0.125f
#define EPS_V   1e-6f

// Scratch (static device memory)
__device__ float g_q   [(size_t)Mtok * Cdim];
__device__ float g_k   [(size_t)Mtok * Cdim];
__device__ float g_v   [(size_t)Mtok * Cdim];
__device__ float g_attn[(size_t)Mtok * Cdim];
__device__ float g_kv  [NBGRP * Hn * En * En];
__device__ float g_ksum[NBGRP * Hn * En];

// ---------------------------------------------------------------------------
// Helpers
// ---------------------------------------------------------------------------
// Split two fp32 into packed bf16x2 hi + bf16x2 lo (x = hi + lo + O(2^-18))
__device__ __forceinline__ void split2(float x, float y, uint32_t& hi, uint32_t& lo) {
    __nv_bfloat16 hx = __float2bfloat16(x);
    __nv_bfloat16 hy = __float2bfloat16(y);
    float lx = x - __bfloat162float(hx);
    float ly = y - __bfloat162float(hy);
    __nv_bfloat16 gx = __float2bfloat16(lx);
    __nv_bfloat16 gy = __float2bfloat16(ly);
    hi = ((uint32_t)__bfloat16_as_ushort(hy) << 16) | (uint32_t)__bfloat16_as_ushort(hx);
    lo = ((uint32_t)__bfloat16_as_ushort(gy) << 16) | (uint32_t)__bfloat16_as_ushort(gx);
}

// mma.sync m16n8k16 row.col f32 += bf16 * bf16
__device__ __forceinline__ void mma16816(float* d, const uint32_t* a,
                                         uint32_t b0, uint32_t b1) {
    asm volatile(
        "mma.sync.aligned.m16n8k16.row.col.f32.bf16.bf16.f32 "
        "{%0,%1,%2,%3}, {%4,%5,%6,%7}, {%8,%9}, {%0,%1,%2,%3};"
        : "+f"(d[0]), "+f"(d[1]), "+f"(d[2]), "+f"(d[3])
        : "r"(a[0]), "r"(a[1]), "r"(a[2]), "r"(a[3]), "r"(b0), "r"(b1));
}

// ---------------------------------------------------------------------------
// Split-BF16 tensor-core NT GEMM: C[m,n] = sum_k A[m,k] * W[n,k]
// Block tile 128x128, K-chunk 32, 256 threads (8 warps as 4(m) x 2(n)),
// warp tile 32(m) x 64(n), micro tile m16n8k16, 3 MMAs per micro (split).
// SMEM: bf16x2 words, row stride 17 words (16 pairs + 1 pad) to spread banks.
// MODE 0: A = x, W = w_qkv (N=3072). Epilogue splits q/k/v, relu+scale.
// MODE 1: A = g_attn, W = w_proj (N=1024). Epilogue adds bias -> out.
// ---------------------------------------------------------------------------
#define ROWW 17                       // words per row (32 bf16 = 16 words + 1 pad)
#define ARR_W (128 * ROWW)            // words per operand array
#define STG_W (4 * ARR_W)             // Ahi, Alo, Bhi, Blo
#define GEMM_SMEM (2 * STG_W * 4)     // bytes, double buffered

template<int MODE>
__global__ __launch_bounds__(256, 1)
void gemm_tc(const float* __restrict__ A, const float* __restrict__ W,
             const float* __restrict__ bias, float* __restrict__ out)
{
    extern __shared__ uint32_t sw[];
    const int tid  = threadIdx.x;
    const int lane = tid & 31;
    const int w    = tid >> 5;
    const int wm   = w & 3;           // warp m group (0..3) -> rows wm*32
    const int wn   = w >> 2;          // warp n group (0..1) -> cols wn*64
    const int m0 = blockIdx.y * 128;
    const int n0 = blockIdx.x * 128;

    const float* Ab = (MODE == 0) ? A : g_attn;

    // per-thread global load coords: 4 float4 per operand per chunk
    // id = tid + i*256 -> row = id>>3 (0..127), quad = id&7 (k offset quad*4)
    float4 pa[4], pb[4];
    #pragma unroll
    for (int i = 0; i < 4; i++) {
        int id = tid + i * 256;
        int row = id >> 3, kq = id & 7;
        pa[i] = *(const float4*)(Ab + (size_t)(m0 + row) * Cdim + kq * 4);
        pb[i] = *(const float4*)(W  + (size_t)(n0 + row) * Cdim + kq * 4);
    }

    float acc[2][8][4];
    #pragma unroll
    for (int mt = 0; mt < 2; mt++)
        #pragma unroll
        for (int nt = 0; nt < 8; nt++)
            #pragma unroll
            for (int r = 0; r < 4; r++) acc[mt][nt][r] = 0.0f;

    const int r4 = lane >> 2;         // 0..7
    const int c4 = lane & 3;          // 0..3

    for (int c = 0; c < 32; c++) {
        const int s = c & 1;
        uint32_t* Ahi = sw + s * STG_W;
        uint32_t* Alo = Ahi + ARR_W;
        uint32_t* Bhi = Ahi + 2 * ARR_W;
        uint32_t* Blo = Ahi + 3 * ARR_W;

        __syncthreads();
        #pragma unroll
        for (int i = 0; i < 4; i++) {
            int id = tid + i * 256;
            int row = id >> 3, kq = id & 7;
            int base = row * ROWW + kq * 2;
            uint32_t h0, l0, h1, l1;
            split2(pa[i].x, pa[i].y, h0, l0);
            split2(pa[i].z, pa[i].w, h1, l1);
            Ahi[base] = h0; Ahi[base + 1] = h1;
            Alo[base] = l0; Alo[base + 1] = l1;
            split2(pb[i].x, pb[i].y, h0, l0);
            split2(pb[i].z, pb[i].w, h1, l1);
            Bhi[base] = h0; Bhi[base + 1] = h1;
            Blo[base] = l0; Blo[base + 1] = l1;
        }
        __syncthreads();

        if (c + 1 < 32) {
            const int k0 = (c + 1) * 32;
            #pragma unroll
            for (int i = 0; i < 4; i++) {
                int id = tid + i * 256;
                int row = id >> 3, kq = id & 7;
                pa[i] = *(const float4*)(Ab + (size_t)(m0 + row) * Cdim + k0 + kq * 4);
                pb[i] = *(const float4*)(W  + (size_t)(n0 + row) * Cdim + k0 + kq * 4);
            }
        }

        #pragma unroll
        for (int ks = 0; ks < 2; ks++) {
            const int kb = ks * 8;
            uint32_t ah[2][4], al[2][4];
            #pragma unroll
            for (int mt = 0; mt < 2; mt++) {
                int rb = (wm * 32 + mt * 16 + r4) * ROWW + kb + c4;
                ah[mt][0] = Ahi[rb];
                ah[mt][1] = Ahi[rb + 8 * ROWW];
                ah[mt][2] = Ahi[rb + 4];
                ah[mt][3] = Ahi[rb + 8 * ROWW + 4];
                al[mt][0] = Alo[rb];
                al[mt][1] = Alo[rb + 8 * ROWW];
                al[mt][2] = Alo[rb + 4];
                al[mt][3] = Alo[rb + 8 * ROWW + 4];
            }
            #pragma unroll
            for (int nt = 0; nt < 8; nt++) {
                int nb = (wn * 64 + nt * 8 + r4) * ROWW + kb + c4;
                uint32_t bh0 = Bhi[nb], bh1 = Bhi[nb + 4];
                uint32_t bl0 = Blo[nb], bl1 = Blo[nb + 4];
                #pragma unroll
                for (int mt = 0; mt < 2; mt++) {
                    mma16816(acc[mt][nt], ah[mt], bh0, bh1);
                    mma16816(acc[mt][nt], ah[mt], bl0, bl1);
                    mma16816(acc[mt][nt], al[mt], bh0, bh1);
                }
            }
        }
    }

    // Epilogue: acc[mt][nt] tile at (wm*32 + mt*16, wn*64 + nt*8)
    // thread holds (r4, c4*2), (r4, c4*2+1), (r4+8, ...), via d0..d3
    if (MODE == 0) {
        const int sN = n0 >> 10;                 // 0:q 1:k 2:v
        float* dst = (sN == 0) ? g_q : (sN == 1) ? g_k : g_v;
        const int colb = (n0 & 1023) + wn * 64;
        #pragma unroll
        for (int mt = 0; mt < 2; mt++) {
            #pragma unroll
            for (int nt = 0; nt < 8; nt++) {
                float v0 = acc[mt][nt][0], v1 = acc[mt][nt][1];
                float v2 = acc[mt][nt][2], v3 = acc[mt][nt][3];
                if (sN < 2) {
                    v0 = fmaxf(v0, 0.0f) + SCALE_Q;
                    v1 = fmaxf(v1, 0.0f) + SCALE_Q;
                    v2 = fmaxf(v2, 0.0f) + SCALE_Q;
                    v3 = fmaxf(v3, 0.0f) + SCALE_Q;
                }
                int m = m0 + wm * 32 + mt * 16 + r4;
                int col = colb + nt * 8 + c4 * 2;
                *(float2*)(dst + (size_t)m * Cdim + col)       = make_float2(v0, v1);
                *(float2*)(dst + (size_t)(m + 8) * Cdim + col) = make_float2(v2, v3);
            }
        }
    } else {
        #pragma unroll
        for (int mt = 0; mt < 2; mt++) {
            #pragma unroll
            for (int nt = 0; nt < 8; nt++) {
                int m = m0 + wm * 32 + mt * 16 + r4;
                int col = n0 + wn * 64 + nt * 8 + c4 * 2;
                float b0 = __ldg(bias + col), b1 = __ldg(bias + col + 1);
                *(float2*)(out + (size_t)m * Cdim + col) =
                    make_float2(acc[mt][nt][0] + b0, acc[mt][nt][1] + b1);
                *(float2*)(out + (size_t)(m + 8) * Cdim + col) =
                    make_float2(acc[mt][nt][2] + b0, acc[mt][nt][3] + b1);
            }
        }
    }
}

// ---------------------------------------------------------------------------
// k_sum[bh][e] = sum over n of k_[bb, n, h, e]
// ---------------------------------------------------------------------------
__global__ __launch_bounds__(256)
void ksum_kernel()
{
    const int bh = blockIdx.x;
    const int bb = bh >> 4, h = bh & 15;
    const int e    = threadIdx.x & 63;
    const int part = threadIdx.x >> 6;
    float s = 0.0f;
    const size_t base = (size_t)bb * Lseq * Cdim + h * En + e;
    for (int n = part; n < Lseq; n += 4)
        s += g_k[base + (size_t)n * Cdim];
    __shared__ float red[4][64];
    red[part][e] = s;
    __syncthreads();
    if (part == 0)
        g_ksum[bh * En + e] = red[0][e] + red[1][e] + red[2][e] + red[3][e];
}

// ---------------------------------------------------------------------------
// kv[bh][e][d] = sum over n of k_[bb,n,h,e] * v[bb,n,h,d]
// ---------------------------------------------------------------------------
__global__ __launch_bounds__(256)
void kv_kernel()
{
    __shared__ float sk[64][68];
    __shared__ float sv[64][68];
    const int bh = blockIdx.x;
    const int bb = bh >> 4, h = bh & 15;
    const int tid = threadIdx.x;
    const int tx = tid & 15, ty = tid >> 4;
    float acc[4][4] = {};
    const size_t base = (size_t)bb * Lseq * Cdim + h * En;

    for (int n0 = 0; n0 < Lseq; n0 += 64) {
        __syncthreads();
        #pragma unroll
        for (int i = 0; i < 4; i++) {
            int lin = tid + i * 256;
            int row = lin >> 4;
            int c4  = (lin & 15) << 2;
            size_t g = base + (size_t)(n0 + row) * Cdim + c4;
            *(float4*)&sk[row][c4] = *(const float4*)&g_k[g];
            *(float4*)&sv[row][c4] = *(const float4*)&g_v[g];
        }
        __syncthreads();
        #pragma unroll 4
        for (int n = 0; n < 64; n++) {
            float4 a = *(const float4*)&sk[n][ty * 4];
            float4 b = *(const float4*)&sv[n][tx * 4];
            float av[4] = {a.x, a.y, a.z, a.w};
            float bv[4] = {b.x, b.y, b.z, b.w};
            #pragma unroll
            for (int i = 0; i < 4; i++)
                #pragma unroll
                for (int j = 0; j < 4; j++)
                    acc[i][j] += av[i] * bv[j];
        }
    }
    float* dst = g_kv + bh * (En * En);
    #pragma unroll
    for (int i = 0; i < 4; i++)
        *(float4*)&dst[(ty * 4 + i) * En + tx * 4] =
            make_float4(acc[i][0], acc[i][1], acc[i][2], acc[i][3]);
}

// ---------------------------------------------------------------------------
// out[bb,n,h,d] = (sum_e q_[bb,n,h,e] * kv[bh][e][d]) * z[n]
// ---------------------------------------------------------------------------
__global__ __launch_bounds__(256)
void attn_kernel()
{
    __shared__ float sq [64][68];
    __shared__ float skv[64][68];
    __shared__ float sks[64];
    __shared__ float sz [64];
    const int bh = blockIdx.y;
    const int bb = bh >> 4, h = bh & 15;
    const int n0 = blockIdx.x * 64;
    const int tid = threadIdx.x;
    const int tx = tid & 15, ty = tid >> 4;

    #pragma unroll
    for (int i = 0; i < 4; i++) {
        int lin = tid + i * 256;
        int row = lin >> 4;
        int c4  = (lin & 15) << 2;
        *(float4*)&skv[row][c4] = *(const float4*)&g_kv[bh * (En * En) + row * En + c4];
        size_t g = ((size_t)bb * Lseq + n0 + row) * Cdim + h * En + c4;
        *(float4*)&sq[row][c4] = *(const float4*)&g_q[g];
    }
    if (tid < 16)
        *(float4*)&sks[tid * 4] = *(const float4*)&g_ksum[bh * En + tid * 4];
    __syncthreads();

    if (tid < 64) {
        float d = 0.0f;
        #pragma unroll
        for (int e = 0; e < 64; e++) d += sq[tid][e] * sks[e];
        sz[tid] = 1.0f / (d + EPS_V);
    }
    __syncthreads();

    float acc[4][4] = {};
    #pragma unroll 4
    for (int e = 0; e < 64; e++) {
        float a0 = sq[ty * 4 + 0][e];
        float a1 = sq[ty * 4 + 1][e];
        float a2 = sq[ty * 4 + 2][e];
        float a3 = sq[ty * 4 + 3][e];
        float4 b = *(const float4*)&skv[e][tx * 4];
        acc[0][0] += a0 * b.x; acc[0][1] += a0 * b.y; acc[0][2] += a0 * b.z; acc[0][3] += a0 * b.w;
        acc[1][0] += a1 * b.x; acc[1][1] += a1 * b.y; acc[1][2] += a1 * b.z; acc[1][3] += a1 * b.w;
        acc[2][0] += a2 * b.x; acc[2][1] += a2 * b.y; acc[2][2] += a2 * b.z; acc[2][3] += a2 * b.w;
        acc[3][0] += a3 * b.x; acc[3][1] += a3 * b.y; acc[3][2] += a3 * b.z; acc[3][3] += a3 * b.w;
    }

    #pragma unroll
    for (int i = 0; i < 4; i++) {
        float z = sz[ty * 4 + i];
        size_t g = ((size_t)bb * Lseq + n0 + ty * 4 + i) * Cdim + h * En + tx * 4;
        *(float4*)&g_attn[g] =
            make_float4(acc[i][0] * z, acc[i][1] * z, acc[i][2] * z, acc[i][3] * z);
    }
}

// ---------------------------------------------------------------------------
extern "C" void kernel_launch(void* const* d_in, const int* in_sizes, int n_in,
                              void* d_out, int out_size)
{
    const float* x      = (const float*)d_in[0];
    const float* w_qkv  = (const float*)d_in[1];
    const float* w_proj = (const float*)d_in[2];
    const float* b_proj = (const float*)d_in[3];
    float* out = (float*)d_out;

    cudaFuncSetAttribute(gemm_tc<0>, cudaFuncAttributeMaxDynamicSharedMemorySize, GEMM_SMEM);
    cudaFuncSetAttribute(gemm_tc<1>, cudaFuncAttributeMaxDynamicSharedMemorySize, GEMM_SMEM);

    // 1) qkv = x @ w_qkv^T  (split-bf16 tensor cores), fused q/k/v split + relu+scale
    gemm_tc<0><<<dim3(24, 196), 256, GEMM_SMEM>>>(x, w_qkv, nullptr, nullptr);
    // 2) k_sum
    ksum_kernel<<<128, 256>>>();
    // 3) kv = k_^T @ v
    kv_kernel<<<128, 256>>>();
    // 4) out = (q_ @ kv) * z
    attn_kernel<<<dim3(49, 128), 256>>>();
    // 5) final = attn @ w_proj^T + b_proj
    gemm_tc<1><<<dim3(8, 196), 256, GEMM_SMEM>>>(nullptr, w_proj, b_proj, out);
}

// round 4
// speedup vs baseline: 2.2374x; 1.2795x over previous
#include <cuda_runtime.h>
#include <cuda_bf16.h>
#include <cstdint>

// Problem constants
#define Cdim 1024
#define Hn   16
#define En   64
#define Mtok 25088          // B*N
#define Lseq 3136           // f*N
#define NBGRP 8
#define SCALE_Q 0.125f
#define EPS_V   1e-6f

// Scratch (static device memory)
__device__ float g_q[(size_t)Mtok * Cdim];
__device__ float g_k[(size_t)Mtok * Cdim];
__device__ float g_v[(size_t)Mtok * Cdim];
__device__ float g_kv  [NBGRP * Hn * En * En];
__device__ float g_ksum[NBGRP * Hn * En];
// bf16 hi/lo pairs (stored as packed uint32 = 2 bf16)
__device__ uint32_t g_xhi[(size_t)Mtok * Cdim / 2];
__device__ uint32_t g_xlo[(size_t)Mtok * Cdim / 2];
__device__ uint32_t g_ahi[(size_t)Mtok * Cdim / 2];
__device__ uint32_t g_alo[(size_t)Mtok * Cdim / 2];
__device__ uint32_t g_wqhi[3072 * Cdim / 2];
__device__ uint32_t g_wqlo[3072 * Cdim / 2];
__device__ uint32_t g_wphi[Cdim * Cdim / 2];
__device__ uint32_t g_wplo[Cdim * Cdim / 2];

// ---------------------------------------------------------------------------
// Helpers
// ---------------------------------------------------------------------------
__device__ __forceinline__ void split2(float x, float y, uint32_t& hi, uint32_t& lo) {
    __nv_bfloat16 hx = __float2bfloat16(x);
    __nv_bfloat16 hy = __float2bfloat16(y);
    float lx = x - __bfloat162float(hx);
    float ly = y - __bfloat162float(hy);
    __nv_bfloat16 gx = __float2bfloat16(lx);
    __nv_bfloat16 gy = __float2bfloat16(ly);
    hi = ((uint32_t)__bfloat16_as_ushort(hy) << 16) | (uint32_t)__bfloat16_as_ushort(hx);
    lo = ((uint32_t)__bfloat16_as_ushort(gy) << 16) | (uint32_t)__bfloat16_as_ushort(gx);
}

__device__ __forceinline__ uint32_t smem_u32(const void* p) {
    uint32_t a;
    asm("{ .reg .u64 t; cvta.to.shared.u64 t, %1; cvt.u32.u64 %0, t; }" : "=r"(a) : "l"(p));
    return a;
}

__device__ __forceinline__ void mma16816(float* d, const uint32_t* a,
                                         uint32_t b0, uint32_t b1) {
    asm volatile(
        "mma.sync.aligned.m16n8k16.row.col.f32.bf16.bf16.f32 "
        "{%0,%1,%2,%3}, {%4,%5,%6,%7}, {%8,%9}, {%0,%1,%2,%3};"
        : "+f"(d[0]), "+f"(d[1]), "+f"(d[2]), "+f"(d[3])
        : "r"(a[0]), "r"(a[1]), "r"(a[2]), "r"(a[3]), "r"(b0), "r"(b1));
}

__device__ __forceinline__ void ldsm4(uint32_t addr, uint32_t* r) {
    asm volatile("ldmatrix.sync.aligned.m8n8.x4.shared.b16 {%0,%1,%2,%3}, [%4];"
                 : "=r"(r[0]), "=r"(r[1]), "=r"(r[2]), "=r"(r[3]) : "r"(addr));
}

#define CP16(dst, src) \
    asm volatile("cp.async.cg.shared.global [%0], [%1], 16;" :: "r"(dst), "l"(src))
#define CP_COMMIT() asm volatile("cp.async.commit_group;" ::: "memory")
#define CP_WAIT1()  asm volatile("cp.async.wait_group 1;" ::: "memory")

// ---------------------------------------------------------------------------
// fp32 -> bf16 hi/lo conversion kernel
// ---------------------------------------------------------------------------
__global__ __launch_bounds__(256)
void conv_kernel(const float4* __restrict__ src, uint32_t* __restrict__ hi,
                 uint32_t* __restrict__ lo, int n4)
{
    int i = blockIdx.x * blockDim.x + threadIdx.x;
    if (i < n4) {
        float4 x = src[i];
        uint32_t h0, l0, h1, l1;
        split2(x.x, x.y, h0, l0);
        split2(x.z, x.w, h1, l1);
        *(uint2*)&hi[i * 2] = make_uint2(h0, h1);
        *(uint2*)&lo[i * 2] = make_uint2(l0, l1);
    }
}

// ---------------------------------------------------------------------------
// Split-BF16 tensor-core NT GEMM: C[m,n] = sum_k A[m,k] * W[n,k]
// Inputs pre-converted to bf16 hi/lo. Block 128x128, K-chunk 32, 256 threads
// (8 warps = 4m x 2n), warp tile 32x64, cp.async 3-stage, ldmatrix fragments,
// 3 MMAs per micro tile (hi*hi + hi*lo + lo*hi).
// MODE 0: epilogue splits q/k/v with relu+scale. MODE 1: bias -> out.
// ---------------------------------------------------------------------------
#define PITCH 80                      // bytes per 32-bf16 row (64 + 16 pad)
#define ARR_B (128 * PITCH)           // 10240 bytes per operand array
#define STG_B (4 * ARR_B)             // Ahi, Alo, Bhi, Blo = 40960
#define NSTG 3
#define GEMM_SMEM (NSTG * STG_B)      // 122880

template<int MODE>
__global__ __launch_bounds__(256, 1)
void gemm_tc(const __nv_bfloat16* __restrict__ Ahi_g,
             const __nv_bfloat16* __restrict__ Alo_g,
             const __nv_bfloat16* __restrict__ Whi_g,
             const __nv_bfloat16* __restrict__ Wlo_g,
             const float* __restrict__ bias, float* __restrict__ out)
{
    extern __shared__ __align__(128) char smem[];
    const uint32_t sbase = smem_u32(smem);
    const int tid  = threadIdx.x;
    const int lane = tid & 31;
    const int w    = tid >> 5;
    const int wm   = w & 3;
    const int wn   = w >> 2;
    const int m0 = blockIdx.y * 128;
    const int n0 = blockIdx.x * 128;

    // cp.async thread mapping: id -> row = id>>2 (0..127), quad = id&3
    const int r0a = tid >> 2, q0 = (tid & 3);
    const int r1a = (tid + 256) >> 2, q1 = ((tid + 256) & 3);

    // ldmatrix lane address components
    const int a_row = (lane & 7) + ((lane >> 3) & 1) * 8;
    const int a_kh  = ((lane >> 4) & 1) * 16;
    const int b_row = (lane & 7) + (lane >> 4) * 8;
    const int b_kh  = ((lane >> 3) & 1) * 16;

    auto issue = [&](int c) {
        const int st = (c % NSTG) * STG_B;
        const int k0 = c * 32;
        const uint32_t dA = sbase + st;
        const uint32_t dB = sbase + st + 2 * ARR_B;
        {   // A rows
            size_t g0 = (size_t)(m0 + r0a) * Cdim + k0 + q0 * 8;
            size_t g1 = (size_t)(m0 + r1a) * Cdim + k0 + q1 * 8;
            CP16(dA + r0a * PITCH + q0 * 16, Ahi_g + g0);
            CP16(dA + ARR_B + r0a * PITCH + q0 * 16, Alo_g + g0);
            CP16(dA + r1a * PITCH + q1 * 16, Ahi_g + g1);
            CP16(dA + ARR_B + r1a * PITCH + q1 * 16, Alo_g + g1);
        }
        {   // B rows
            size_t g0 = (size_t)(n0 + r0a) * Cdim + k0 + q0 * 8;
            size_t g1 = (size_t)(n0 + r1a) * Cdim + k0 + q1 * 8;
            CP16(dB + r0a * PITCH + q0 * 16, Whi_g + g0);
            CP16(dB + ARR_B + r0a * PITCH + q0 * 16, Wlo_g + g0);
            CP16(dB + r1a * PITCH + q1 * 16, Whi_g + g1);
            CP16(dB + ARR_B + r1a * PITCH + q1 * 16, Wlo_g + g1);
        }
    };

    float acc[2][8][4];
    #pragma unroll
    for (int mt = 0; mt < 2; mt++)
        #pragma unroll
        for (int nt = 0; nt < 8; nt++)
            #pragma unroll
            for (int r = 0; r < 4; r++) acc[mt][nt][r] = 0.0f;

    issue(0); CP_COMMIT();
    issue(1); CP_COMMIT();

    for (int c = 0; c < 32; c++) {
        CP_WAIT1();
        __syncthreads();
        if (c + 2 < 32) issue(c + 2);
        CP_COMMIT();

        const uint32_t st = sbase + (c % NSTG) * STG_B;
        const uint32_t sAhi = st, sAlo = st + ARR_B;
        const uint32_t sBhi = st + 2 * ARR_B, sBlo = st + 3 * ARR_B;

        #pragma unroll
        for (int ks = 0; ks < 2; ks++) {
            const int kb = ks * 32;   // byte offset of k16 block
            uint32_t ah[2][4], al[2][4];
            #pragma unroll
            for (int mt = 0; mt < 2; mt++) {
                uint32_t ra = (wm * 32 + mt * 16 + a_row) * PITCH + kb + a_kh;
                ldsm4(sAhi + ra, ah[mt]);
                ldsm4(sAlo + ra, al[mt]);
            }
            uint32_t bh[4][4], bl[4][4];
            #pragma unroll
            for (int bt = 0; bt < 4; bt++) {
                uint32_t rb = (wn * 64 + bt * 16 + b_row) * PITCH + kb + b_kh;
                ldsm4(sBhi + rb, bh[bt]);
                ldsm4(sBlo + rb, bl[bt]);
            }
            #pragma unroll
            for (int bt = 0; bt < 4; bt++) {
                #pragma unroll
                for (int half = 0; half < 2; half++) {
                    const int nt = bt * 2 + half;
                    uint32_t bh0 = bh[bt][half * 2], bh1 = bh[bt][half * 2 + 1];
                    uint32_t bl0 = bl[bt][half * 2], bl1 = bl[bt][half * 2 + 1];
                    #pragma unroll
                    for (int mt = 0; mt < 2; mt++) {
                        mma16816(acc[mt][nt], ah[mt], bh0, bh1);
                        mma16816(acc[mt][nt], ah[mt], bl0, bl1);
                        mma16816(acc[mt][nt], al[mt], bh0, bh1);
                    }
                }
            }
        }
    }

    // Epilogue
    const int r4 = lane >> 2, c4 = lane & 3;
    if (MODE == 0) {
        const int sN = n0 >> 10;                 // 0:q 1:k 2:v
        float* dst = (sN == 0) ? g_q : (sN == 1) ? g_k : g_v;
        const int colb = (n0 & 1023) + wn * 64;
        #pragma unroll
        for (int mt = 0; mt < 2; mt++) {
            #pragma unroll
            for (int nt = 0; nt < 8; nt++) {
                float v0 = acc[mt][nt][0], v1 = acc[mt][nt][1];
                float v2 = acc[mt][nt][2], v3 = acc[mt][nt][3];
                if (sN < 2) {
                    v0 = fmaxf(v0, 0.0f) + SCALE_Q;
                    v1 = fmaxf(v1, 0.0f) + SCALE_Q;
                    v2 = fmaxf(v2, 0.0f) + SCALE_Q;
                    v3 = fmaxf(v3, 0.0f) + SCALE_Q;
                }
                int m = m0 + wm * 32 + mt * 16 + r4;
                int col = colb + nt * 8 + c4 * 2;
                *(float2*)(dst + (size_t)m * Cdim + col)       = make_float2(v0, v1);
                *(float2*)(dst + (size_t)(m + 8) * Cdim + col) = make_float2(v2, v3);
            }
        }
    } else {
        #pragma unroll
        for (int mt = 0; mt < 2; mt++) {
            #pragma unroll
            for (int nt = 0; nt < 8; nt++) {
                int m = m0 + wm * 32 + mt * 16 + r4;
                int col = n0 + wn * 64 + nt * 8 + c4 * 2;
                float b0 = __ldg(bias + col), b1 = __ldg(bias + col + 1);
                *(float2*)(out + (size_t)m * Cdim + col) =
                    make_float2(acc[mt][nt][0] + b0, acc[mt][nt][1] + b1);
                *(float2*)(out + (size_t)(m + 8) * Cdim + col) =
                    make_float2(acc[mt][nt][2] + b0, acc[mt][nt][3] + b1);
            }
        }
    }
}

// ---------------------------------------------------------------------------
// k_sum[bh][e] = sum over n of k_[bb, n, h, e]
// ---------------------------------------------------------------------------
__global__ __launch_bounds__(256)
void ksum_kernel()
{
    const int bh = blockIdx.x;
    const int bb = bh >> 4, h = bh & 15;
    const int e    = threadIdx.x & 63;
    const int part = threadIdx.x >> 6;
    float s = 0.0f;
    const size_t base = (size_t)bb * Lseq * Cdim + h * En + e;
    for (int n = part; n < Lseq; n += 4)
        s += g_k[base + (size_t)n * Cdim];
    __shared__ float red[4][64];
    red[part][e] = s;
    __syncthreads();
    if (part == 0)
        g_ksum[bh * En + e] = red[0][e] + red[1][e] + red[2][e] + red[3][e];
}

// ---------------------------------------------------------------------------
// kv[bh][e][d] = sum over n of k_[bb,n,h,e] * v[bb,n,h,d]
// ---------------------------------------------------------------------------
__global__ __launch_bounds__(256)
void kv_kernel()
{
    __shared__ float sk[64][68];
    __shared__ float sv[64][68];
    const int bh = blockIdx.x;
    const int bb = bh >> 4, h = bh & 15;
    const int tid = threadIdx.x;
    const int tx = tid & 15, ty = tid >> 4;
    float acc[4][4] = {};
    const size_t base = (size_t)bb * Lseq * Cdim + h * En;

    for (int n0 = 0; n0 < Lseq; n0 += 64) {
        __syncthreads();
        #pragma unroll
        for (int i = 0; i < 4; i++) {
            int lin = tid + i * 256;
            int row = lin >> 4;
            int c4  = (lin & 15) << 2;
            size_t g = base + (size_t)(n0 + row) * Cdim + c4;
            *(float4*)&sk[row][c4] = *(const float4*)&g_k[g];
            *(float4*)&sv[row][c4] = *(const float4*)&g_v[g];
        }
        __syncthreads();
        #pragma unroll 4
        for (int n = 0; n < 64; n++) {
            float4 a = *(const float4*)&sk[n][ty * 4];
            float4 b = *(const float4*)&sv[n][tx * 4];
            float av[4] = {a.x, a.y, a.z, a.w};
            float bv[4] = {b.x, b.y, b.z, b.w};
            #pragma unroll
            for (int i = 0; i < 4; i++)
                #pragma unroll
                for (int j = 0; j < 4; j++)
                    acc[i][j] += av[i] * bv[j];
        }
    }
    float* dst = g_kv + bh * (En * En);
    #pragma unroll
    for (int i = 0; i < 4; i++)
        *(float4*)&dst[(ty * 4 + i) * En + tx * 4] =
            make_float4(acc[i][0], acc[i][1], acc[i][2], acc[i][3]);
}

// ---------------------------------------------------------------------------
// out[bb,n,h,d] = (sum_e q_[bb,n,h,e] * kv[bh][e][d]) * z[n]
// Writes result directly as bf16 hi/lo (input to GEMM2).
// ---------------------------------------------------------------------------
__global__ __launch_bounds__(256)
void attn_kernel()
{
    __shared__ float sq [64][68];
    __shared__ float skv[64][68];
    __shared__ float sks[64];
    __shared__ float sz [64];
    const int bh = blockIdx.y;
    const int bb = bh >> 4, h = bh & 15;
    const int n0 = blockIdx.x * 64;
    const int tid = threadIdx.x;
    const int tx = tid & 15, ty = tid >> 4;

    #pragma unroll
    for (int i = 0; i < 4; i++) {
        int lin = tid + i * 256;
        int row = lin >> 4;
        int c4  = (lin & 15) << 2;
        *(float4*)&skv[row][c4] = *(const float4*)&g_kv[bh * (En * En) + row * En + c4];
        size_t g = ((size_t)bb * Lseq + n0 + row) * Cdim + h * En + c4;
        *(float4*)&sq[row][c4] = *(const float4*)&g_q[g];
    }
    if (tid < 16)
        *(float4*)&sks[tid * 4] = *(const float4*)&g_ksum[bh * En + tid * 4];
    __syncthreads();

    if (tid < 64) {
        float d = 0.0f;
        #pragma unroll
        for (int e = 0; e < 64; e++) d += sq[tid][e] * sks[e];
        sz[tid] = 1.0f / (d + EPS_V);
    }
    __syncthreads();

    float acc[4][4] = {};
    #pragma unroll 4
    for (int e = 0; e < 64; e++) {
        float a0 = sq[ty * 4 + 0][e];
        float a1 = sq[ty * 4 + 1][e];
        float a2 = sq[ty * 4 + 2][e];
        float a3 = sq[ty * 4 + 3][e];
        float4 b = *(const float4*)&skv[e][tx * 4];
        acc[0][0] += a0 * b.x; acc[0][1] += a0 * b.y; acc[0][2] += a0 * b.z; acc[0][3] += a0 * b.w;
        acc[1][0] += a1 * b.x; acc[1][1] += a1 * b.y; acc[1][2] += a1 * b.z; acc[1][3] += a1 * b.w;
        acc[2][0] += a2 * b.x; acc[2][1] += a2 * b.y; acc[2][2] += a2 * b.z; acc[2][3] += a2 * b.w;
        acc[3][0] += a3 * b.x; acc[3][1] += a3 * b.y; acc[3][2] += a3 * b.z; acc[3][3] += a3 * b.w;
    }

    #pragma unroll
    for (int i = 0; i < 4; i++) {
        float z = sz[ty * 4 + i];
        float v0 = acc[i][0] * z, v1 = acc[i][1] * z;
        float v2 = acc[i][2] * z, v3 = acc[i][3] * z;
        uint32_t h0, l0, h1, l1;
        split2(v0, v1, h0, l0);
        split2(v2, v3, h1, l1);
        size_t g = ((size_t)bb * Lseq + n0 + ty * 4 + i) * Cdim + h * En + tx * 4;
        *(uint2*)&g_ahi[g >> 1] = make_uint2(h0, h1);
        *(uint2*)&g_alo[g >> 1] = make_uint2(l0, l1);
    }
}

// ---------------------------------------------------------------------------
extern "C" void kernel_launch(void* const* d_in, const int* in_sizes, int n_in,
                              void* d_out, int out_size)
{
    const float* x      = (const float*)d_in[0];
    const float* w_qkv  = (const float*)d_in[1];
    const float* w_proj = (const float*)d_in[2];
    const float* b_proj = (const float*)d_in[3];
    float* out = (float*)d_out;

    static bool attr_done = false;
    if (!attr_done) {
        cudaFuncSetAttribute(gemm_tc<0>, cudaFuncAttributeMaxDynamicSharedMemorySize, GEMM_SMEM);
        cudaFuncSetAttribute(gemm_tc<1>, cudaFuncAttributeMaxDynamicSharedMemorySize, GEMM_SMEM);
        attr_done = true;
    }

    uint32_t *xhi, *xlo, *ahi, *alo, *wqhi, *wqlo, *wphi, *wplo;
    cudaGetSymbolAddress((void**)&xhi,  g_xhi);
    cudaGetSymbolAddress((void**)&xlo,  g_xlo);
    cudaGetSymbolAddress((void**)&ahi,  g_ahi);
    cudaGetSymbolAddress((void**)&alo,  g_alo);
    cudaGetSymbolAddress((void**)&wqhi, g_wqhi);
    cudaGetSymbolAddress((void**)&wqlo, g_wqlo);
    cudaGetSymbolAddress((void**)&wphi, g_wphi);
    cudaGetSymbolAddress((void**)&wplo, g_wplo);

    // 0) fp32 -> bf16 hi/lo conversions
    {
        int n4 = Mtok * (Cdim / 4);
        conv_kernel<<<(n4 + 255) / 256, 256>>>((const float4*)x, xhi, xlo, n4);
        n4 = 3072 * Cdim / 4;
        conv_kernel<<<(n4 + 255) / 256, 256>>>((const float4*)w_qkv, wqhi, wqlo, n4);
        n4 = Cdim * Cdim / 4;
        conv_kernel<<<(n4 + 255) / 256, 256>>>((const float4*)w_proj, wphi, wplo, n4);
    }

    // 1) qkv = x @ w_qkv^T (tensor cores), fused q/k/v split + relu+scale
    gemm_tc<0><<<dim3(24, 196), 256, GEMM_SMEM>>>(
        (const __nv_bfloat16*)xhi, (const __nv_bfloat16*)xlo,
        (const __nv_bfloat16*)wqhi, (const __nv_bfloat16*)wqlo, nullptr, nullptr);
    // 2) k_sum
    ksum_kernel<<<128, 256>>>();
    // 3) kv = k_^T @ v
    kv_kernel<<<128, 256>>>();
    // 4) out = (q_ @ kv) * z  -> bf16 hi/lo
    attn_kernel<<<dim3(49, 128), 256>>>();
    // 5) final = attn @ w_proj^T + b_proj
    gemm_tc<1><<<dim3(8, 196), 256, GEMM_SMEM>>>(
        (const __nv_bfloat16*)ahi, (const __nv_bfloat16*)alo,
        (const __nv_bfloat16*)wphi, (const __nv_bfloat16*)wplo, b_proj, out);
}

// round 5
// speedup vs baseline: 2.4333x; 1.0876x over previous
#include <cuda_runtime.h>
#include <cuda_bf16.h>
#include <cstdint>

// Problem constants
#define Cdim 1024
#define Hn   16
#define En   64
#define Mtok 25088          // B*N
#define Lseq 3136           // f*N
#define NBGRP 8
#define SCALE_Q 0.125f
#define EPS_V   1e-6f

// Scratch (static device memory)
__device__ float g_q[(size_t)Mtok * Cdim];
__device__ float g_k[(size_t)Mtok * Cdim];
__device__ float g_v[(size_t)Mtok * Cdim];
__device__ float g_kv  [NBGRP * Hn * En * En];
__device__ float g_ksum[NBGRP * Hn * En];
// bf16 hi/lo pairs (stored as packed uint32 = 2 bf16)
__device__ uint32_t g_xhi[(size_t)Mtok * Cdim / 2];
__device__ uint32_t g_xlo[(size_t)Mtok * Cdim / 2];
__device__ uint32_t g_ahi[(size_t)Mtok * Cdim / 2];
__device__ uint32_t g_alo[(size_t)Mtok * Cdim / 2];
__device__ uint32_t g_wqhi[3072 * Cdim / 2];
__device__ uint32_t g_wqlo[3072 * Cdim / 2];
__device__ uint32_t g_wphi[Cdim * Cdim / 2];
__device__ uint32_t g_wplo[Cdim * Cdim / 2];

// ---------------------------------------------------------------------------
// Helpers
// ---------------------------------------------------------------------------
__device__ __forceinline__ void split2(float x, float y, uint32_t& hi, uint32_t& lo) {
    __nv_bfloat16 hx = __float2bfloat16(x);
    __nv_bfloat16 hy = __float2bfloat16(y);
    float lx = x - __bfloat162float(hx);
    float ly = y - __bfloat162float(hy);
    __nv_bfloat16 gx = __float2bfloat16(lx);
    __nv_bfloat16 gy = __float2bfloat16(ly);
    hi = ((uint32_t)__bfloat16_as_ushort(hy) << 16) | (uint32_t)__bfloat16_as_ushort(hx);
    lo = ((uint32_t)__bfloat16_as_ushort(gy) << 16) | (uint32_t)__bfloat16_as_ushort(gx);
}

__device__ __forceinline__ uint32_t smem_u32(const void* p) {
    uint32_t a;
    asm("{ .reg .u64 t; cvta.to.shared.u64 t, %1; cvt.u32.u64 %0, t; }" : "=r"(a) : "l"(p));
    return a;
}

__device__ __forceinline__ void mma16816(float* d, const uint32_t* a,
                                         uint32_t b0, uint32_t b1) {
    asm volatile(
        "mma.sync.aligned.m16n8k16.row.col.f32.bf16.bf16.f32 "
        "{%0,%1,%2,%3}, {%4,%5,%6,%7}, {%8,%9}, {%0,%1,%2,%3};"
        : "+f"(d[0]), "+f"(d[1]), "+f"(d[2]), "+f"(d[3])
        : "r"(a[0]), "r"(a[1]), "r"(a[2]), "r"(a[3]), "r"(b0), "r"(b1));
}

__device__ __forceinline__ void ldsm4(uint32_t addr, uint32_t* r) {
    asm volatile("ldmatrix.sync.aligned.m8n8.x4.shared.b16 {%0,%1,%2,%3}, [%4];"
                 : "=r"(r[0]), "=r"(r[1]), "=r"(r[2]), "=r"(r[3]) : "r"(addr));
}

#define CP16(dst, src) \
    asm volatile("cp.async.cg.shared.global [%0], [%1], 16;" :: "r"(dst), "l"(src))
#define CP_COMMIT() asm volatile("cp.async.commit_group;" ::: "memory")
#define CP_WAIT1()  asm volatile("cp.async.wait_group 1;" ::: "memory")

// ---------------------------------------------------------------------------
// fp32 -> bf16 hi/lo conversion kernel
// ---------------------------------------------------------------------------
__global__ __launch_bounds__(256)
void conv_kernel(const float4* __restrict__ src, uint32_t* __restrict__ hi,
                 uint32_t* __restrict__ lo, int n4)
{
    int i = blockIdx.x * blockDim.x + threadIdx.x;
    if (i < n4) {
        float4 x = src[i];
        uint32_t h0, l0, h1, l1;
        split2(x.x, x.y, h0, l0);
        split2(x.z, x.w, h1, l1);
        *(uint2*)&hi[i * 2] = make_uint2(h0, h1);
        *(uint2*)&lo[i * 2] = make_uint2(l0, l1);
    }
}

// ---------------------------------------------------------------------------
// Split-BF16 tensor-core NT GEMM: C[m,n] = sum_k A[m,k] * W[n,k]
// Block tile 64(M)x128(N), K-chunk 32, 128 threads (4 warps = 2m x 2n),
// warp tile 32x64, cp.async 3-stage, ldmatrix fragments, 3 MMAs per micro.
// Small CTA + 92KB smem -> 2 CTAs/SM so sync bubbles overlap across CTAs.
// MODE 0: epilogue splits q/k/v with relu+scale. MODE 1: bias -> out.
// ---------------------------------------------------------------------------
#define PITCH 80                      // bytes per 32-bf16 row (64 + 16 pad)
#define ARR_A (64 * PITCH)            // 5120 bytes per A operand array
#define ARR_BB (128 * PITCH)          // 10240 bytes per B operand array
#define STG_B (2 * ARR_A + 2 * ARR_BB)  // 30720
#define NSTG 3
#define GEMM_SMEM (NSTG * STG_B)      // 92160

template<int MODE>
__global__ __launch_bounds__(128, 2)
void gemm_tc(const __nv_bfloat16* __restrict__ Ahi_g,
             const __nv_bfloat16* __restrict__ Alo_g,
             const __nv_bfloat16* __restrict__ Whi_g,
             const __nv_bfloat16* __restrict__ Wlo_g,
             const float* __restrict__ bias, float* __restrict__ out)
{
    extern __shared__ __align__(128) char smem[];
    const uint32_t sbase = smem_u32(smem);
    const int tid  = threadIdx.x;
    const int lane = tid & 31;
    const int w    = tid >> 5;        // 0..3
    const int wm   = w & 1;           // m group -> rows wm*32
    const int wn   = w >> 1;          // n group -> cols wn*64
    const int m0 = blockIdx.y * 64;
    const int n0 = blockIdx.x * 128;

    // ldmatrix lane address components
    const int a_row = (lane & 7) + ((lane >> 3) & 1) * 8;
    const int a_kh  = ((lane >> 4) & 1) * 16;
    const int b_row = (lane & 7) + (lane >> 4) * 8;
    const int b_kh  = ((lane >> 3) & 1) * 16;

    auto issue = [&](int c) {
        const int st = (c % NSTG) * STG_B;
        const int k0 = c * 32;
        const uint32_t dAhi = sbase + st;
        const uint32_t dAlo = dAhi + ARR_A;
        const uint32_t dBhi = dAhi + 2 * ARR_A;
        const uint32_t dBlo = dBhi + ARR_BB;
        #pragma unroll
        for (int p = 0; p < 2; p++) {       // A: 64 rows x 4 quads
            int id = tid + p * 128;
            int row = id >> 2, quad = id & 3;
            size_t g = (size_t)(m0 + row) * Cdim + k0 + quad * 8;
            uint32_t so = row * PITCH + quad * 16;
            CP16(dAhi + so, Ahi_g + g);
            CP16(dAlo + so, Alo_g + g);
        }
        #pragma unroll
        for (int p = 0; p < 4; p++) {       // B: 128 rows x 4 quads
            int id = tid + p * 128;
            int row = id >> 2, quad = id & 3;
            size_t g = (size_t)(n0 + row) * Cdim + k0 + quad * 8;
            uint32_t so = row * PITCH + quad * 16;
            CP16(dBhi + so, Whi_g + g);
            CP16(dBlo + so, Wlo_g + g);
        }
    };

    float acc[2][8][4];
    #pragma unroll
    for (int mt = 0; mt < 2; mt++)
        #pragma unroll
        for (int nt = 0; nt < 8; nt++)
            #pragma unroll
            for (int r = 0; r < 4; r++) acc[mt][nt][r] = 0.0f;

    issue(0); CP_COMMIT();
    issue(1); CP_COMMIT();

    for (int c = 0; c < 32; c++) {
        CP_WAIT1();
        __syncthreads();
        if (c + 2 < 32) issue(c + 2);
        CP_COMMIT();

        const uint32_t st = sbase + (c % NSTG) * STG_B;
        const uint32_t sAhi = st, sAlo = st + ARR_A;
        const uint32_t sBhi = st + 2 * ARR_A, sBlo = sBhi + ARR_BB;

        #pragma unroll
        for (int ks = 0; ks < 2; ks++) {
            const int kb = ks * 32;   // byte offset of k16 block
            uint32_t ah[2][4], al[2][4];
            #pragma unroll
            for (int mt = 0; mt < 2; mt++) {
                uint32_t ra = (wm * 32 + mt * 16 + a_row) * PITCH + kb + a_kh;
                ldsm4(sAhi + ra, ah[mt]);
                ldsm4(sAlo + ra, al[mt]);
            }
            uint32_t bh[4][4], bl[4][4];
            #pragma unroll
            for (int bt = 0; bt < 4; bt++) {
                uint32_t rb = (wn * 64 + bt * 16 + b_row) * PITCH + kb + b_kh;
                ldsm4(sBhi + rb, bh[bt]);
                ldsm4(sBlo + rb, bl[bt]);
            }
            #pragma unroll
            for (int bt = 0; bt < 4; bt++) {
                #pragma unroll
                for (int half = 0; half < 2; half++) {
                    const int nt = bt * 2 + half;
                    uint32_t bh0 = bh[bt][half * 2], bh1 = bh[bt][half * 2 + 1];
                    uint32_t bl0 = bl[bt][half * 2], bl1 = bl[bt][half * 2 + 1];
                    #pragma unroll
                    for (int mt = 0; mt < 2; mt++) {
                        mma16816(acc[mt][nt], ah[mt], bh0, bh1);
                        mma16816(acc[mt][nt], ah[mt], bl0, bl1);
                        mma16816(acc[mt][nt], al[mt], bh0, bh1);
                    }
                }
            }
        }
    }

    // Epilogue
    const int r4 = lane >> 2, c4 = lane & 3;
    if (MODE == 0) {
        const int sN = n0 >> 10;                 // 0:q 1:k 2:v
        float* dst = (sN == 0) ? g_q : (sN == 1) ? g_k : g_v;
        const int colb = (n0 & 1023) + wn * 64;
        #pragma unroll
        for (int mt = 0; mt < 2; mt++) {
            #pragma unroll
            for (int nt = 0; nt < 8; nt++) {
                float v0 = acc[mt][nt][0], v1 = acc[mt][nt][1];
                float v2 = acc[mt][nt][2], v3 = acc[mt][nt][3];
                if (sN < 2) {
                    v0 = fmaxf(v0, 0.0f) + SCALE_Q;
                    v1 = fmaxf(v1, 0.0f) + SCALE_Q;
                    v2 = fmaxf(v2, 0.0f) + SCALE_Q;
                    v3 = fmaxf(v3, 0.0f) + SCALE_Q;
                }
                int m = m0 + wm * 32 + mt * 16 + r4;
                int col = colb + nt * 8 + c4 * 2;
                *(float2*)(dst + (size_t)m * Cdim + col)       = make_float2(v0, v1);
                *(float2*)(dst + (size_t)(m + 8) * Cdim + col) = make_float2(v2, v3);
            }
        }
    } else {
        #pragma unroll
        for (int mt = 0; mt < 2; mt++) {
            #pragma unroll
            for (int nt = 0; nt < 8; nt++) {
                int m = m0 + wm * 32 + mt * 16 + r4;
                int col = n0 + wn * 64 + nt * 8 + c4 * 2;
                float b0 = __ldg(bias + col), b1 = __ldg(bias + col + 1);
                *(float2*)(out + (size_t)m * Cdim + col) =
                    make_float2(acc[mt][nt][0] + b0, acc[mt][nt][1] + b1);
                *(float2*)(out + (size_t)(m + 8) * Cdim + col) =
                    make_float2(acc[mt][nt][2] + b0, acc[mt][nt][3] + b1);
            }
        }
    }
}

// ---------------------------------------------------------------------------
// k_sum[bh][e] = sum over n of k_[bb, n, h, e]
// ---------------------------------------------------------------------------
__global__ __launch_bounds__(256)
void ksum_kernel()
{
    const int bh = blockIdx.x;
    const int bb = bh >> 4, h = bh & 15;
    const int e    = threadIdx.x & 63;
    const int part = threadIdx.x >> 6;
    float s = 0.0f;
    const size_t base = (size_t)bb * Lseq * Cdim + h * En + e;
    for (int n = part; n < Lseq; n += 4)
        s += g_k[base + (size_t)n * Cdim];
    __shared__ float red[4][64];
    red[part][e] = s;
    __syncthreads();
    if (part == 0)
        g_ksum[bh * En + e] = red[0][e] + red[1][e] + red[2][e] + red[3][e];
}

// ---------------------------------------------------------------------------
// kv[bh][e][d] = sum over n of k_[bb,n,h,e] * v[bb,n,h,d]
// ---------------------------------------------------------------------------
__global__ __launch_bounds__(256)
void kv_kernel()
{
    __shared__ float sk[64][68];
    __shared__ float sv[64][68];
    const int bh = blockIdx.x;
    const int bb = bh >> 4, h = bh & 15;
    const int tid = threadIdx.x;
    const int tx = tid & 15, ty = tid >> 4;
    float acc[4][4] = {};
    const size_t base = (size_t)bb * Lseq * Cdim + h * En;

    for (int n0 = 0; n0 < Lseq; n0 += 64) {
        __syncthreads();
        #pragma unroll
        for (int i = 0; i < 4; i++) {
            int lin = tid + i * 256;
            int row = lin >> 4;
            int c4  = (lin & 15) << 2;
            size_t g = base + (size_t)(n0 + row) * Cdim + c4;
            *(float4*)&sk[row][c4] = *(const float4*)&g_k[g];
            *(float4*)&sv[row][c4] = *(const float4*)&g_v[g];
        }
        __syncthreads();
        #pragma unroll 4
        for (int n = 0; n < 64; n++) {
            float4 a = *(const float4*)&sk[n][ty * 4];
            float4 b = *(const float4*)&sv[n][tx * 4];
            float av[4] = {a.x, a.y, a.z, a.w};
            float bv[4] = {b.x, b.y, b.z, b.w};
            #pragma unroll
            for (int i = 0; i < 4; i++)
                #pragma unroll
                for (int j = 0; j < 4; j++)
                    acc[i][j] += av[i] * bv[j];
        }
    }
    float* dst = g_kv + bh * (En * En);
    #pragma unroll
    for (int i = 0; i < 4; i++)
        *(float4*)&dst[(ty * 4 + i) * En + tx * 4] =
            make_float4(acc[i][0], acc[i][1], acc[i][2], acc[i][3]);
}

// ---------------------------------------------------------------------------
// out[bb,n,h,d] = (sum_e q_[bb,n,h,e] * kv[bh][e][d]) * z[n]
// Writes result directly as bf16 hi/lo (input to GEMM2).
// ---------------------------------------------------------------------------
__global__ __launch_bounds__(256)
void attn_kernel()
{
    __shared__ float sq [64][68];
    __shared__ float skv[64][68];
    __shared__ float sks[64];
    __shared__ float sz [64];
    const int bh = blockIdx.y;
    const int bb = bh >> 4, h = bh & 15;
    const int n0 = blockIdx.x * 64;
    const int tid = threadIdx.x;
    const int tx = tid & 15, ty = tid >> 4;

    #pragma unroll
    for (int i = 0; i < 4; i++) {
        int lin = tid + i * 256;
        int row = lin >> 4;
        int c4  = (lin & 15) << 2;
        *(float4*)&skv[row][c4] = *(const float4*)&g_kv[bh * (En * En) + row * En + c4];
        size_t g = ((size_t)bb * Lseq + n0 + row) * Cdim + h * En + c4;
        *(float4*)&sq[row][c4] = *(const float4*)&g_q[g];
    }
    if (tid < 16)
        *(float4*)&sks[tid * 4] = *(const float4*)&g_ksum[bh * En + tid * 4];
    __syncthreads();

    if (tid < 64) {
        float d = 0.0f;
        #pragma unroll
        for (int e = 0; e < 64; e++) d += sq[tid][e] * sks[e];
        sz[tid] = 1.0f / (d + EPS_V);
    }
    __syncthreads();

    float acc[4][4] = {};
    #pragma unroll 4
    for (int e = 0; e < 64; e++) {
        float a0 = sq[ty * 4 + 0][e];
        float a1 = sq[ty * 4 + 1][e];
        float a2 = sq[ty * 4 + 2][e];
        float a3 = sq[ty * 4 + 3][e];
        float4 b = *(const float4*)&skv[e][tx * 4];
        acc[0][0] += a0 * b.x; acc[0][1] += a0 * b.y; acc[0][2] += a0 * b.z; acc[0][3] += a0 * b.w;
        acc[1][0] += a1 * b.x; acc[1][1] += a1 * b.y; acc[1][2] += a1 * b.z; acc[1][3] += a1 * b.w;
        acc[2][0] += a2 * b.x; acc[2][1] += a2 * b.y; acc[2][2] += a2 * b.z; acc[2][3] += a2 * b.w;
        acc[3][0] += a3 * b.x; acc[3][1] += a3 * b.y; acc[3][2] += a3 * b.z; acc[3][3] += a3 * b.w;
    }

    #pragma unroll
    for (int i = 0; i < 4; i++) {
        float z = sz[ty * 4 + i];
        float v0 = acc[i][0] * z, v1 = acc[i][1] * z;
        float v2 = acc[i][2] * z, v3 = acc[i][3] * z;
        uint32_t h0, l0, h1, l1;
        split2(v0, v1, h0, l0);
        split2(v2, v3, h1, l1);
        size_t g = ((size_t)bb * Lseq + n0 + ty * 4 + i) * Cdim + h * En + tx * 4;
        *(uint2*)&g_ahi[g >> 1] = make_uint2(h0, h1);
        *(uint2*)&g_alo[g >> 1] = make_uint2(l0, l1);
    }
}

// ---------------------------------------------------------------------------
extern "C" void kernel_launch(void* const* d_in, const int* in_sizes, int n_in,
                              void* d_out, int out_size)
{
    const float* x      = (const float*)d_in[0];
    const float* w_qkv  = (const float*)d_in[1];
    const float* w_proj = (const float*)d_in[2];
    const float* b_proj = (const float*)d_in[3];
    float* out = (float*)d_out;

    static bool attr_done = false;
    if (!attr_done) {
        cudaFuncSetAttribute(gemm_tc<0>, cudaFuncAttributeMaxDynamicSharedMemorySize, GEMM_SMEM);
        cudaFuncSetAttribute(gemm_tc<1>, cudaFuncAttributeMaxDynamicSharedMemorySize, GEMM_SMEM);
        attr_done = true;
    }

    uint32_t *xhi, *xlo, *ahi, *alo, *wqhi, *wqlo, *wphi, *wplo;
    cudaGetSymbolAddress((void**)&xhi,  g_xhi);
    cudaGetSymbolAddress((void**)&xlo,  g_xlo);
    cudaGetSymbolAddress((void**)&ahi,  g_ahi);
    cudaGetSymbolAddress((void**)&alo,  g_alo);
    cudaGetSymbolAddress((void**)&wqhi, g_wqhi);
    cudaGetSymbolAddress((void**)&wqlo, g_wqlo);
    cudaGetSymbolAddress((void**)&wphi, g_wphi);
    cudaGetSymbolAddress((void**)&wplo, g_wplo);

    // 0) fp32 -> bf16 hi/lo conversions
    {
        int n4 = Mtok * (Cdim / 4);
        conv_kernel<<<(n4 + 255) / 256, 256>>>((const float4*)x, xhi, xlo, n4);
        n4 = 3072 * Cdim / 4;
        conv_kernel<<<(n4 + 255) / 256, 256>>>((const float4*)w_qkv, wqhi, wqlo, n4);
        n4 = Cdim * Cdim / 4;
        conv_kernel<<<(n4 + 255) / 256, 256>>>((const float4*)w_proj, wphi, wplo, n4);
    }

    // 1) qkv = x @ w_qkv^T (tensor cores), fused q/k/v split + relu+scale
    gemm_tc<0><<<dim3(24, 392), 128, GEMM_SMEM>>>(
        (const __nv_bfloat16*)xhi, (const __nv_bfloat16*)xlo,
        (const __nv_bfloat16*)wqhi, (const __nv_bfloat16*)wqlo, nullptr, nullptr);
    // 2) k_sum
    ksum_kernel<<<128, 256>>>();
    // 3) kv = k_^T @ v
    kv_kernel<<<128, 256>>>();
    // 4) out = (q_ @ kv) * z  -> bf16 hi/lo
    attn_kernel<<<dim3(49, 128), 256>>>();
    // 5) final = attn @ w_proj^T + b_proj
    gemm_tc<1><<<dim3(8, 392), 128, GEMM_SMEM>>>(
        (const __nv_bfloat16*)ahi, (const __nv_bfloat16*)alo,
        (const __nv_bfloat16*)wphi, (const __nv_bfloat16*)wplo, b_proj, out);
}

// round 6
// speedup vs baseline: 3.0066x; 1.2356x over previous
#include <cuda_runtime.h>
#include <cuda_bf16.h>
#include <cstdint>

// Problem constants
#define Cdim 1024
#define Hn   16
#define En   64
#define Mtok 25088          // B*N
#define Lseq 3136           // f*N
#define NBGRP 8
#define SCALE_Q 0.125f
#define EPS_V   1e-6f

// Scratch (static device memory)
__device__ float g_q[(size_t)Mtok * Cdim];
__device__ float g_k[(size_t)Mtok * Cdim];
__device__ float g_v[(size_t)Mtok * Cdim];
__device__ float g_kv  [NBGRP * Hn * En * En];
__device__ float g_ksum[NBGRP * Hn * En];
// bf16 hi/lo pairs (stored as packed uint32 = 2 bf16)
__device__ uint32_t g_xhi[(size_t)Mtok * Cdim / 2];
__device__ uint32_t g_xlo[(size_t)Mtok * Cdim / 2];
__device__ uint32_t g_ahi[(size_t)Mtok * Cdim / 2];
__device__ uint32_t g_alo[(size_t)Mtok * Cdim / 2];
__device__ uint32_t g_wqhi[3072 * Cdim / 2];
__device__ uint32_t g_wqlo[3072 * Cdim / 2];
__device__ uint32_t g_wphi[Cdim * Cdim / 2];
__device__ uint32_t g_wplo[Cdim * Cdim / 2];

// ---------------------------------------------------------------------------
// Helpers
// ---------------------------------------------------------------------------
__device__ __forceinline__ void split2(float x, float y, uint32_t& hi, uint32_t& lo) {
    __nv_bfloat16 hx = __float2bfloat16(x);
    __nv_bfloat16 hy = __float2bfloat16(y);
    float lx = x - __bfloat162float(hx);
    float ly = y - __bfloat162float(hy);
    __nv_bfloat16 gx = __float2bfloat16(lx);
    __nv_bfloat16 gy = __float2bfloat16(ly);
    hi = ((uint32_t)__bfloat16_as_ushort(hy) << 16) | (uint32_t)__bfloat16_as_ushort(hx);
    lo = ((uint32_t)__bfloat16_as_ushort(gy) << 16) | (uint32_t)__bfloat16_as_ushort(gx);
}

__device__ __forceinline__ uint32_t smem_u32(const void* p) {
    uint32_t a;
    asm("{ .reg .u64 t; cvta.to.shared.u64 t, %1; cvt.u32.u64 %0, t; }" : "=r"(a) : "l"(p));
    return a;
}

__device__ __forceinline__ void mma16816(float* d, const uint32_t* a,
                                         uint32_t b0, uint32_t b1) {
    asm volatile(
        "mma.sync.aligned.m16n8k16.row.col.f32.bf16.bf16.f32 "
        "{%0,%1,%2,%3}, {%4,%5,%6,%7}, {%8,%9}, {%0,%1,%2,%3};"
        : "+f"(d[0]), "+f"(d[1]), "+f"(d[2]), "+f"(d[3])
        : "r"(a[0]), "r"(a[1]), "r"(a[2]), "r"(a[3]), "r"(b0), "r"(b1));
}

__device__ __forceinline__ void ldsm4(uint32_t addr, uint32_t* r) {
    asm volatile("ldmatrix.sync.aligned.m8n8.x4.shared.b16 {%0,%1,%2,%3}, [%4];"
                 : "=r"(r[0]), "=r"(r[1]), "=r"(r[2]), "=r"(r[3]) : "r"(addr));
}

#define CP16(dst, src) \
    asm volatile("cp.async.cg.shared.global [%0], [%1], 16;" :: "r"(dst), "l"(src))
#define CP_COMMIT() asm volatile("cp.async.commit_group;" ::: "memory")
#define CP_WAIT1()  asm volatile("cp.async.wait_group 1;" ::: "memory")

// Swizzled byte offset inside one operand array: row in [0,128), quad in [0,4)
// 64 bytes per row; XOR swizzle keeps ldmatrix + cp.async conflict-free.
__device__ __forceinline__ uint32_t swz(uint32_t row, uint32_t quad) {
    return (row << 6) + ((quad ^ ((row >> 1) & 3)) << 4);
}

// ---------------------------------------------------------------------------
// fp32 -> bf16 hi/lo conversion kernel
// ---------------------------------------------------------------------------
__global__ __launch_bounds__(256)
void conv_kernel(const float4* __restrict__ src, uint32_t* __restrict__ hi,
                 uint32_t* __restrict__ lo, int n4)
{
    int i = blockIdx.x * blockDim.x + threadIdx.x;
    if (i < n4) {
        float4 x = src[i];
        uint32_t h0, l0, h1, l1;
        split2(x.x, x.y, h0, l0);
        split2(x.z, x.w, h1, l1);
        *(uint2*)&hi[i * 2] = make_uint2(h0, h1);
        *(uint2*)&lo[i * 2] = make_uint2(l0, l1);
    }
}

// ---------------------------------------------------------------------------
// Split-BF16 tensor-core NT GEMM: C[m,n] = sum_k A[m,k] * W[n,k]
// Block tile 128x128, K-chunk 32, 128 threads (4 warps = 2m x 2n),
// warp tile 64x64 (high MMA/LDSM ratio), cp.async 3-stage, swizzled smem,
// 3 MMAs per micro (hi*hi + hi*lo + lo*hi). 2 CTAs/SM.
// MODE 0: epilogue splits q/k/v with relu+scale. MODE 1: bias -> out.
// ---------------------------------------------------------------------------
#define ARR_SZ 8192                   // 128 rows x 64 bytes
#define STG_B (4 * ARR_SZ)            // Ahi, Alo, Bhi, Blo = 32768
#define NSTG 3
#define GEMM_SMEM (NSTG * STG_B)      // 98304

template<int MODE>
__global__ __launch_bounds__(128, 2)
void gemm_tc(const __nv_bfloat16* __restrict__ Ahi_g,
             const __nv_bfloat16* __restrict__ Alo_g,
             const __nv_bfloat16* __restrict__ Whi_g,
             const __nv_bfloat16* __restrict__ Wlo_g,
             const float* __restrict__ bias, float* __restrict__ out)
{
    extern __shared__ __align__(128) char smem[];
    const uint32_t sbase = smem_u32(smem);
    const int tid  = threadIdx.x;
    const int lane = tid & 31;
    const int w    = tid >> 5;        // 0..3
    const int wm   = w & 1;           // m group -> rows wm*64
    const int wn   = w >> 1;          // n group -> cols wn*64
    const int m0 = blockIdx.y * 128;
    const int n0 = blockIdx.x * 128;

    // ldmatrix lane row/k components
    const int a_row = (lane & 7) + ((lane >> 3) & 1) * 8;   // 0..15
    const int a_kq  = (lane >> 4) & 1;                      // k quad within ks
    const int b_row = (lane & 7) + (lane >> 4) * 8;         // 0..15
    const int b_kq  = (lane >> 3) & 1;

    auto issue = [&](int c) {
        const uint32_t st = sbase + (c % NSTG) * STG_B;
        const int k0 = c * 32;
        const uint32_t dAhi = st;
        const uint32_t dAlo = st + ARR_SZ;
        const uint32_t dBhi = st + 2 * ARR_SZ;
        const uint32_t dBlo = st + 3 * ARR_SZ;
        #pragma unroll
        for (int p = 0; p < 4; p++) {
            int id = tid + p * 128;
            int row = id >> 2, quad = id & 3;
            uint32_t so = swz(row, quad);
            size_t ga = (size_t)(m0 + row) * Cdim + k0 + quad * 8;
            size_t gb = (size_t)(n0 + row) * Cdim + k0 + quad * 8;
            CP16(dAhi + so, Ahi_g + ga);
            CP16(dAlo + so, Alo_g + ga);
            CP16(dBhi + so, Whi_g + gb);
            CP16(dBlo + so, Wlo_g + gb);
        }
    };

    float acc[4][8][4];
    #pragma unroll
    for (int mt = 0; mt < 4; mt++)
        #pragma unroll
        for (int nt = 0; nt < 8; nt++)
            #pragma unroll
            for (int r = 0; r < 4; r++) acc[mt][nt][r] = 0.0f;

    issue(0); CP_COMMIT();
    issue(1); CP_COMMIT();

    for (int c = 0; c < 32; c++) {
        CP_WAIT1();
        __syncthreads();
        if (c + 2 < 32) issue(c + 2);
        CP_COMMIT();

        const uint32_t st = sbase + (c % NSTG) * STG_B;
        const uint32_t sAhi = st, sAlo = st + ARR_SZ;
        const uint32_t sBhi = st + 2 * ARR_SZ, sBlo = st + 3 * ARR_SZ;

        #pragma unroll
        for (int ks = 0; ks < 2; ks++) {
            uint32_t ah[4][4], al[4][4];
            #pragma unroll
            for (int mt = 0; mt < 4; mt++) {
                uint32_t row = wm * 64 + mt * 16 + a_row;
                uint32_t ra = swz(row, ks * 2 + a_kq);
                ldsm4(sAhi + ra, ah[mt]);
                ldsm4(sAlo + ra, al[mt]);
            }
            #pragma unroll
            for (int bt = 0; bt < 4; bt++) {
                uint32_t row = wn * 64 + bt * 16 + b_row;
                uint32_t rb = swz(row, ks * 2 + b_kq);
                uint32_t bh[4], bl[4];
                ldsm4(sBhi + rb, bh);
                ldsm4(sBlo + rb, bl);
                #pragma unroll
                for (int half = 0; half < 2; half++) {
                    const int nt = bt * 2 + half;
                    uint32_t bh0 = bh[half * 2], bh1 = bh[half * 2 + 1];
                    uint32_t bl0 = bl[half * 2], bl1 = bl[half * 2 + 1];
                    #pragma unroll
                    for (int mt = 0; mt < 4; mt++) {
                        mma16816(acc[mt][nt], ah[mt], bh0, bh1);
                        mma16816(acc[mt][nt], ah[mt], bl0, bl1);
                        mma16816(acc[mt][nt], al[mt], bh0, bh1);
                    }
                }
            }
        }
    }

    // Epilogue
    const int r4 = lane >> 2, c4 = lane & 3;
    if (MODE == 0) {
        const int sN = n0 >> 10;                 // 0:q 1:k 2:v
        float* dst = (sN == 0) ? g_q : (sN == 1) ? g_k : g_v;
        const int colb = (n0 & 1023) + wn * 64;
        #pragma unroll
        for (int mt = 0; mt < 4; mt++) {
            #pragma unroll
            for (int nt = 0; nt < 8; nt++) {
                float v0 = acc[mt][nt][0], v1 = acc[mt][nt][1];
                float v2 = acc[mt][nt][2], v3 = acc[mt][nt][3];
                if (sN < 2) {
                    v0 = fmaxf(v0, 0.0f) + SCALE_Q;
                    v1 = fmaxf(v1, 0.0f) + SCALE_Q;
                    v2 = fmaxf(v2, 0.0f) + SCALE_Q;
                    v3 = fmaxf(v3, 0.0f) + SCALE_Q;
                }
                int m = m0 + wm * 64 + mt * 16 + r4;
                int col = colb + nt * 8 + c4 * 2;
                *(float2*)(dst + (size_t)m * Cdim + col)       = make_float2(v0, v1);
                *(float2*)(dst + (size_t)(m + 8) * Cdim + col) = make_float2(v2, v3);
            }
        }
    } else {
        #pragma unroll
        for (int mt = 0; mt < 4; mt++) {
            #pragma unroll
            for (int nt = 0; nt < 8; nt++) {
                int m = m0 + wm * 64 + mt * 16 + r4;
                int col = n0 + wn * 64 + nt * 8 + c4 * 2;
                float b0 = __ldg(bias + col), b1 = __ldg(bias + col + 1);
                *(float2*)(out + (size_t)m * Cdim + col) =
                    make_float2(acc[mt][nt][0] + b0, acc[mt][nt][1] + b1);
                *(float2*)(out + (size_t)(m + 8) * Cdim + col) =
                    make_float2(acc[mt][nt][2] + b0, acc[mt][nt][3] + b1);
            }
        }
    }
}

// ---------------------------------------------------------------------------
// k_sum[bh][e] = sum over n of k_[bb, n, h, e]
// ---------------------------------------------------------------------------
__global__ __launch_bounds__(256)
void ksum_kernel()
{
    const int bh = blockIdx.x;
    const int bb = bh >> 4, h = bh & 15;
    const int e    = threadIdx.x & 63;
    const int part = threadIdx.x >> 6;
    float s = 0.0f;
    const size_t base = (size_t)bb * Lseq * Cdim + h * En + e;
    for (int n = part; n < Lseq; n += 4)
        s += g_k[base + (size_t)n * Cdim];
    __shared__ float red[4][64];
    red[part][e] = s;
    __syncthreads();
    if (part == 0)
        g_ksum[bh * En + e] = red[0][e] + red[1][e] + red[2][e] + red[3][e];
}

// ---------------------------------------------------------------------------
// kv[bh][e][d] = sum over n of k_[bb,n,h,e] * v[bb,n,h,d]
// ---------------------------------------------------------------------------
__global__ __launch_bounds__(256)
void kv_kernel()
{
    __shared__ float sk[64][68];
    __shared__ float sv[64][68];
    const int bh = blockIdx.x;
    const int bb = bh >> 4, h = bh & 15;
    const int tid = threadIdx.x;
    const int tx = tid & 15, ty = tid >> 4;
    float acc[4][4] = {};
    const size_t base = (size_t)bb * Lseq * Cdim + h * En;

    for (int n0 = 0; n0 < Lseq; n0 += 64) {
        __syncthreads();
        #pragma unroll
        for (int i = 0; i < 4; i++) {
            int lin = tid + i * 256;
            int row = lin >> 4;
            int c4  = (lin & 15) << 2;
            size_t g = base + (size_t)(n0 + row) * Cdim + c4;
            *(float4*)&sk[row][c4] = *(const float4*)&g_k[g];
            *(float4*)&sv[row][c4] = *(const float4*)&g_v[g];
        }
        __syncthreads();
        #pragma unroll 4
        for (int n = 0; n < 64; n++) {
            float4 a = *(const float4*)&sk[n][ty * 4];
            float4 b = *(const float4*)&sv[n][tx * 4];
            float av[4] = {a.x, a.y, a.z, a.w};
            float bv[4] = {b.x, b.y, b.z, b.w};
            #pragma unroll
            for (int i = 0; i < 4; i++)
                #pragma unroll
                for (int j = 0; j < 4; j++)
                    acc[i][j] += av[i] * bv[j];
        }
    }
    float* dst = g_kv + bh * (En * En);
    #pragma unroll
    for (int i = 0; i < 4; i++)
        *(float4*)&dst[(ty * 4 + i) * En + tx * 4] =
            make_float4(acc[i][0], acc[i][1], acc[i][2], acc[i][3]);
}

// ---------------------------------------------------------------------------
// out[bb,n,h,d] = (sum_e q_[bb,n,h,e] * kv[bh][e][d]) * z[n]
// Writes result directly as bf16 hi/lo (input to GEMM2).
// ---------------------------------------------------------------------------
__global__ __launch_bounds__(256)
void attn_kernel()
{
    __shared__ float sq [64][68];
    __shared__ float skv[64][68];
    __shared__ float sks[64];
    __shared__ float sz [64];
    const int bh = blockIdx.y;
    const int bb = bh >> 4, h = bh & 15;
    const int n0 = blockIdx.x * 64;
    const int tid = threadIdx.x;
    const int tx = tid & 15, ty = tid >> 4;

    #pragma unroll
    for (int i = 0; i < 4; i++) {
        int lin = tid + i * 256;
        int row = lin >> 4;
        int c4  = (lin & 15) << 2;
        *(float4*)&skv[row][c4] = *(const float4*)&g_kv[bh * (En * En) + row * En + c4];
        size_t g = ((size_t)bb * Lseq + n0 + row) * Cdim + h * En + c4;
        *(float4*)&sq[row][c4] = *(const float4*)&g_q[g];
    }
    if (tid < 16)
        *(float4*)&sks[tid * 4] = *(const float4*)&g_ksum[bh * En + tid * 4];
    __syncthreads();

    if (tid < 64) {
        float d = 0.0f;
        #pragma unroll
        for (int e = 0; e < 64; e++) d += sq[tid][e] * sks[e];
        sz[tid] = 1.0f / (d + EPS_V);
    }
    __syncthreads();

    float acc[4][4] = {};
    #pragma unroll 4
    for (int e = 0; e < 64; e++) {
        float a0 = sq[ty * 4 + 0][e];
        float a1 = sq[ty * 4 + 1][e];
        float a2 = sq[ty * 4 + 2][e];
        float a3 = sq[ty * 4 + 3][e];
        float4 b = *(const float4*)&skv[e][tx * 4];
        acc[0][0] += a0 * b.x; acc[0][1] += a0 * b.y; acc[0][2] += a0 * b.z; acc[0][3] += a0 * b.w;
        acc[1][0] += a1 * b.x; acc[1][1] += a1 * b.y; acc[1][2] += a1 * b.z; acc[1][3] += a1 * b.w;
        acc[2][0] += a2 * b.x; acc[2][1] += a2 * b.y; acc[2][2] += a2 * b.z; acc[2][3] += a2 * b.w;
        acc[3][0] += a3 * b.x; acc[3][1] += a3 * b.y; acc[3][2] += a3 * b.z; acc[3][3] += a3 * b.w;
    }

    #pragma unroll
    for (int i = 0; i < 4; i++) {
        float z = sz[ty * 4 + i];
        float v0 = acc[i][0] * z, v1 = acc[i][1] * z;
        float v2 = acc[i][2] * z, v3 = acc[i][3] * z;
        uint32_t h0, l0, h1, l1;
        split2(v0, v1, h0, l0);
        split2(v2, v3, h1, l1);
        size_t g = ((size_t)bb * Lseq + n0 + ty * 4 + i) * Cdim + h * En + tx * 4;
        *(uint2*)&g_ahi[g >> 1] = make_uint2(h0, h1);
        *(uint2*)&g_alo[g >> 1] = make_uint2(l0, l1);
    }
}

// ---------------------------------------------------------------------------
extern "C" void kernel_launch(void* const* d_in, const int* in_sizes, int n_in,
                              void* d_out, int out_size)
{
    const float* x      = (const float*)d_in[0];
    const float* w_qkv  = (const float*)d_in[1];
    const float* w_proj = (const float*)d_in[2];
    const float* b_proj = (const float*)d_in[3];
    float* out = (float*)d_out;

    static bool attr_done = false;
    if (!attr_done) {
        cudaFuncSetAttribute(gemm_tc<0>, cudaFuncAttributeMaxDynamicSharedMemorySize, GEMM_SMEM);
        cudaFuncSetAttribute(gemm_tc<1>, cudaFuncAttributeMaxDynamicSharedMemorySize, GEMM_SMEM);
        attr_done = true;
    }

    uint32_t *xhi, *xlo, *ahi, *alo, *wqhi, *wqlo, *wphi, *wplo;
    cudaGetSymbolAddress((void**)&xhi,  g_xhi);
    cudaGetSymbolAddress((void**)&xlo,  g_xlo);
    cudaGetSymbolAddress((void**)&ahi,  g_ahi);
    cudaGetSymbolAddress((void**)&alo,  g_alo);
    cudaGetSymbolAddress((void**)&wqhi, g_wqhi);
    cudaGetSymbolAddress((void**)&wqlo, g_wqlo);
    cudaGetSymbolAddress((void**)&wphi, g_wphi);
    cudaGetSymbolAddress((void**)&wplo, g_wplo);

    // 0) fp32 -> bf16 hi/lo conversions
    {
        int n4 = Mtok * (Cdim / 4);
        conv_kernel<<<(n4 + 255) / 256, 256>>>((const float4*)x, xhi, xlo, n4);
        n4 = 3072 * Cdim / 4;
        conv_kernel<<<(n4 + 255) / 256, 256>>>((const float4*)w_qkv, wqhi, wqlo, n4);
        n4 = Cdim * Cdim / 4;
        conv_kernel<<<(n4 + 255) / 256, 256>>>((const float4*)w_proj, wphi, wplo, n4);
    }

    // 1) qkv = x @ w_qkv^T (tensor cores), fused q/k/v split + relu+scale
    gemm_tc<0><<<dim3(24, 196), 128, GEMM_SMEM>>>(
        (const __nv_bfloat16*)xhi, (const __nv_bfloat16*)xlo,
        (const __nv_bfloat16*)wqhi, (const __nv_bfloat16*)wqlo, nullptr, nullptr);
    // 2) k_sum
    ksum_kernel<<<128, 256>>>();
    // 3) kv = k_^T @ v
    kv_kernel<<<128, 256>>>();
    // 4) out = (q_ @ kv) * z  -> bf16 hi/lo
    attn_kernel<<<dim3(49, 128), 256>>>();
    // 5) final = attn @ w_proj^T + b_proj
    gemm_tc<1><<<dim3(8, 196), 128, GEMM_SMEM>>>(
        (const __nv_bfloat16*)ahi, (const __nv_bfloat16*)alo,
        (const __nv_bfloat16*)wphi, (const __nv_bfloat16*)wplo, b_proj, out);
}

// round 7
// speedup vs baseline: 5.4098x; 1.7993x over previous
#include <cuda_runtime.h>
#include <cuda_fp16.h>
#include <cstdint>

// Problem constants
#define Cdim 1024
#define Hn   16
#define En   64
#define Mtok 25088          // B*N
#define Lseq 3136           // f*N
#define NBGRP 8
#define SCALE_Q 0.125f
#define EPS_V   1e-6f

// Scratch (static device memory)
__device__ float g_q[(size_t)Mtok * Cdim];
__device__ float g_k[(size_t)Mtok * Cdim];
__device__ float g_v[(size_t)Mtok * Cdim];
__device__ float g_kv  [NBGRP * Hn * En * En];
__device__ float g_ksum[NBGRP * Hn * En];
// fp16 operands
__device__ __half g_xh[(size_t)Mtok * Cdim];   // x
__device__ __half g_ah[(size_t)Mtok * Cdim];   // attn output
__device__ __half g_wqh[3072 * Cdim];
__device__ __half g_wph[Cdim * Cdim];

// ---------------------------------------------------------------------------
// Helpers
// ---------------------------------------------------------------------------
__device__ __forceinline__ uint32_t smem_u32(const void* p) {
    uint32_t a;
    asm("{ .reg .u64 t; cvta.to.shared.u64 t, %1; cvt.u32.u64 %0, t; }" : "=r"(a) : "l"(p));
    return a;
}

__device__ __forceinline__ void mma16816(float* d, const uint32_t* a,
                                         uint32_t b0, uint32_t b1) {
    asm volatile(
        "mma.sync.aligned.m16n8k16.row.col.f32.f16.f16.f32 "
        "{%0,%1,%2,%3}, {%4,%5,%6,%7}, {%8,%9}, {%0,%1,%2,%3};"
        : "+f"(d[0]), "+f"(d[1]), "+f"(d[2]), "+f"(d[3])
        : "r"(a[0]), "r"(a[1]), "r"(a[2]), "r"(a[3]), "r"(b0), "r"(b1));
}

__device__ __forceinline__ void ldsm4(uint32_t addr, uint32_t* r) {
    asm volatile("ldmatrix.sync.aligned.m8n8.x4.shared.b16 {%0,%1,%2,%3}, [%4];"
                 : "=r"(r[0]), "=r"(r[1]), "=r"(r[2]), "=r"(r[3]) : "r"(addr));
}

#define CP16(dst, src) \
    asm volatile("cp.async.cg.shared.global [%0], [%1], 16;" :: "r"(dst), "l"(src))
#define CP_COMMIT() asm volatile("cp.async.commit_group;" ::: "memory")
#define CP_WAIT2()  asm volatile("cp.async.wait_group 2;" ::: "memory")

// Swizzled byte offset: row in [0,128), quad in [0,4); 64 bytes per row.
__device__ __forceinline__ uint32_t swz(uint32_t row, uint32_t quad) {
    return (row << 6) + ((quad ^ ((row >> 1) & 3)) << 4);
}

// ---------------------------------------------------------------------------
// fp32 -> fp16 conversion kernel
// ---------------------------------------------------------------------------
__global__ __launch_bounds__(256)
void conv_kernel(const float4* __restrict__ src, __half* __restrict__ dst, int n4)
{
    int i = blockIdx.x * blockDim.x + threadIdx.x;
    if (i < n4) {
        float4 x = src[i];
        __half2 h01 = __floats2half2_rn(x.x, x.y);
        __half2 h23 = __floats2half2_rn(x.z, x.w);
        *(uint2*)&dst[(size_t)i * 4] =
            make_uint2(*(uint32_t*)&h01, *(uint32_t*)&h23);
    }
}

// ---------------------------------------------------------------------------
// FP16 tensor-core NT GEMM: C[m,n] = sum_k A[m,k] * W[n,k]
// Block 128x128, K-chunk 32, 128 threads (4 warps = 2m x 2n), warp tile 64x64,
// cp.async 4-stage, swizzled smem, 1 MMA per micro. 3 CTAs/SM.
// MODE 0: epilogue splits q/k/v with relu+scale. MODE 1: bias -> out.
// ---------------------------------------------------------------------------
#define ARR_SZ 8192                   // 128 rows x 64 bytes
#define STG_B (2 * ARR_SZ)            // A, B = 16384
#define NSTG 4
#define GEMM_SMEM (NSTG * STG_B)      // 65536

template<int MODE>
__global__ __launch_bounds__(128, 3)
void gemm_tc(const __half* __restrict__ A_g,
             const __half* __restrict__ W_g,
             const float* __restrict__ bias, float* __restrict__ out)
{
    extern __shared__ __align__(128) char smem[];
    const uint32_t sbase = smem_u32(smem);
    const int tid  = threadIdx.x;
    const int lane = tid & 31;
    const int w    = tid >> 5;        // 0..3
    const int wm   = w & 1;           // m group -> rows wm*64
    const int wn   = w >> 1;          // n group -> cols wn*64
    const int m0 = blockIdx.y * 128;
    const int n0 = blockIdx.x * 128;

    const int a_row = (lane & 7) + ((lane >> 3) & 1) * 8;
    const int a_kq  = (lane >> 4) & 1;
    const int b_row = (lane & 7) + (lane >> 4) * 8;
    const int b_kq  = (lane >> 3) & 1;

    auto issue = [&](int c) {
        const uint32_t st = sbase + (c % NSTG) * STG_B;
        const int k0 = c * 32;
        #pragma unroll
        for (int p = 0; p < 4; p++) {
            int id = tid + p * 128;
            int row = id >> 2, quad = id & 3;
            uint32_t so = swz(row, quad);
            CP16(st + so, A_g + (size_t)(m0 + row) * Cdim + k0 + quad * 8);
            CP16(st + ARR_SZ + so, W_g + (size_t)(n0 + row) * Cdim + k0 + quad * 8);
        }
    };

    float acc[4][8][4];
    #pragma unroll
    for (int mt = 0; mt < 4; mt++)
        #pragma unroll
        for (int nt = 0; nt < 8; nt++)
            #pragma unroll
            for (int r = 0; r < 4; r++) acc[mt][nt][r] = 0.0f;

    issue(0); CP_COMMIT();
    issue(1); CP_COMMIT();
    issue(2); CP_COMMIT();

    for (int c = 0; c < 32; c++) {
        CP_WAIT2();
        __syncthreads();
        if (c + 3 < 32) issue(c + 3);
        CP_COMMIT();

        const uint32_t st = sbase + (c % NSTG) * STG_B;
        const uint32_t sA = st, sB = st + ARR_SZ;

        #pragma unroll
        for (int ks = 0; ks < 2; ks++) {
            uint32_t ah[4][4];
            #pragma unroll
            for (int mt = 0; mt < 4; mt++) {
                uint32_t row = wm * 64 + mt * 16 + a_row;
                ldsm4(sA + swz(row, ks * 2 + a_kq), ah[mt]);
            }
            #pragma unroll
            for (int bt = 0; bt < 4; bt++) {
                uint32_t row = wn * 64 + bt * 16 + b_row;
                uint32_t bh[4];
                ldsm4(sB + swz(row, ks * 2 + b_kq), bh);
                #pragma unroll
                for (int half = 0; half < 2; half++) {
                    const int nt = bt * 2 + half;
                    #pragma unroll
                    for (int mt = 0; mt < 4; mt++)
                        mma16816(acc[mt][nt], ah[mt], bh[half * 2], bh[half * 2 + 1]);
                }
            }
        }
    }

    // Epilogue
    const int r4 = lane >> 2, c4 = lane & 3;
    if (MODE == 0) {
        const int sN = n0 >> 10;                 // 0:q 1:k 2:v
        float* dst = (sN == 0) ? g_q : (sN == 1) ? g_k : g_v;
        const int colb = (n0 & 1023) + wn * 64;
        #pragma unroll
        for (int mt = 0; mt < 4; mt++) {
            #pragma unroll
            for (int nt = 0; nt < 8; nt++) {
                float v0 = acc[mt][nt][0], v1 = acc[mt][nt][1];
                float v2 = acc[mt][nt][2], v3 = acc[mt][nt][3];
                if (sN < 2) {
                    v0 = fmaxf(v0, 0.0f) + SCALE_Q;
                    v1 = fmaxf(v1, 0.0f) + SCALE_Q;
                    v2 = fmaxf(v2, 0.0f) + SCALE_Q;
                    v3 = fmaxf(v3, 0.0f) + SCALE_Q;
                }
                int m = m0 + wm * 64 + mt * 16 + r4;
                int col = colb + nt * 8 + c4 * 2;
                *(float2*)(dst + (size_t)m * Cdim + col)       = make_float2(v0, v1);
                *(float2*)(dst + (size_t)(m + 8) * Cdim + col) = make_float2(v2, v3);
            }
        }
    } else {
        #pragma unroll
        for (int mt = 0; mt < 4; mt++) {
            #pragma unroll
            for (int nt = 0; nt < 8; nt++) {
                int m = m0 + wm * 64 + mt * 16 + r4;
                int col = n0 + wn * 64 + nt * 8 + c4 * 2;
                float b0 = __ldg(bias + col), b1 = __ldg(bias + col + 1);
                *(float2*)(out + (size_t)m * Cdim + col) =
                    make_float2(acc[mt][nt][0] + b0, acc[mt][nt][1] + b1);
                *(float2*)(out + (size_t)(m + 8) * Cdim + col) =
                    make_float2(acc[mt][nt][2] + b0, acc[mt][nt][3] + b1);
            }
        }
    }
}

// ---------------------------------------------------------------------------
// kv[bh][e][d] = sum over n of k_[bb,n,h,e] * v[bb,n,h,d]
// Also computes k_sum[bh][e] (fused; saves a separate pass over g_k).
// ---------------------------------------------------------------------------
__global__ __launch_bounds__(256)
void kv_kernel()
{
    __shared__ float sk[64][68];
    __shared__ float sv[64][68];
    __shared__ float red[4][64];
    const int bh = blockIdx.x;
    const int bb = bh >> 4, h = bh & 15;
    const int tid = threadIdx.x;
    const int tx = tid & 15, ty = tid >> 4;
    const int e_id = tid & 63, part = tid >> 6;
    float acc[4][4] = {};
    float ks_part = 0.0f;
    const size_t base = (size_t)bb * Lseq * Cdim + h * En;

    for (int n0 = 0; n0 < Lseq; n0 += 64) {
        __syncthreads();
        #pragma unroll
        for (int i = 0; i < 4; i++) {
            int lin = tid + i * 256;
            int row = lin >> 4;
            int c4  = (lin & 15) << 2;
            size_t g = base + (size_t)(n0 + row) * Cdim + c4;
            *(float4*)&sk[row][c4] = *(const float4*)&g_k[g];
            *(float4*)&sv[row][c4] = *(const float4*)&g_v[g];
        }
        __syncthreads();
        #pragma unroll 4
        for (int n = 0; n < 64; n++) {
            float4 a = *(const float4*)&sk[n][ty * 4];
            float4 b = *(const float4*)&sv[n][tx * 4];
            float av[4] = {a.x, a.y, a.z, a.w};
            float bv[4] = {b.x, b.y, b.z, b.w};
            #pragma unroll
            for (int i = 0; i < 4; i++)
                #pragma unroll
                for (int j = 0; j < 4; j++)
                    acc[i][j] += av[i] * bv[j];
        }
        // fused k_sum: part p sums rows p*16 .. p*16+15 for column e_id
        #pragma unroll
        for (int n = 0; n < 16; n++)
            ks_part += sk[part * 16 + n][e_id];
    }
    float* dst = g_kv + bh * (En * En);
    #pragma unroll
    for (int i = 0; i < 4; i++)
        *(float4*)&dst[(ty * 4 + i) * En + tx * 4] =
            make_float4(acc[i][0], acc[i][1], acc[i][2], acc[i][3]);

    __syncthreads();
    red[part][e_id] = ks_part;
    __syncthreads();
    if (part == 0)
        g_ksum[bh * En + e_id] = red[0][e_id] + red[1][e_id] + red[2][e_id] + red[3][e_id];
}

// ---------------------------------------------------------------------------
// out[bb,n,h,d] = (sum_e q_[bb,n,h,e] * kv[bh][e][d]) * z[n]   -> fp16
// ---------------------------------------------------------------------------
__global__ __launch_bounds__(256)
void attn_kernel()
{
    __shared__ float sq [64][68];
    __shared__ float skv[64][68];
    __shared__ float sks[64];
    __shared__ float sz [64];
    const int bh = blockIdx.y;
    const int bb = bh >> 4, h = bh & 15;
    const int n0 = blockIdx.x * 64;
    const int tid = threadIdx.x;
    const int tx = tid & 15, ty = tid >> 4;

    #pragma unroll
    for (int i = 0; i < 4; i++) {
        int lin = tid + i * 256;
        int row = lin >> 4;
        int c4  = (lin & 15) << 2;
        *(float4*)&skv[row][c4] = *(const float4*)&g_kv[bh * (En * En) + row * En + c4];
        size_t g = ((size_t)bb * Lseq + n0 + row) * Cdim + h * En + c4;
        *(float4*)&sq[row][c4] = *(const float4*)&g_q[g];
    }
    if (tid < 16)
        *(float4*)&sks[tid * 4] = *(const float4*)&g_ksum[bh * En + tid * 4];
    __syncthreads();

    if (tid < 64) {
        float d = 0.0f;
        #pragma unroll
        for (int e = 0; e < 64; e++) d += sq[tid][e] * sks[e];
        sz[tid] = 1.0f / (d + EPS_V);
    }
    __syncthreads();

    float acc[4][4] = {};
    #pragma unroll 4
    for (int e = 0; e < 64; e++) {
        float a0 = sq[ty * 4 + 0][e];
        float a1 = sq[ty * 4 + 1][e];
        float a2 = sq[ty * 4 + 2][e];
        float a3 = sq[ty * 4 + 3][e];
        float4 b = *(const float4*)&skv[e][tx * 4];
        acc[0][0] += a0 * b.x; acc[0][1] += a0 * b.y; acc[0][2] += a0 * b.z; acc[0][3] += a0 * b.w;
        acc[1][0] += a1 * b.x; acc[1][1] += a1 * b.y; acc[1][2] += a1 * b.z; acc[1][3] += a1 * b.w;
        acc[2][0] += a2 * b.x; acc[2][1] += a2 * b.y; acc[2][2] += a2 * b.z; acc[2][3] += a2 * b.w;
        acc[3][0] += a3 * b.x; acc[3][1] += a3 * b.y; acc[3][2] += a3 * b.z; acc[3][3] += a3 * b.w;
    }

    #pragma unroll
    for (int i = 0; i < 4; i++) {
        float z = sz[ty * 4 + i];
        __half2 h01 = __floats2half2_rn(acc[i][0] * z, acc[i][1] * z);
        __half2 h23 = __floats2half2_rn(acc[i][2] * z, acc[i][3] * z);
        size_t g = ((size_t)bb * Lseq + n0 + ty * 4 + i) * Cdim + h * En + tx * 4;
        *(uint2*)&g_ah[g] = make_uint2(*(uint32_t*)&h01, *(uint32_t*)&h23);
    }
}

// ---------------------------------------------------------------------------
extern "C" void kernel_launch(void* const* d_in, const int* in_sizes, int n_in,
                              void* d_out, int out_size)
{
    const float* x      = (const float*)d_in[0];
    const float* w_qkv  = (const float*)d_in[1];
    const float* w_proj = (const float*)d_in[2];
    const float* b_proj = (const float*)d_in[3];
    float* out = (float*)d_out;

    cudaFuncSetAttribute(gemm_tc<0>, cudaFuncAttributeMaxDynamicSharedMemorySize, GEMM_SMEM);
    cudaFuncSetAttribute(gemm_tc<1>, cudaFuncAttributeMaxDynamicSharedMemorySize, GEMM_SMEM);

    __half *xh, *ah, *wqh, *wph;
    cudaGetSymbolAddress((void**)&xh,  g_xh);
    cudaGetSymbolAddress((void**)&ah,  g_ah);
    cudaGetSymbolAddress((void**)&wqh, g_wqh);
    cudaGetSymbolAddress((void**)&wph, g_wph);

    // 0) fp32 -> fp16 conversions
    {
        int n4 = Mtok * (Cdim / 4);
        conv_kernel<<<(n4 + 255) / 256, 256>>>((const float4*)x, xh, n4);
        n4 = 3072 * Cdim / 4;
        conv_kernel<<<(n4 + 255) / 256, 256>>>((const float4*)w_qkv, wqh, n4);
        n4 = Cdim * Cdim / 4;
        conv_kernel<<<(n4 + 255) / 256, 256>>>((const float4*)w_proj, wph, n4);
    }

    // 1) qkv = x @ w_qkv^T (fp16 tensor cores), fused q/k/v split + relu+scale
    gemm_tc<0><<<dim3(24, 196), 128, GEMM_SMEM>>>(xh, wqh, nullptr, nullptr);
    // 2) kv = k_^T @ v  (+ fused k_sum)
    kv_kernel<<<128, 256>>>();
    // 3) out = (q_ @ kv) * z  -> fp16
    attn_kernel<<<dim3(49, 128), 256>>>();
    // 4) final = attn @ w_proj^T + b_proj
    gemm_tc<1><<<dim3(8, 196), 128, GEMM_SMEM>>>(ah, wph, b_proj, out);
}

// round 8
// speedup vs baseline: 5.9315x; 1.0964x over previous
#include <cuda_runtime.h>
#include <cuda_fp16.h>
#include <cstdint>

// Problem constants
#define Cdim 1024
#define Hn   16
#define En   64
#define Mtok 25088          // B*N
#define Lseq 3136           // f*N
#define NBGRP 8
#define SCALE_Q 0.125f
#define EPS_V   1e-6f

// Scratch (static device memory)
__device__ float g_kv  [NBGRP * Hn * En * En];
__device__ float g_ksum[NBGRP * Hn * En];
// fp16 tensors
__device__ __half g_xh[(size_t)Mtok * Cdim];    // x
__device__ __half g_qh[(size_t)Mtok * Cdim];    // q_ (relu+scale applied)
__device__ __half g_kh[(size_t)Mtok * Cdim];    // k_ (relu+scale applied)
__device__ __half g_vh[(size_t)Mtok * Cdim];    // v
__device__ __half g_ah[(size_t)Mtok * Cdim];    // attn output
__device__ __half g_wqh[3072 * Cdim];
__device__ __half g_wph[Cdim * Cdim];

// ---------------------------------------------------------------------------
// Helpers
// ---------------------------------------------------------------------------
__device__ __forceinline__ uint32_t smem_u32(const void* p) {
    uint32_t a;
    asm("{ .reg .u64 t; cvta.to.shared.u64 t, %1; cvt.u32.u64 %0, t; }" : "=r"(a) : "l"(p));
    return a;
}

__device__ __forceinline__ void mma16816(float* d, const uint32_t* a,
                                         uint32_t b0, uint32_t b1) {
    asm volatile(
        "mma.sync.aligned.m16n8k16.row.col.f32.f16.f16.f32 "
        "{%0,%1,%2,%3}, {%4,%5,%6,%7}, {%8,%9}, {%0,%1,%2,%3};"
        : "+f"(d[0]), "+f"(d[1]), "+f"(d[2]), "+f"(d[3])
        : "r"(a[0]), "r"(a[1]), "r"(a[2]), "r"(a[3]), "r"(b0), "r"(b1));
}

__device__ __forceinline__ void ldsm4(uint32_t addr, uint32_t* r) {
    asm volatile("ldmatrix.sync.aligned.m8n8.x4.shared.b16 {%0,%1,%2,%3}, [%4];"
                 : "=r"(r[0]), "=r"(r[1]), "=r"(r[2]), "=r"(r[3]) : "r"(addr));
}

#define CP16(dst, src) \
    asm volatile("cp.async.cg.shared.global [%0], [%1], 16;" :: "r"(dst), "l"(src))
#define CP_COMMIT() asm volatile("cp.async.commit_group;" ::: "memory")
#define CP_WAIT0()  asm volatile("cp.async.wait_group 0;" ::: "memory")

// Swizzled byte offset for 128-byte rows: row in [0,128), quad in [0,8)
__device__ __forceinline__ uint32_t swz(uint32_t row, uint32_t quad) {
    return (row << 7) + ((quad ^ (row & 7)) << 4);
}

// ---------------------------------------------------------------------------
// fp32 -> fp16 conversion kernel
// ---------------------------------------------------------------------------
__global__ __launch_bounds__(256)
void conv_kernel(const float4* __restrict__ src, __half* __restrict__ dst, int n4)
{
    int i = blockIdx.x * blockDim.x + threadIdx.x;
    if (i < n4) {
        float4 x = src[i];
        __half2 h01 = __floats2half2_rn(x.x, x.y);
        __half2 h23 = __floats2half2_rn(x.z, x.w);
        *(uint2*)&dst[(size_t)i * 4] =
            make_uint2(*(uint32_t*)&h01, *(uint32_t*)&h23);
    }
}

// ---------------------------------------------------------------------------
// FP16 tensor-core NT GEMM: C[m,n] = sum_k A[m,k] * W[n,k]
// Block 128x128, K-chunk 64, 128 threads (4 warps = 2m x 2n), warp tile 64x64,
// cp.async 2-stage (load c+1 overlaps compute c), swizzled 128B-row smem.
// 64KB smem + <=170 regs -> 3 CTAs/SM for cross-CTA bubble overlap.
// MODE 0: epilogue splits q/k/v (fp16) with relu+scale. MODE 1: bias -> fp32 out.
// ---------------------------------------------------------------------------
#define ARR_SZ 16384                  // 128 rows x 128 bytes
#define STG_B (2 * ARR_SZ)            // A, B = 32768
#define NSTG 2
#define GEMM_SMEM (NSTG * STG_B)      // 65536

template<int MODE>
__global__ __launch_bounds__(128, 3)
void gemm_tc(const __half* __restrict__ A_g,
             const __half* __restrict__ W_g,
             const float* __restrict__ bias, float* __restrict__ out)
{
    extern __shared__ __align__(128) char smem[];
    const uint32_t sbase = smem_u32(smem);
    const int tid  = threadIdx.x;
    const int lane = tid & 31;
    const int w    = tid >> 5;        // 0..3
    const int wm   = w & 1;           // m group -> rows wm*64
    const int wn   = w >> 1;          // n group -> cols wn*64
    const int m0 = blockIdx.y * 128;
    const int n0 = blockIdx.x * 128;

    const int a_row = (lane & 7) + ((lane >> 3) & 1) * 8;
    const int a_kq  = (lane >> 4) & 1;
    const int b_row = (lane & 7) + (lane >> 4) * 8;
    const int b_kq  = (lane >> 3) & 1;

    auto issue = [&](int c) {
        const uint32_t st = sbase + (c & 1) * STG_B;
        const int k0 = c * 64;
        #pragma unroll
        for (int p = 0; p < 8; p++) {
            int id = tid + p * 128;
            int row = id >> 3, quad = id & 7;
            uint32_t so = swz(row, quad);
            CP16(st + so, A_g + (size_t)(m0 + row) * Cdim + k0 + quad * 8);
            CP16(st + ARR_SZ + so, W_g + (size_t)(n0 + row) * Cdim + k0 + quad * 8);
        }
    };

    float acc[4][8][4];
    #pragma unroll
    for (int mt = 0; mt < 4; mt++)
        #pragma unroll
        for (int nt = 0; nt < 8; nt++)
            #pragma unroll
            for (int r = 0; r < 4; r++) acc[mt][nt][r] = 0.0f;

    issue(0); CP_COMMIT();

    for (int c = 0; c < 16; c++) {
        CP_WAIT0();
        __syncthreads();
        if (c + 1 < 16) { issue(c + 1); CP_COMMIT(); }

        const uint32_t st = sbase + (c & 1) * STG_B;
        const uint32_t sA = st, sB = st + ARR_SZ;

        #pragma unroll
        for (int ks = 0; ks < 4; ks++) {
            uint32_t ah[4][4];
            #pragma unroll
            for (int mt = 0; mt < 4; mt++) {
                uint32_t row = wm * 64 + mt * 16 + a_row;
                ldsm4(sA + swz(row, ks * 2 + a_kq), ah[mt]);
            }
            #pragma unroll
            for (int bt = 0; bt < 4; bt++) {
                uint32_t row = wn * 64 + bt * 16 + b_row;
                uint32_t bh[4];
                ldsm4(sB + swz(row, ks * 2 + b_kq), bh);
                #pragma unroll
                for (int half = 0; half < 2; half++) {
                    const int nt = bt * 2 + half;
                    #pragma unroll
                    for (int mt = 0; mt < 4; mt++)
                        mma16816(acc[mt][nt], ah[mt], bh[half * 2], bh[half * 2 + 1]);
                }
            }
        }
    }

    // Epilogue
    const int r4 = lane >> 2, c4 = lane & 3;
    if (MODE == 0) {
        const int sN = n0 >> 10;                 // 0:q 1:k 2:v
        __half* dst = (sN == 0) ? g_qh : (sN == 1) ? g_kh : g_vh;
        const int colb = (n0 & 1023) + wn * 64;
        #pragma unroll
        for (int mt = 0; mt < 4; mt++) {
            #pragma unroll
            for (int nt = 0; nt < 8; nt++) {
                float v0 = acc[mt][nt][0], v1 = acc[mt][nt][1];
                float v2 = acc[mt][nt][2], v3 = acc[mt][nt][3];
                if (sN < 2) {
                    v0 = fmaxf(v0, 0.0f) + SCALE_Q;
                    v1 = fmaxf(v1, 0.0f) + SCALE_Q;
                    v2 = fmaxf(v2, 0.0f) + SCALE_Q;
                    v3 = fmaxf(v3, 0.0f) + SCALE_Q;
                }
                int m = m0 + wm * 64 + mt * 16 + r4;
                int col = colb + nt * 8 + c4 * 2;
                __half2 h01 = __floats2half2_rn(v0, v1);
                __half2 h23 = __floats2half2_rn(v2, v3);
                *(uint32_t*)(dst + (size_t)m * Cdim + col)       = *(uint32_t*)&h01;
                *(uint32_t*)(dst + (size_t)(m + 8) * Cdim + col) = *(uint32_t*)&h23;
            }
        }
    } else {
        #pragma unroll
        for (int mt = 0; mt < 4; mt++) {
            #pragma unroll
            for (int nt = 0; nt < 8; nt++) {
                int m = m0 + wm * 64 + mt * 16 + r4;
                int col = n0 + wn * 64 + nt * 8 + c4 * 2;
                float b0 = __ldg(bias + col), b1 = __ldg(bias + col + 1);
                *(float2*)(out + (size_t)m * Cdim + col) =
                    make_float2(acc[mt][nt][0] + b0, acc[mt][nt][1] + b1);
                *(float2*)(out + (size_t)(m + 8) * Cdim + col) =
                    make_float2(acc[mt][nt][2] + b0, acc[mt][nt][3] + b1);
            }
        }
    }
}

// ---------------------------------------------------------------------------
// kv[bh][e][d] = sum over n of k_[bb,n,h,e] * v[bb,n,h,d]   (fp16 in, fp32 acc)
// Also computes k_sum[bh][e] (fused).
// ---------------------------------------------------------------------------
__global__ __launch_bounds__(256)
void kv_kernel()
{
    __shared__ float sk[64][68];
    __shared__ float sv[64][68];
    __shared__ float red[4][64];
    const int bh = blockIdx.x;
    const int bb = bh >> 4, h = bh & 15;
    const int tid = threadIdx.x;
    const int tx = tid & 15, ty = tid >> 4;
    const int e_id = tid & 63, part = tid >> 6;
    float acc[4][4] = {};
    float ks_part = 0.0f;
    const size_t base = (size_t)bb * Lseq * Cdim + h * En;

    for (int n0 = 0; n0 < Lseq; n0 += 64) {
        __syncthreads();
        #pragma unroll
        for (int i = 0; i < 2; i++) {
            int lin = tid + i * 256;
            int row = lin >> 3;
            int c8  = (lin & 7) * 8;
            size_t g = base + (size_t)(n0 + row) * Cdim + c8;
            uint4 uk = *(const uint4*)(g_kh + g);
            uint4 uv = *(const uint4*)(g_vh + g);
            __half2* hk = (__half2*)&uk;
            __half2* hv = (__half2*)&uv;
            #pragma unroll
            for (int j = 0; j < 4; j++) {
                *(float2*)&sk[row][c8 + j * 2] = __half22float2(hk[j]);
                *(float2*)&sv[row][c8 + j * 2] = __half22float2(hv[j]);
            }
        }
        __syncthreads();
        #pragma unroll 4
        for (int n = 0; n < 64; n++) {
            float4 a = *(const float4*)&sk[n][ty * 4];
            float4 b = *(const float4*)&sv[n][tx * 4];
            float av[4] = {a.x, a.y, a.z, a.w};
            float bv[4] = {b.x, b.y, b.z, b.w};
            #pragma unroll
            for (int i = 0; i < 4; i++)
                #pragma unroll
                for (int j = 0; j < 4; j++)
                    acc[i][j] += av[i] * bv[j];
        }
        // fused k_sum: part p sums rows p*16 .. p*16+15 for column e_id
        #pragma unroll
        for (int n = 0; n < 16; n++)
            ks_part += sk[part * 16 + n][e_id];
    }
    float* dst = g_kv + bh * (En * En);
    #pragma unroll
    for (int i = 0; i < 4; i++)
        *(float4*)&dst[(ty * 4 + i) * En + tx * 4] =
            make_float4(acc[i][0], acc[i][1], acc[i][2], acc[i][3]);

    __syncthreads();
    red[part][e_id] = ks_part;
    __syncthreads();
    if (part == 0)
        g_ksum[bh * En + e_id] = red[0][e_id] + red[1][e_id] + red[2][e_id] + red[3][e_id];
}

// ---------------------------------------------------------------------------
// out[bb,n,h,d] = (sum_e q_[bb,n,h,e] * kv[bh][e][d]) * z[n]   -> fp16
// ---------------------------------------------------------------------------
__global__ __launch_bounds__(256)
void attn_kernel()
{
    __shared__ float sq [64][68];
    __shared__ float skv[64][68];
    __shared__ float sks[64];
    __shared__ float sz [64];
    const int bh = blockIdx.y;
    const int bb = bh >> 4, h = bh & 15;
    const int n0 = blockIdx.x * 64;
    const int tid = threadIdx.x;
    const int tx = tid & 15, ty = tid >> 4;

    #pragma unroll
    for (int i = 0; i < 4; i++) {
        int lin = tid + i * 256;
        int row = lin >> 4;
        int c4  = (lin & 15) << 2;
        *(float4*)&skv[row][c4] = *(const float4*)&g_kv[bh * (En * En) + row * En + c4];
    }
    #pragma unroll
    for (int i = 0; i < 2; i++) {
        int lin = tid + i * 256;
        int row = lin >> 3;
        int c8  = (lin & 7) * 8;
        size_t g = ((size_t)bb * Lseq + n0 + row) * Cdim + h * En + c8;
        uint4 uq = *(const uint4*)(g_qh + g);
        __half2* hq = (__half2*)&uq;
        #pragma unroll
        for (int j = 0; j < 4; j++)
            *(float2*)&sq[row][c8 + j * 2] = __half22float2(hq[j]);
    }
    if (tid < 16)
        *(float4*)&sks[tid * 4] = *(const float4*)&g_ksum[bh * En + tid * 4];
    __syncthreads();

    if (tid < 64) {
        float d = 0.0f;
        #pragma unroll
        for (int e = 0; e < 64; e++) d += sq[tid][e] * sks[e];
        sz[tid] = 1.0f / (d + EPS_V);
    }
    __syncthreads();

    float acc[4][4] = {};
    #pragma unroll 4
    for (int e = 0; e < 64; e++) {
        float a0 = sq[ty * 4 + 0][e];
        float a1 = sq[ty * 4 + 1][e];
        float a2 = sq[ty * 4 + 2][e];
        float a3 = sq[ty * 4 + 3][e];
        float4 b = *(const float4*)&skv[e][tx * 4];
        acc[0][0] += a0 * b.x; acc[0][1] += a0 * b.y; acc[0][2] += a0 * b.z; acc[0][3] += a0 * b.w;
        acc[1][0] += a1 * b.x; acc[1][1] += a1 * b.y; acc[1][2] += a1 * b.z; acc[1][3] += a1 * b.w;
        acc[2][0] += a2 * b.x; acc[2][1] += a2 * b.y; acc[2][2] += a2 * b.z; acc[2][3] += a2 * b.w;
        acc[3][0] += a3 * b.x; acc[3][1] += a3 * b.y; acc[3][2] += a3 * b.z; acc[3][3] += a3 * b.w;
    }

    #pragma unroll
    for (int i = 0; i < 4; i++) {
        float z = sz[ty * 4 + i];
        __half2 h01 = __floats2half2_rn(acc[i][0] * z, acc[i][1] * z);
        __half2 h23 = __floats2half2_rn(acc[i][2] * z, acc[i][3] * z);
        size_t g = ((size_t)bb * Lseq + n0 + ty * 4 + i) * Cdim + h * En + tx * 4;
        *(uint2*)&g_ah[g] = make_uint2(*(uint32_t*)&h01, *(uint32_t*)&h23);
    }
}

// ---------------------------------------------------------------------------
extern "C" void kernel_launch(void* const* d_in, const int* in_sizes, int n_in,
                              void* d_out, int out_size)
{
    const float* x      = (const float*)d_in[0];
    const float* w_qkv  = (const float*)d_in[1];
    const float* w_proj = (const float*)d_in[2];
    const float* b_proj = (const float*)d_in[3];
    float* out = (float*)d_out;

    cudaFuncSetAttribute(gemm_tc<0>, cudaFuncAttributeMaxDynamicSharedMemorySize, GEMM_SMEM);
    cudaFuncSetAttribute(gemm_tc<1>, cudaFuncAttributeMaxDynamicSharedMemorySize, GEMM_SMEM);

    __half *xh, *ah, *wqh, *wph;
    cudaGetSymbolAddress((void**)&xh,  g_xh);
    cudaGetSymbolAddress((void**)&ah,  g_ah);
    cudaGetSymbolAddress((void**)&wqh, g_wqh);
    cudaGetSymbolAddress((void**)&wph, g_wph);

    // 0) fp32 -> fp16 conversions
    {
        int n4 = Mtok * (Cdim / 4);
        conv_kernel<<<(n4 + 255) / 256, 256>>>((const float4*)x, xh, n4);
        n4 = 3072 * Cdim / 4;
        conv_kernel<<<(n4 + 255) / 256, 256>>>((const float4*)w_qkv, wqh, n4);
        n4 = Cdim * Cdim / 4;
        conv_kernel<<<(n4 + 255) / 256, 256>>>((const float4*)w_proj, wph, n4);
    }

    // 1) qkv = x @ w_qkv^T (fp16 tensor cores), fused q/k/v split + relu+scale
    gemm_tc<0><<<dim3(24, 196), 128, GEMM_SMEM>>>(xh, wqh, nullptr, nullptr);
    // 2) kv = k_^T @ v  (+ fused k_sum)
    kv_kernel<<<128, 256>>>();
    // 3) out = (q_ @ kv) * z  -> fp16
    attn_kernel<<<dim3(49, 128), 256>>>();
    // 4) final = attn @ w_proj^T + b_proj
    gemm_tc<1><<<dim3(8, 196), 128, GEMM_SMEM>>>(ah, wph, b_proj, out);
}

// round 9
// speedup vs baseline: 6.6170x; 1.1156x over previous
#include <cuda_runtime.h>
#include <cuda_fp16.h>
#include <cstdint>

// Problem constants
#define Cdim 1024
#define Hn   16
#define En   64
#define Mtok 25088          // B*N
#define Lseq 3136           // f*N
#define NBGRP 8
#define SCALE_Q 0.125f
#define EPS_V   1e-6f
#define KVP  7              // kv sequence partitions (49 tiles = 7*7)

// Scratch (static device memory)
__device__ float g_kv  [NBGRP * Hn * En * En];
__device__ float g_ksum[NBGRP * Hn * En];
__device__ float g_kvp [KVP][NBGRP * Hn * En * En];
__device__ float g_ksp [KVP][NBGRP * Hn * En];
// fp16 tensors
__device__ __half g_xh[(size_t)Mtok * Cdim];    // x
__device__ __half g_qh[(size_t)Mtok * Cdim];    // q_ (relu+scale applied)
__device__ __half g_kh[(size_t)Mtok * Cdim];    // k_ (relu+scale applied)
__device__ __half g_vh[(size_t)Mtok * Cdim];    // v
__device__ __half g_ah[(size_t)Mtok * Cdim];    // attn output
__device__ __half g_wqh[3072 * Cdim];
__device__ __half g_wph[Cdim * Cdim];

// ---------------------------------------------------------------------------
// Helpers
// ---------------------------------------------------------------------------
__device__ __forceinline__ uint32_t smem_u32(const void* p) {
    uint32_t a;
    asm("{ .reg .u64 t; cvta.to.shared.u64 t, %1; cvt.u32.u64 %0, t; }" : "=r"(a) : "l"(p));
    return a;
}

__device__ __forceinline__ void mma16816(float* d, const uint32_t* a,
                                         uint32_t b0, uint32_t b1) {
    asm volatile(
        "mma.sync.aligned.m16n8k16.row.col.f32.f16.f16.f32 "
        "{%0,%1,%2,%3}, {%4,%5,%6,%7}, {%8,%9}, {%0,%1,%2,%3};"
        : "+f"(d[0]), "+f"(d[1]), "+f"(d[2]), "+f"(d[3])
        : "r"(a[0]), "r"(a[1]), "r"(a[2]), "r"(a[3]), "r"(b0), "r"(b1));
}

__device__ __forceinline__ void ldsm4(uint32_t addr, uint32_t* r) {
    asm volatile("ldmatrix.sync.aligned.m8n8.x4.shared.b16 {%0,%1,%2,%3}, [%4];"
                 : "=r"(r[0]), "=r"(r[1]), "=r"(r[2]), "=r"(r[3]) : "r"(addr));
}

#define CP16(dst, src) \
    asm volatile("cp.async.cg.shared.global [%0], [%1], 16;" :: "r"(dst), "l"(src))
#define CP_COMMIT() asm volatile("cp.async.commit_group;" ::: "memory")
#define CP_WAIT1()  asm volatile("cp.async.wait_group 1;" ::: "memory")

// Swizzled byte offset for 128-byte rows: row in [0,128), quad in [0,8)
__device__ __forceinline__ uint32_t swz(uint32_t row, uint32_t quad) {
    return (row << 7) + ((quad ^ (row & 7)) << 4);
}

// ---------------------------------------------------------------------------
// fp32 -> fp16 conversion kernel
// ---------------------------------------------------------------------------
__global__ __launch_bounds__(256)
void conv_kernel(const float4* __restrict__ src, __half* __restrict__ dst, int n4)
{
    int i = blockIdx.x * blockDim.x + threadIdx.x;
    if (i < n4) {
        float4 x = src[i];
        __half2 h01 = __floats2half2_rn(x.x, x.y);
        __half2 h23 = __floats2half2_rn(x.z, x.w);
        *(uint2*)&dst[(size_t)i * 4] =
            make_uint2(*(uint32_t*)&h01, *(uint32_t*)&h23);
    }
}

// ---------------------------------------------------------------------------
// FP16 tensor-core NT GEMM: C[m,n] = sum_k A[m,k] * W[n,k]
// Block 128x128, K-chunk 64, 128 threads (4 warps = 2m x 2n), warp tile 64x64.
// A fragments for the WHOLE chunk hoisted before the MMA loop (software
// pipelining: MMA stream only interleaves B-LDSM, 1 per 8 MMAs).
// cp.async 3-stage, wait_group 1. 96KB smem, 2 CTAs/SM.
// MODE 0: epilogue splits q/k/v (fp16) with relu+scale. MODE 1: bias -> fp32 out.
// ---------------------------------------------------------------------------
#define ARR_SZ 16384                  // 128 rows x 128 bytes
#define STG_B (2 * ARR_SZ)            // A, B = 32768
#define NSTG 3
#define GEMM_SMEM (NSTG * STG_B)      // 98304

template<int MODE>
__global__ __launch_bounds__(128, 2)
void gemm_tc(const __half* __restrict__ A_g,
             const __half* __restrict__ W_g,
             const float* __restrict__ bias, float* __restrict__ out)
{
    extern __shared__ __align__(128) char smem[];
    const uint32_t sbase = smem_u32(smem);
    const int tid  = threadIdx.x;
    const int lane = tid & 31;
    const int w    = tid >> 5;        // 0..3
    const int wm   = w & 1;           // m group -> rows wm*64
    const int wn   = w >> 1;          // n group -> cols wn*64
    const int m0 = blockIdx.y * 128;
    const int n0 = blockIdx.x * 128;

    const int a_row = (lane & 7) + ((lane >> 3) & 1) * 8;
    const int a_kq  = (lane >> 4) & 1;
    const int b_row = (lane & 7) + (lane >> 4) * 8;
    const int b_kq  = (lane >> 3) & 1;

    auto issue = [&](int c) {
        const uint32_t st = sbase + (c % NSTG) * STG_B;
        const int k0 = c * 64;
        #pragma unroll
        for (int p = 0; p < 8; p++) {
            int id = tid + p * 128;
            int row = id >> 3, quad = id & 7;
            uint32_t so = swz(row, quad);
            CP16(st + so, A_g + (size_t)(m0 + row) * Cdim + k0 + quad * 8);
            CP16(st + ARR_SZ + so, W_g + (size_t)(n0 + row) * Cdim + k0 + quad * 8);
        }
    };

    float acc[4][8][4];
    #pragma unroll
    for (int mt = 0; mt < 4; mt++)
        #pragma unroll
        for (int nt = 0; nt < 8; nt++)
            #pragma unroll
            for (int r = 0; r < 4; r++) acc[mt][nt][r] = 0.0f;

    issue(0); CP_COMMIT();
    issue(1); CP_COMMIT();

    for (int c = 0; c < 16; c++) {
        CP_WAIT1();
        __syncthreads();
        if (c + 2 < 16) { issue(c + 2); CP_COMMIT(); }

        const uint32_t st = sbase + (c % NSTG) * STG_B;
        const uint32_t sA = st, sB = st + ARR_SZ;

        // Hoist all A fragments for this chunk (16 LDSM -> 64 regs)
        uint32_t ah[4][4][4];
        #pragma unroll
        for (int ks = 0; ks < 4; ks++)
            #pragma unroll
            for (int mt = 0; mt < 4; mt++) {
                uint32_t row = wm * 64 + mt * 16 + a_row;
                ldsm4(sA + swz(row, ks * 2 + a_kq), ah[ks][mt]);
            }

        #pragma unroll
        for (int ks = 0; ks < 4; ks++) {
            #pragma unroll
            for (int bt = 0; bt < 4; bt++) {
                uint32_t row = wn * 64 + bt * 16 + b_row;
                uint32_t bh[4];
                ldsm4(sB + swz(row, ks * 2 + b_kq), bh);
                #pragma unroll
                for (int half = 0; half < 2; half++) {
                    const int nt = bt * 2 + half;
                    #pragma unroll
                    for (int mt = 0; mt < 4; mt++)
                        mma16816(acc[mt][nt], ah[ks][mt], bh[half * 2], bh[half * 2 + 1]);
                }
            }
        }
    }

    // Epilogue
    const int r4 = lane >> 2, c4 = lane & 3;
    if (MODE == 0) {
        const int sN = n0 >> 10;                 // 0:q 1:k 2:v
        __half* dst = (sN == 0) ? g_qh : (sN == 1) ? g_kh : g_vh;
        const int colb = (n0 & 1023) + wn * 64;
        #pragma unroll
        for (int mt = 0; mt < 4; mt++) {
            #pragma unroll
            for (int nt = 0; nt < 8; nt++) {
                float v0 = acc[mt][nt][0], v1 = acc[mt][nt][1];
                float v2 = acc[mt][nt][2], v3 = acc[mt][nt][3];
                if (sN < 2) {
                    v0 = fmaxf(v0, 0.0f) + SCALE_Q;
                    v1 = fmaxf(v1, 0.0f) + SCALE_Q;
                    v2 = fmaxf(v2, 0.0f) + SCALE_Q;
                    v3 = fmaxf(v3, 0.0f) + SCALE_Q;
                }
                int m = m0 + wm * 64 + mt * 16 + r4;
                int col = colb + nt * 8 + c4 * 2;
                __half2 h01 = __floats2half2_rn(v0, v1);
                __half2 h23 = __floats2half2_rn(v2, v3);
                *(uint32_t*)(dst + (size_t)m * Cdim + col)       = *(uint32_t*)&h01;
                *(uint32_t*)(dst + (size_t)(m + 8) * Cdim + col) = *(uint32_t*)&h23;
            }
        }
    } else {
        #pragma unroll
        for (int mt = 0; mt < 4; mt++) {
            #pragma unroll
            for (int nt = 0; nt < 8; nt++) {
                int m = m0 + wm * 64 + mt * 16 + r4;
                int col = n0 + wn * 64 + nt * 8 + c4 * 2;
                float b0 = __ldg(bias + col), b1 = __ldg(bias + col + 1);
                *(float2*)(out + (size_t)m * Cdim + col) =
                    make_float2(acc[mt][nt][0] + b0, acc[mt][nt][1] + b1);
                *(float2*)(out + (size_t)(m + 8) * Cdim + col) =
                    make_float2(acc[mt][nt][2] + b0, acc[mt][nt][3] + b1);
            }
        }
    }
}

// ---------------------------------------------------------------------------
// Partial kv: kvp[p][bh][e][d] = sum over partition p's tiles of k_ * v
// grid (128 bh, KVP partitions); each block handles 7 tiles of 64 rows.
// Also partial k_sum.
// ---------------------------------------------------------------------------
__global__ __launch_bounds__(256)
void kvp_kernel()
{
    __shared__ float sk[64][68];
    __shared__ float sv[64][68];
    __shared__ float red[4][64];
    const int bh = blockIdx.x;
    const int prt = blockIdx.y;
    const int bb = bh >> 4, h = bh & 15;
    const int tid = threadIdx.x;
    const int tx = tid & 15, ty = tid >> 4;
    const int e_id = tid & 63, part = tid >> 6;
    float acc[4][4] = {};
    float ks_part = 0.0f;
    const size_t base = (size_t)bb * Lseq * Cdim + h * En;

    for (int it = 0; it < 7; it++) {
        const int n0 = (prt * 7 + it) * 64;
        __syncthreads();
        #pragma unroll
        for (int i = 0; i < 2; i++) {
            int lin = tid + i * 256;
            int row = lin >> 3;
            int c8  = (lin & 7) * 8;
            size_t g = base + (size_t)(n0 + row) * Cdim + c8;
            uint4 uk = *(const uint4*)(g_kh + g);
            uint4 uv = *(const uint4*)(g_vh + g);
            __half2* hk = (__half2*)&uk;
            __half2* hv = (__half2*)&uv;
            #pragma unroll
            for (int j = 0; j < 4; j++) {
                *(float2*)&sk[row][c8 + j * 2] = __half22float2(hk[j]);
                *(float2*)&sv[row][c8 + j * 2] = __half22float2(hv[j]);
            }
        }
        __syncthreads();
        #pragma unroll 4
        for (int n = 0; n < 64; n++) {
            float4 a = *(const float4*)&sk[n][ty * 4];
            float4 b = *(const float4*)&sv[n][tx * 4];
            float av[4] = {a.x, a.y, a.z, a.w};
            float bv[4] = {b.x, b.y, b.z, b.w};
            #pragma unroll
            for (int i = 0; i < 4; i++)
                #pragma unroll
                for (int j = 0; j < 4; j++)
                    acc[i][j] += av[i] * bv[j];
        }
        #pragma unroll
        for (int n = 0; n < 16; n++)
            ks_part += sk[part * 16 + n][e_id];
    }
    float* dst = g_kvp[prt] + bh * (En * En);
    #pragma unroll
    for (int i = 0; i < 4; i++)
        *(float4*)&dst[(ty * 4 + i) * En + tx * 4] =
            make_float4(acc[i][0], acc[i][1], acc[i][2], acc[i][3]);

    __syncthreads();
    red[part][e_id] = ks_part;
    __syncthreads();
    if (part == 0)
        g_ksp[prt][bh * En + e_id] =
            red[0][e_id] + red[1][e_id] + red[2][e_id] + red[3][e_id];
}

// ---------------------------------------------------------------------------
// Reduce partial kv/ksum over the KVP partitions.
// ---------------------------------------------------------------------------
__global__ __launch_bounds__(256)
void kvred_kernel()
{
    const int bh = blockIdx.x;
    const int tid = threadIdx.x;
    #pragma unroll
    for (int i = 0; i < 16; i++) {
        int idx = bh * (En * En) + tid + i * 256;
        float s = 0.0f;
        #pragma unroll
        for (int p = 0; p < KVP; p++) s += g_kvp[p][idx];
        g_kv[idx] = s;
    }
    if (tid < 64) {
        float s = 0.0f;
        #pragma unroll
        for (int p = 0; p < KVP; p++) s += g_ksp[p][bh * En + tid];
        g_ksum[bh * En + tid] = s;
    }
}

// ---------------------------------------------------------------------------
// out[bb,n,h,d] = (sum_e q_[bb,n,h,e] * kv[bh][e][d]) * z[n]   -> fp16
// ---------------------------------------------------------------------------
__global__ __launch_bounds__(256)
void attn_kernel()
{
    __shared__ float sq [64][68];
    __shared__ float skv[64][68];
    __shared__ float sks[64];
    __shared__ float sz [64];
    const int bh = blockIdx.y;
    const int bb = bh >> 4, h = bh & 15;
    const int n0 = blockIdx.x * 64;
    const int tid = threadIdx.x;
    const int tx = tid & 15, ty = tid >> 4;

    #pragma unroll
    for (int i = 0; i < 4; i++) {
        int lin = tid + i * 256;
        int row = lin >> 4;
        int c4  = (lin & 15) << 2;
        *(float4*)&skv[row][c4] = *(const float4*)&g_kv[bh * (En * En) + row * En + c4];
    }
    #pragma unroll
    for (int i = 0; i < 2; i++) {
        int lin = tid + i * 256;
        int row = lin >> 3;
        int c8  = (lin & 7) * 8;
        size_t g = ((size_t)bb * Lseq + n0 + row) * Cdim + h * En + c8;
        uint4 uq = *(const uint4*)(g_qh + g);
        __half2* hq = (__half2*)&uq;
        #pragma unroll
        for (int j = 0; j < 4; j++)
            *(float2*)&sq[row][c8 + j * 2] = __half22float2(hq[j]);
    }
    if (tid < 16)
        *(float4*)&sks[tid * 4] = *(const float4*)&g_ksum[bh * En + tid * 4];
    __syncthreads();

    if (tid < 64) {
        float d = 0.0f;
        #pragma unroll
        for (int e = 0; e < 64; e++) d += sq[tid][e] * sks[e];
        sz[tid] = 1.0f / (d + EPS_V);
    }
    __syncthreads();

    float acc[4][4] = {};
    #pragma unroll 4
    for (int e = 0; e < 64; e++) {
        float a0 = sq[ty * 4 + 0][e];
        float a1 = sq[ty * 4 + 1][e];
        float a2 = sq[ty * 4 + 2][e];
        float a3 = sq[ty * 4 + 3][e];
        float4 b = *(const float4*)&skv[e][tx * 4];
        acc[0][0] += a0 * b.x; acc[0][1] += a0 * b.y; acc[0][2] += a0 * b.z; acc[0][3] += a0 * b.w;
        acc[1][0] += a1 * b.x; acc[1][1] += a1 * b.y; acc[1][2] += a1 * b.z; acc[1][3] += a1 * b.w;
        acc[2][0] += a2 * b.x; acc[2][1] += a2 * b.y; acc[2][2] += a2 * b.z; acc[2][3] += a2 * b.w;
        acc[3][0] += a3 * b.x; acc[3][1] += a3 * b.y; acc[3][2] += a3 * b.z; acc[3][3] += a3 * b.w;
    }

    #pragma unroll
    for (int i = 0; i < 4; i++) {
        float z = sz[ty * 4 + i];
        __half2 h01 = __floats2half2_rn(acc[i][0] * z, acc[i][1] * z);
        __half2 h23 = __floats2half2_rn(acc[i][2] * z, acc[i][3] * z);
        size_t g = ((size_t)bb * Lseq + n0 + ty * 4 + i) * Cdim + h * En + tx * 4;
        *(uint2*)&g_ah[g] = make_uint2(*(uint32_t*)&h01, *(uint32_t*)&h23);
    }
}

// ---------------------------------------------------------------------------
extern "C" void kernel_launch(void* const* d_in, const int* in_sizes, int n_in,
                              void* d_out, int out_size)
{
    const float* x      = (const float*)d_in[0];
    const float* w_qkv  = (const float*)d_in[1];
    const float* w_proj = (const float*)d_in[2];
    const float* b_proj = (const float*)d_in[3];
    float* out = (float*)d_out;

    cudaFuncSetAttribute(gemm_tc<0>, cudaFuncAttributeMaxDynamicSharedMemorySize, GEMM_SMEM);
    cudaFuncSetAttribute(gemm_tc<1>, cudaFuncAttributeMaxDynamicSharedMemorySize, GEMM_SMEM);

    __half *xh, *ah, *wqh, *wph;
    cudaGetSymbolAddress((void**)&xh,  g_xh);
    cudaGetSymbolAddress((void**)&ah,  g_ah);
    cudaGetSymbolAddress((void**)&wqh, g_wqh);
    cudaGetSymbolAddress((void**)&wph, g_wph);

    // 0) fp32 -> fp16 conversions
    {
        int n4 = Mtok * (Cdim / 4);
        conv_kernel<<<(n4 + 255) / 256, 256>>>((const float4*)x, xh, n4);
        n4 = 3072 * Cdim / 4;
        conv_kernel<<<(n4 + 255) / 256, 256>>>((const float4*)w_qkv, wqh, n4);
        n4 = Cdim * Cdim / 4;
        conv_kernel<<<(n4 + 255) / 256, 256>>>((const float4*)w_proj, wph, n4);
    }

    // 1) qkv = x @ w_qkv^T (fp16 tensor cores), fused q/k/v split + relu+scale
    gemm_tc<0><<<dim3(24, 196), 128, GEMM_SMEM>>>(xh, wqh, nullptr, nullptr);
    // 2) partial kv (+ partial k_sum), then reduce
    kvp_kernel<<<dim3(128, KVP), 256>>>();
    kvred_kernel<<<128, 256>>>();
    // 3) out = (q_ @ kv) * z  -> fp16
    attn_kernel<<<dim3(49, 128), 256>>>();
    // 4) final = attn @ w_proj^T + b_proj
    gemm_tc<1><<<dim3(8, 196), 128, GEMM_SMEM>>>(ah, wph, b_proj, out);
}

// round 10
// speedup vs baseline: 6.9674x; 1.0529x over previous
#include <cuda_runtime.h>
#include <cuda_fp16.h>
#include <cstdint>

// Problem constants
#define Cdim 1024
#define Hn   16
#define En   64
#define Mtok 25088          // B*N
#define Lseq 3136           // f*N
#define NBGRP 8
#define SCALE_Q 0.125f
#define EPS_V   1e-6f
#define KVP  7              // kv sequence partitions

#define N4X  (Mtok * (Cdim / 4))
#define N4WQ (3072 * Cdim / 4)
#define N4WP (Cdim * Cdim / 4)

// Scratch (static device memory)
__device__ float g_kv  [NBGRP * Hn * En * En];
__device__ float g_ksum[NBGRP * Hn * En];
__device__ float g_kvp [KVP][NBGRP * Hn * En * En];
__device__ float g_ksp [KVP][NBGRP * Hn * En];
// fp16 tensors
__device__ __half g_xh[(size_t)Mtok * Cdim];
__device__ __half g_qh[(size_t)Mtok * Cdim];
__device__ __half g_kh[(size_t)Mtok * Cdim];
__device__ __half g_vh[(size_t)Mtok * Cdim];
__device__ __half g_ah[(size_t)Mtok * Cdim];
__device__ __half g_wqh[3072 * Cdim];
__device__ __half g_wph[Cdim * Cdim];

// ---------------------------------------------------------------------------
// Helpers
// ---------------------------------------------------------------------------
__device__ __forceinline__ uint32_t smem_u32(const void* p) {
    uint32_t a;
    asm("{ .reg .u64 t; cvta.to.shared.u64 t, %1; cvt.u32.u64 %0, t; }" : "=r"(a) : "l"(p));
    return a;
}

__device__ __forceinline__ void mma16816(float* d, const uint32_t* a,
                                         uint32_t b0, uint32_t b1) {
    asm volatile(
        "mma.sync.aligned.m16n8k16.row.col.f32.f16.f16.f32 "
        "{%0,%1,%2,%3}, {%4,%5,%6,%7}, {%8,%9}, {%0,%1,%2,%3};"
        : "+f"(d[0]), "+f"(d[1]), "+f"(d[2]), "+f"(d[3])
        : "r"(a[0]), "r"(a[1]), "r"(a[2]), "r"(a[3]), "r"(b0), "r"(b1));
}

__device__ __forceinline__ void ldsm4(uint32_t addr, uint32_t* r) {
    asm volatile("ldmatrix.sync.aligned.m8n8.x4.shared.b16 {%0,%1,%2,%3}, [%4];"
                 : "=r"(r[0]), "=r"(r[1]), "=r"(r[2]), "=r"(r[3]) : "r"(addr));
}

#define FMA2(acc, a, b) \
    asm("fma.rn.f32x2 %0, %1, %2, %0;" : "+l"(acc) : "l"(a), "l"(b))

__device__ __forceinline__ float ull_lo(unsigned long long v) {
    return __uint_as_float((unsigned)(v & 0xffffffffull));
}
__device__ __forceinline__ float ull_hi(unsigned long long v) {
    return __uint_as_float((unsigned)(v >> 32));
}

#define CP16(dst, src) \
    asm volatile("cp.async.cg.shared.global [%0], [%1], 16;" :: "r"(dst), "l"(src))
#define CP_COMMIT() asm volatile("cp.async.commit_group;" ::: "memory")
#define CP_WAIT1()  asm volatile("cp.async.wait_group 1;" ::: "memory")

// Swizzled byte offset for 128-byte rows: row in [0,128), quad in [0,8)
__device__ __forceinline__ uint32_t swz(uint32_t row, uint32_t quad) {
    return (row << 7) + ((quad ^ (row & 7)) << 4);
}

// sigma row remap for transposed f32x2 tiles: d -> (d%4)*16 + d/4
__device__ __forceinline__ int sgm(int d) { return (d & 3) * 16 + (d >> 2); }

// ---------------------------------------------------------------------------
// Fused fp32 -> fp16 conversion (x, w_qkv, w_proj in one launch)
// ---------------------------------------------------------------------------
__global__ __launch_bounds__(256)
void conv_all(const float4* __restrict__ x, const float4* __restrict__ wq,
              const float4* __restrict__ wp)
{
    int i = blockIdx.x * 256 + threadIdx.x;
    const float4* src; __half* dst; int j;
    if (i < N4X)                { src = x;  dst = g_xh;  j = i; }
    else if (i < N4X + N4WQ)    { src = wq; dst = g_wqh; j = i - N4X; }
    else if (i < N4X + N4WQ + N4WP) { src = wp; dst = g_wph; j = i - N4X - N4WQ; }
    else return;
    float4 v = src[j];
    __half2 h01 = __floats2half2_rn(v.x, v.y);
    __half2 h23 = __floats2half2_rn(v.z, v.w);
    *(uint2*)&dst[(size_t)j * 4] = make_uint2(*(uint32_t*)&h01, *(uint32_t*)&h23);
}

// ---------------------------------------------------------------------------
// FP16 tensor-core NT GEMM: C[m,n] = sum_k A[m,k] * W[n,k]
// Block 128x128, K-chunk 64, 4 warps, warp tile 64x64. A fragments hoisted
// per chunk; B fragments double-buffered across the 16 (ks,bt) iterations.
// cp.async 3-stage, wait_group 1. 96KB smem, 2 CTAs/SM.
// ---------------------------------------------------------------------------
#define ARR_SZ 16384
#define STG_B (2 * ARR_SZ)
#define NSTG 3
#define GEMM_SMEM (NSTG * STG_B)

template<int MODE>
__global__ __launch_bounds__(128, 2)
void gemm_tc(const __half* __restrict__ A_g,
             const __half* __restrict__ W_g,
             const float* __restrict__ bias, float* __restrict__ out)
{
    extern __shared__ __align__(128) char smem[];
    const uint32_t sbase = smem_u32(smem);
    const int tid  = threadIdx.x;
    const int lane = tid & 31;
    const int w    = tid >> 5;
    const int wm   = w & 1;
    const int wn   = w >> 1;
    const int m0 = blockIdx.y * 128;
    const int n0 = blockIdx.x * 128;

    const int a_row = (lane & 7) + ((lane >> 3) & 1) * 8;
    const int a_kq  = (lane >> 4) & 1;
    const int b_row = (lane & 7) + (lane >> 4) * 8;
    const int b_kq  = (lane >> 3) & 1;

    auto issue = [&](int c) {
        const uint32_t st = sbase + (c % NSTG) * STG_B;
        const int k0 = c * 64;
        #pragma unroll
        for (int p = 0; p < 8; p++) {
            int id = tid + p * 128;
            int row = id >> 3, quad = id & 7;
            uint32_t so = swz(row, quad);
            CP16(st + so, A_g + (size_t)(m0 + row) * Cdim + k0 + quad * 8);
            CP16(st + ARR_SZ + so, W_g + (size_t)(n0 + row) * Cdim + k0 + quad * 8);
        }
    };

    float acc[4][8][4];
    #pragma unroll
    for (int mt = 0; mt < 4; mt++)
        #pragma unroll
        for (int nt = 0; nt < 8; nt++)
            #pragma unroll
            for (int r = 0; r < 4; r++) acc[mt][nt][r] = 0.0f;

    issue(0); CP_COMMIT();
    issue(1); CP_COMMIT();

    for (int c = 0; c < 16; c++) {
        CP_WAIT1();
        __syncthreads();
        if (c + 2 < 16) { issue(c + 2); CP_COMMIT(); }

        const uint32_t st = sbase + (c % NSTG) * STG_B;
        const uint32_t sA = st, sB = st + ARR_SZ;

        // Hoist all A fragments for this chunk
        uint32_t ah[4][4][4];
        #pragma unroll
        for (int ks = 0; ks < 4; ks++)
            #pragma unroll
            for (int mt = 0; mt < 4; mt++) {
                uint32_t row = wm * 64 + mt * 16 + a_row;
                ldsm4(sA + swz(row, ks * 2 + a_kq), ah[ks][mt]);
            }

        // B double-buffered over flattened (ks, bt) iterations
        uint32_t bf[2][4];
        {
            uint32_t row = wn * 64 + 0 * 16 + b_row;
            ldsm4(sB + swz(row, 0 * 2 + b_kq), bf[0]);
        }
        #pragma unroll
        for (int it = 0; it < 16; it++) {
            const int ks = it >> 2, bt = it & 3;
            if (it + 1 < 16) {
                const int ks2 = (it + 1) >> 2, bt2 = (it + 1) & 3;
                uint32_t row = wn * 64 + bt2 * 16 + b_row;
                ldsm4(sB + swz(row, ks2 * 2 + b_kq), bf[(it + 1) & 1]);
            }
            const uint32_t* bh = bf[it & 1];
            #pragma unroll
            for (int half = 0; half < 2; half++) {
                const int nt = bt * 2 + half;
                #pragma unroll
                for (int mt = 0; mt < 4; mt++)
                    mma16816(acc[mt][nt], ah[ks][mt], bh[half * 2], bh[half * 2 + 1]);
            }
        }
    }

    // Epilogue
    const int r4 = lane >> 2, c4 = lane & 3;
    if (MODE == 0) {
        const int sN = n0 >> 10;                 // 0:q 1:k 2:v
        __half* dst = (sN == 0) ? g_qh : (sN == 1) ? g_kh : g_vh;
        const int colb = (n0 & 1023) + wn * 64;
        #pragma unroll
        for (int mt = 0; mt < 4; mt++) {
            #pragma unroll
            for (int nt = 0; nt < 8; nt++) {
                float v0 = acc[mt][nt][0], v1 = acc[mt][nt][1];
                float v2 = acc[mt][nt][2], v3 = acc[mt][nt][3];
                if (sN < 2) {
                    v0 = fmaxf(v0, 0.0f) + SCALE_Q;
                    v1 = fmaxf(v1, 0.0f) + SCALE_Q;
                    v2 = fmaxf(v2, 0.0f) + SCALE_Q;
                    v3 = fmaxf(v3, 0.0f) + SCALE_Q;
                }
                int m = m0 + wm * 64 + mt * 16 + r4;
                int col = colb + nt * 8 + c4 * 2;
                __half2 h01 = __floats2half2_rn(v0, v1);
                __half2 h23 = __floats2half2_rn(v2, v3);
                *(uint32_t*)(dst + (size_t)m * Cdim + col)       = *(uint32_t*)&h01;
                *(uint32_t*)(dst + (size_t)(m + 8) * Cdim + col) = *(uint32_t*)&h23;
            }
        }
    } else {
        #pragma unroll
        for (int mt = 0; mt < 4; mt++) {
            #pragma unroll
            for (int nt = 0; nt < 8; nt++) {
                int m = m0 + wm * 64 + mt * 16 + r4;
                int col = n0 + wn * 64 + nt * 8 + c4 * 2;
                float b0 = __ldg(bias + col), b1 = __ldg(bias + col + 1);
                *(float2*)(out + (size_t)m * Cdim + col) =
                    make_float2(acc[mt][nt][0] + b0, acc[mt][nt][1] + b1);
                *(float2*)(out + (size_t)(m + 8) * Cdim + col) =
                    make_float2(acc[mt][nt][2] + b0, acc[mt][nt][3] + b1);
            }
        }
    }
}

// ---------------------------------------------------------------------------
// Partial kv + partial k_sum. Transposed sigma-mapped tiles; f32x2-packed
// accumulation over n (two sequence steps per FFMA2).
// ---------------------------------------------------------------------------
__global__ __launch_bounds__(256)
void kvp_kernel()
{
    __shared__ __align__(16) float skT[64][66];   // row sgm(e), col n
    __shared__ __align__(16) float svT[64][66];   // row sgm(d), col n
    __shared__ float red[4][64];
    const int bh = blockIdx.x;
    const int prt = blockIdx.y;
    const int bb = bh >> 4, h = bh & 15;
    const int tid = threadIdx.x;
    const int tx = tid & 15, ty = tid >> 4;
    const int e_id = tid & 63, part = tid >> 6;
    unsigned long long acc2[4][4] = {};
    float ks_part = 0.0f;
    const size_t base = (size_t)bb * Lseq * Cdim + h * En;
    const int se = sgm(e_id);

    for (int it = 0; it < 7; it++) {
        const int n0 = (prt * 7 + it) * 64;
        __syncthreads();
        #pragma unroll
        for (int i = 0; i < 2; i++) {
            int lin = tid + i * 256;
            int row = lin >> 3;
            int c8  = (lin & 7) * 8;
            size_t g = base + (size_t)(n0 + row) * Cdim + c8;
            uint4 uk = *(const uint4*)(g_kh + g);
            uint4 uv = *(const uint4*)(g_vh + g);
            __half2* hk = (__half2*)&uk;
            __half2* hv = (__half2*)&uv;
            #pragma unroll
            for (int j = 0; j < 4; j++) {
                float2 fk = __half22float2(hk[j]);
                float2 fv = __half22float2(hv[j]);
                skT[sgm(c8 + j * 2)][row]     = fk.x;
                skT[sgm(c8 + j * 2 + 1)][row] = fk.y;
                svT[sgm(c8 + j * 2)][row]     = fv.x;
                svT[sgm(c8 + j * 2 + 1)][row] = fv.y;
            }
        }
        __syncthreads();
        #pragma unroll 2
        for (int n = 0; n < 64; n += 2) {
            unsigned long long a2[4], b2[4];
            #pragma unroll
            for (int i = 0; i < 4; i++)
                a2[i] = *(const unsigned long long*)&skT[i * 16 + ty][n];
            #pragma unroll
            for (int j = 0; j < 4; j++)
                b2[j] = *(const unsigned long long*)&svT[j * 16 + tx][n];
            #pragma unroll
            for (int i = 0; i < 4; i++)
                #pragma unroll
                for (int j = 0; j < 4; j++)
                    FMA2(acc2[i][j], a2[i], b2[j]);
        }
        // fused k_sum: part p sums n in [p*16, p*16+16) of column e_id
        #pragma unroll
        for (int n = 0; n < 16; n++)
            ks_part += skT[se][part * 16 + n];
    }
    float* dst = g_kvp[prt] + bh * (En * En);
    #pragma unroll
    for (int i = 0; i < 4; i++) {
        float4 v;
        v.x = ull_lo(acc2[i][0]) + ull_hi(acc2[i][0]);
        v.y = ull_lo(acc2[i][1]) + ull_hi(acc2[i][1]);
        v.z = ull_lo(acc2[i][2]) + ull_hi(acc2[i][2]);
        v.w = ull_lo(acc2[i][3]) + ull_hi(acc2[i][3]);
        *(float4*)&dst[(ty * 4 + i) * En + tx * 4] = v;
    }

    __syncthreads();
    red[part][e_id] = ks_part;
    __syncthreads();
    if (part == 0)
        g_ksp[prt][bh * En + e_id] =
            red[0][e_id] + red[1][e_id] + red[2][e_id] + red[3][e_id];
}

// ---------------------------------------------------------------------------
// Reduce partial kv/ksum over the KVP partitions.
// ---------------------------------------------------------------------------
__global__ __launch_bounds__(256)
void kvred_kernel()
{
    const int bh = blockIdx.x;
    const int tid = threadIdx.x;
    #pragma unroll
    for (int i = 0; i < 16; i++) {
        int idx = bh * (En * En) + tid + i * 256;
        float s = 0.0f;
        #pragma unroll
        for (int p = 0; p < KVP; p++) s += g_kvp[p][idx];
        g_kv[idx] = s;
    }
    if (tid < 64) {
        float s = 0.0f;
        #pragma unroll
        for (int p = 0; p < KVP; p++) s += g_ksp[p][bh * En + tid];
        g_ksum[bh * En + tid] = s;
    }
}

// ---------------------------------------------------------------------------
// out = (q_ @ kv) * z -> fp16. kv stored transposed (sigma-mapped) in smem;
// f32x2-packed accumulation over e (two e-steps per FFMA2).
// ---------------------------------------------------------------------------
__global__ __launch_bounds__(256)
void attn_kernel()
{
    __shared__ __align__(16) float sq [64][68];   // [n_row][e]
    __shared__ __align__(16) float skvt[64][66];  // row sgm(d), col e
    __shared__ float sks[64];
    __shared__ float sz [64];
    const int bh = blockIdx.y;
    const int bb = bh >> 4, h = bh & 15;
    const int n0 = blockIdx.x * 64;
    const int tid = threadIdx.x;
    const int tx = tid & 15, ty = tid >> 4;

    #pragma unroll
    for (int it = 0; it < 4; it++) {
        int lin = tid + it * 256;
        int e   = lin >> 4;
        int c4  = (lin & 15) * 4;
        float4 v = *(const float4*)&g_kv[bh * (En * En) + e * En + c4];
        skvt[sgm(c4 + 0)][e] = v.x;
        skvt[sgm(c4 + 1)][e] = v.y;
        skvt[sgm(c4 + 2)][e] = v.z;
        skvt[sgm(c4 + 3)][e] = v.w;
    }
    #pragma unroll
    for (int i = 0; i < 2; i++) {
        int lin = tid + i * 256;
        int row = lin >> 3;
        int c8  = (lin & 7) * 8;
        size_t g = ((size_t)bb * Lseq + n0 + row) * Cdim + h * En + c8;
        uint4 uq = *(const uint4*)(g_qh + g);
        __half2* hq = (__half2*)&uq;
        #pragma unroll
        for (int j = 0; j < 4; j++)
            *(float2*)&sq[row][c8 + j * 2] = __half22float2(hq[j]);
    }
    if (tid < 16)
        *(float4*)&sks[tid * 4] = *(const float4*)&g_ksum[bh * En + tid * 4];
    __syncthreads();

    if (tid < 64) {
        float d = 0.0f;
        #pragma unroll
        for (int e = 0; e < 64; e++) d += sq[tid][e] * sks[e];
        sz[tid] = 1.0f / (d + EPS_V);
    }
    __syncthreads();

    unsigned long long acc2[4][4] = {};
    #pragma unroll 2
    for (int e = 0; e < 64; e += 2) {
        unsigned long long a2[4], b2[4];
        #pragma unroll
        for (int i = 0; i < 4; i++)
            a2[i] = *(const unsigned long long*)&sq[ty * 4 + i][e];
        #pragma unroll
        for (int j = 0; j < 4; j++)
            b2[j] = *(const unsigned long long*)&skvt[j * 16 + tx][e];
        #pragma unroll
        for (int i = 0; i < 4; i++)
            #pragma unroll
            for (int j = 0; j < 4; j++)
                FMA2(acc2[i][j], a2[i], b2[j]);
    }

    #pragma unroll
    for (int i = 0; i < 4; i++) {
        float z = sz[ty * 4 + i];
        float v0 = (ull_lo(acc2[i][0]) + ull_hi(acc2[i][0])) * z;
        float v1 = (ull_lo(acc2[i][1]) + ull_hi(acc2[i][1])) * z;
        float v2 = (ull_lo(acc2[i][2]) + ull_hi(acc2[i][2])) * z;
        float v3 = (ull_lo(acc2[i][3]) + ull_hi(acc2[i][3])) * z;
        __half2 h01 = __floats2half2_rn(v0, v1);
        __half2 h23 = __floats2half2_rn(v2, v3);
        size_t g = ((size_t)bb * Lseq + n0 + ty * 4 + i) * Cdim + h * En + tx * 4;
        *(uint2*)&g_ah[g] = make_uint2(*(uint32_t*)&h01, *(uint32_t*)&h23);
    }
}

// ---------------------------------------------------------------------------
extern "C" void kernel_launch(void* const* d_in, const int* in_sizes, int n_in,
                              void* d_out, int out_size)
{
    const float* x      = (const float*)d_in[0];
    const float* w_qkv  = (const float*)d_in[1];
    const float* w_proj = (const float*)d_in[2];
    const float* b_proj = (const float*)d_in[3];
    float* out = (float*)d_out;

    cudaFuncSetAttribute(gemm_tc<0>, cudaFuncAttributeMaxDynamicSharedMemorySize, GEMM_SMEM);
    cudaFuncSetAttribute(gemm_tc<1>, cudaFuncAttributeMaxDynamicSharedMemorySize, GEMM_SMEM);

    __half *xh, *ah, *wqh, *wph;
    cudaGetSymbolAddress((void**)&xh,  g_xh);
    cudaGetSymbolAddress((void**)&ah,  g_ah);
    cudaGetSymbolAddress((void**)&wqh, g_wqh);
    cudaGetSymbolAddress((void**)&wph, g_wph);

    // 0) fused fp32 -> fp16 conversions (one launch)
    {
        int total = N4X + N4WQ + N4WP;
        conv_all<<<(total + 255) / 256, 256>>>(
            (const float4*)x, (const float4*)w_qkv, (const float4*)w_proj);
    }

    // 1) qkv = x @ w_qkv^T (fp16 tensor cores), fused q/k/v split + relu+scale
    gemm_tc<0><<<dim3(24, 196), 128, GEMM_SMEM>>>(xh, wqh, nullptr, nullptr);
    // 2) partial kv (+ partial k_sum), then reduce
    kvp_kernel<<<dim3(128, KVP), 256>>>();
    kvred_kernel<<<128, 256>>>();
    // 3) out = (q_ @ kv) * z  -> fp16
    attn_kernel<<<dim3(49, 128), 256>>>();
    // 4) final = attn @ w_proj^T + b_proj
    gemm_tc<1><<<dim3(8, 196), 128, GEMM_SMEM>>>(ah, wph, b_proj, out);
}

// round 11
// speedup vs baseline: 7.0062x; 1.0056x over previous
#include <cuda_runtime.h>
#include <cuda_fp16.h>
#include <cstdint>

// Problem constants
#define Cdim 1024
#define Hn   16
#define En   64
#define Mtok 25088          // B*N
#define Lseq 3136           // f*N
#define NBGRP 8
#define SCALE_Q 0.125f
#define EPS_V   1e-6f
#define KVP  7              // kv sequence partitions

#define N4X  (Mtok * (Cdim / 4))
#define N4WQ (3072 * Cdim / 4)
#define N4WP (Cdim * Cdim / 4)

// Scratch (static device memory)
__device__ float g_kv  [NBGRP * Hn * En * En];
__device__ float g_ksum[NBGRP * Hn * En];
__device__ float g_kvp [KVP][NBGRP * Hn * En * En];
__device__ float g_ksp [KVP][NBGRP * Hn * En];
// fp16 tensors
__device__ __half g_xh[(size_t)Mtok * Cdim];
__device__ __half g_qh[(size_t)Mtok * Cdim];
__device__ __half g_kh[(size_t)Mtok * Cdim];
__device__ __half g_vh[(size_t)Mtok * Cdim];
__device__ __half g_ah[(size_t)Mtok * Cdim];
__device__ __half g_wqh[3072 * Cdim];
__device__ __half g_wph[Cdim * Cdim];

// ---------------------------------------------------------------------------
// Helpers
// ---------------------------------------------------------------------------
__device__ __forceinline__ uint32_t smem_u32(const void* p) {
    uint32_t a;
    asm("{ .reg .u64 t; cvta.to.shared.u64 t, %1; cvt.u32.u64 %0, t; }" : "=r"(a) : "l"(p));
    return a;
}

__device__ __forceinline__ void mma16816(float* d, const uint32_t* a,
                                         uint32_t b0, uint32_t b1) {
    asm volatile(
        "mma.sync.aligned.m16n8k16.row.col.f32.f16.f16.f32 "
        "{%0,%1,%2,%3}, {%4,%5,%6,%7}, {%8,%9}, {%0,%1,%2,%3};"
        : "+f"(d[0]), "+f"(d[1]), "+f"(d[2]), "+f"(d[3])
        : "r"(a[0]), "r"(a[1]), "r"(a[2]), "r"(a[3]), "r"(b0), "r"(b1));
}

__device__ __forceinline__ void ldsm4(uint32_t addr, uint32_t* r) {
    asm volatile("ldmatrix.sync.aligned.m8n8.x4.shared.b16 {%0,%1,%2,%3}, [%4];"
                 : "=r"(r[0]), "=r"(r[1]), "=r"(r[2]), "=r"(r[3]) : "r"(addr));
}

#define FMA2(acc, a, b) \
    asm("fma.rn.f32x2 %0, %1, %2, %0;" : "+l"(acc) : "l"(a), "l"(b))

__device__ __forceinline__ float ull_lo(unsigned long long v) {
    return __uint_as_float((unsigned)(v & 0xffffffffull));
}
__device__ __forceinline__ float ull_hi(unsigned long long v) {
    return __uint_as_float((unsigned)(v >> 32));
}

#define CP16(dst, src) \
    asm volatile("cp.async.cg.shared.global [%0], [%1], 16;" :: "r"(dst), "l"(src))
#define CP_COMMIT() asm volatile("cp.async.commit_group;" ::: "memory")
#define CP_WAIT1()  asm volatile("cp.async.wait_group 1;" ::: "memory")

// Swizzled byte offset for 128-byte rows: row in [0,128), quad in [0,8)
__device__ __forceinline__ uint32_t swz(uint32_t row, uint32_t quad) {
    return (row << 7) + ((quad ^ (row & 7)) << 4);
}

// sigma row remap for transposed f32x2 tiles: d -> (d%4)*16 + d/4
__device__ __forceinline__ int sgm(int d) { return (d & 3) * 16 + (d >> 2); }

// ---------------------------------------------------------------------------
// Fused fp32 -> fp16 conversion (x, w_qkv, w_proj in one launch)
// ---------------------------------------------------------------------------
__global__ __launch_bounds__(256)
void conv_all(const float4* __restrict__ x, const float4* __restrict__ wq,
              const float4* __restrict__ wp)
{
    int i = blockIdx.x * 256 + threadIdx.x;
    const float4* src; __half* dst; int j;
    if (i < N4X)                { src = x;  dst = g_xh;  j = i; }
    else if (i < N4X + N4WQ)    { src = wq; dst = g_wqh; j = i - N4X; }
    else if (i < N4X + N4WQ + N4WP) { src = wp; dst = g_wph; j = i - N4X - N4WQ; }
    else return;
    float4 v = src[j];
    __half2 h01 = __floats2half2_rn(v.x, v.y);
    __half2 h23 = __floats2half2_rn(v.z, v.w);
    *(uint2*)&dst[(size_t)j * 4] = make_uint2(*(uint32_t*)&h01, *(uint32_t*)&h23);
}

// ---------------------------------------------------------------------------
// FP16 tensor-core NT GEMM (unchanged from R10 — 70% tensor, protect it)
// ---------------------------------------------------------------------------
#define ARR_SZ 16384
#define STG_B (2 * ARR_SZ)
#define NSTG 3
#define GEMM_SMEM (NSTG * STG_B)

template<int MODE>
__global__ __launch_bounds__(128, 2)
void gemm_tc(const __half* __restrict__ A_g,
             const __half* __restrict__ W_g,
             const float* __restrict__ bias, float* __restrict__ out)
{
    extern __shared__ __align__(128) char smem[];
    const uint32_t sbase = smem_u32(smem);
    const int tid  = threadIdx.x;
    const int lane = tid & 31;
    const int w    = tid >> 5;
    const int wm   = w & 1;
    const int wn   = w >> 1;
    const int m0 = blockIdx.y * 128;
    const int n0 = blockIdx.x * 128;

    const int a_row = (lane & 7) + ((lane >> 3) & 1) * 8;
    const int a_kq  = (lane >> 4) & 1;
    const int b_row = (lane & 7) + (lane >> 4) * 8;
    const int b_kq  = (lane >> 3) & 1;

    auto issue = [&](int c) {
        const uint32_t st = sbase + (c % NSTG) * STG_B;
        const int k0 = c * 64;
        #pragma unroll
        for (int p = 0; p < 8; p++) {
            int id = tid + p * 128;
            int row = id >> 3, quad = id & 7;
            uint32_t so = swz(row, quad);
            CP16(st + so, A_g + (size_t)(m0 + row) * Cdim + k0 + quad * 8);
            CP16(st + ARR_SZ + so, W_g + (size_t)(n0 + row) * Cdim + k0 + quad * 8);
        }
    };

    float acc[4][8][4];
    #pragma unroll
    for (int mt = 0; mt < 4; mt++)
        #pragma unroll
        for (int nt = 0; nt < 8; nt++)
            #pragma unroll
            for (int r = 0; r < 4; r++) acc[mt][nt][r] = 0.0f;

    issue(0); CP_COMMIT();
    issue(1); CP_COMMIT();

    for (int c = 0; c < 16; c++) {
        CP_WAIT1();
        __syncthreads();
        if (c + 2 < 16) { issue(c + 2); CP_COMMIT(); }

        const uint32_t st = sbase + (c % NSTG) * STG_B;
        const uint32_t sA = st, sB = st + ARR_SZ;

        uint32_t ah[4][4][4];
        #pragma unroll
        for (int ks = 0; ks < 4; ks++)
            #pragma unroll
            for (int mt = 0; mt < 4; mt++) {
                uint32_t row = wm * 64 + mt * 16 + a_row;
                ldsm4(sA + swz(row, ks * 2 + a_kq), ah[ks][mt]);
            }

        uint32_t bf[2][4];
        {
            uint32_t row = wn * 64 + 0 * 16 + b_row;
            ldsm4(sB + swz(row, 0 * 2 + b_kq), bf[0]);
        }
        #pragma unroll
        for (int it = 0; it < 16; it++) {
            const int ks = it >> 2, bt = it & 3;
            if (it + 1 < 16) {
                const int ks2 = (it + 1) >> 2, bt2 = (it + 1) & 3;
                uint32_t row = wn * 64 + bt2 * 16 + b_row;
                ldsm4(sB + swz(row, ks2 * 2 + b_kq), bf[(it + 1) & 1]);
            }
            const uint32_t* bh = bf[it & 1];
            #pragma unroll
            for (int half = 0; half < 2; half++) {
                const int nt = bt * 2 + half;
                #pragma unroll
                for (int mt = 0; mt < 4; mt++)
                    mma16816(acc[mt][nt], ah[ks][mt], bh[half * 2], bh[half * 2 + 1]);
            }
        }
    }

    const int r4 = lane >> 2, c4 = lane & 3;
    if (MODE == 0) {
        const int sN = n0 >> 10;                 // 0:q 1:k 2:v
        __half* dst = (sN == 0) ? g_qh : (sN == 1) ? g_kh : g_vh;
        const int colb = (n0 & 1023) + wn * 64;
        #pragma unroll
        for (int mt = 0; mt < 4; mt++) {
            #pragma unroll
            for (int nt = 0; nt < 8; nt++) {
                float v0 = acc[mt][nt][0], v1 = acc[mt][nt][1];
                float v2 = acc[mt][nt][2], v3 = acc[mt][nt][3];
                if (sN < 2) {
                    v0 = fmaxf(v0, 0.0f) + SCALE_Q;
                    v1 = fmaxf(v1, 0.0f) + SCALE_Q;
                    v2 = fmaxf(v2, 0.0f) + SCALE_Q;
                    v3 = fmaxf(v3, 0.0f) + SCALE_Q;
                }
                int m = m0 + wm * 64 + mt * 16 + r4;
                int col = colb + nt * 8 + c4 * 2;
                __half2 h01 = __floats2half2_rn(v0, v1);
                __half2 h23 = __floats2half2_rn(v2, v3);
                *(uint32_t*)(dst + (size_t)m * Cdim + col)       = *(uint32_t*)&h01;
                *(uint32_t*)(dst + (size_t)(m + 8) * Cdim + col) = *(uint32_t*)&h23;
            }
        }
    } else {
        #pragma unroll
        for (int mt = 0; mt < 4; mt++) {
            #pragma unroll
            for (int nt = 0; nt < 8; nt++) {
                int m = m0 + wm * 64 + mt * 16 + r4;
                int col = n0 + wn * 64 + nt * 8 + c4 * 2;
                float b0 = __ldg(bias + col), b1 = __ldg(bias + col + 1);
                *(float2*)(out + (size_t)m * Cdim + col) =
                    make_float2(acc[mt][nt][0] + b0, acc[mt][nt][1] + b1);
                *(float2*)(out + (size_t)(m + 8) * Cdim + col) =
                    make_float2(acc[mt][nt][2] + b0, acc[mt][nt][3] + b1);
            }
        }
    }
}

// ---------------------------------------------------------------------------
// Partial kv + partial k_sum (unchanged from R10)
// ---------------------------------------------------------------------------
__global__ __launch_bounds__(256)
void kvp_kernel()
{
    __shared__ __align__(16) float skT[64][66];
    __shared__ __align__(16) float svT[64][66];
    __shared__ float red[4][64];
    const int bh = blockIdx.x;
    const int prt = blockIdx.y;
    const int bb = bh >> 4, h = bh & 15;
    const int tid = threadIdx.x;
    const int tx = tid & 15, ty = tid >> 4;
    const int e_id = tid & 63, part = tid >> 6;
    unsigned long long acc2[4][4] = {};
    float ks_part = 0.0f;
    const size_t base = (size_t)bb * Lseq * Cdim + h * En;
    const int se = sgm(e_id);

    for (int it = 0; it < 7; it++) {
        const int n0 = (prt * 7 + it) * 64;
        __syncthreads();
        #pragma unroll
        for (int i = 0; i < 2; i++) {
            int lin = tid + i * 256;
            int row = lin >> 3;
            int c8  = (lin & 7) * 8;
            size_t g = base + (size_t)(n0 + row) * Cdim + c8;
            uint4 uk = *(const uint4*)(g_kh + g);
            uint4 uv = *(const uint4*)(g_vh + g);
            __half2* hk = (__half2*)&uk;
            __half2* hv = (__half2*)&uv;
            #pragma unroll
            for (int j = 0; j < 4; j++) {
                float2 fk = __half22float2(hk[j]);
                float2 fv = __half22float2(hv[j]);
                skT[sgm(c8 + j * 2)][row]     = fk.x;
                skT[sgm(c8 + j * 2 + 1)][row] = fk.y;
                svT[sgm(c8 + j * 2)][row]     = fv.x;
                svT[sgm(c8 + j * 2 + 1)][row] = fv.y;
            }
        }
        __syncthreads();
        #pragma unroll 2
        for (int n = 0; n < 64; n += 2) {
            unsigned long long a2[4], b2[4];
            #pragma unroll
            for (int i = 0; i < 4; i++)
                a2[i] = *(const unsigned long long*)&skT[i * 16 + ty][n];
            #pragma unroll
            for (int j = 0; j < 4; j++)
                b2[j] = *(const unsigned long long*)&svT[j * 16 + tx][n];
            #pragma unroll
            for (int i = 0; i < 4; i++)
                #pragma unroll
                for (int j = 0; j < 4; j++)
                    FMA2(acc2[i][j], a2[i], b2[j]);
        }
        #pragma unroll
        for (int n = 0; n < 16; n++)
            ks_part += skT[se][part * 16 + n];
    }
    float* dst = g_kvp[prt] + bh * (En * En);
    #pragma unroll
    for (int i = 0; i < 4; i++) {
        float4 v;
        v.x = ull_lo(acc2[i][0]) + ull_hi(acc2[i][0]);
        v.y = ull_lo(acc2[i][1]) + ull_hi(acc2[i][1]);
        v.z = ull_lo(acc2[i][2]) + ull_hi(acc2[i][2]);
        v.w = ull_lo(acc2[i][3]) + ull_hi(acc2[i][3]);
        *(float4*)&dst[(ty * 4 + i) * En + tx * 4] = v;
    }

    __syncthreads();
    red[part][e_id] = ks_part;
    __syncthreads();
    if (part == 0)
        g_ksp[prt][bh * En + e_id] =
            red[0][e_id] + red[1][e_id] + red[2][e_id] + red[3][e_id];
}

// ---------------------------------------------------------------------------
// Wide reduce of partial kv/ksum. 512 blocks x 256 thr, one float4/thread.
// Blocks 0..7 additionally reduce ksum (2048 float4 = 8192 floats).
// ---------------------------------------------------------------------------
__global__ __launch_bounds__(256)
void kvred_kernel()
{
    const int gid = blockIdx.x * 256 + threadIdx.x;   // 0 .. 131071
    {
        int idx = gid * 4;                            // covers 524288 floats
        float4 s = *(const float4*)&g_kvp[0][idx];
        #pragma unroll
        for (int p = 1; p < KVP; p++) {
            float4 t = *(const float4*)&g_kvp[p][idx];
            s.x += t.x; s.y += t.y; s.z += t.z; s.w += t.w;
        }
        *(float4*)&g_kv[idx] = s;
    }
    if (gid < 2048) {
        int idx = gid * 4;                            // covers 8192 floats
        float4 s = *(const float4*)&g_ksp[0][idx];
        #pragma unroll
        for (int p = 1; p < KVP; p++) {
            float4 t = *(const float4*)&g_ksp[p][idx];
            s.x += t.x; s.y += t.y; s.z += t.z; s.w += t.w;
        }
        *(float4*)&g_ksum[idx] = s;
    }
}

// ---------------------------------------------------------------------------
// out = (q_ @ kv) * z -> fp16. kv loaded+transposed ONCE per block, then two
// 64-token tiles processed (halves kv L2 re-reads). z-dot parallelized over
// all 256 threads (4 partials of 16 e).
// ---------------------------------------------------------------------------
__global__ __launch_bounds__(256)
void attn_kernel()
{
    __shared__ __align__(16) float sq [64][68];
    __shared__ __align__(16) float skvt[64][66];
    __shared__ float sks[64];
    __shared__ float szp[4][64];
    __shared__ float sz [64];
    const int bh = blockIdx.y;
    const int bb = bh >> 4, h = bh & 15;
    const int tid = threadIdx.x;
    const int tx = tid & 15, ty = tid >> 4;
    const int e_id = tid & 63, part = tid >> 6;

    #pragma unroll
    for (int it = 0; it < 4; it++) {
        int lin = tid + it * 256;
        int e   = lin >> 4;
        int c4  = (lin & 15) * 4;
        float4 v = *(const float4*)&g_kv[bh * (En * En) + e * En + c4];
        skvt[sgm(c4 + 0)][e] = v.x;
        skvt[sgm(c4 + 1)][e] = v.y;
        skvt[sgm(c4 + 2)][e] = v.z;
        skvt[sgm(c4 + 3)][e] = v.w;
    }
    if (tid < 16)
        *(float4*)&sks[tid * 4] = *(const float4*)&g_ksum[bh * En + tid * 4];

    for (int t = 0; t < 2; t++) {
        const int tile = blockIdx.x * 2 + t;
        if (tile >= 49) break;
        const int n0 = tile * 64;

        __syncthreads();
        #pragma unroll
        for (int i = 0; i < 2; i++) {
            int lin = tid + i * 256;
            int row = lin >> 3;
            int c8  = (lin & 7) * 8;
            size_t g = ((size_t)bb * Lseq + n0 + row) * Cdim + h * En + c8;
            uint4 uq = *(const uint4*)(g_qh + g);
            __half2* hq = (__half2*)&uq;
            #pragma unroll
            for (int j = 0; j < 4; j++)
                *(float2*)&sq[row][c8 + j * 2] = __half22float2(hq[j]);
        }
        __syncthreads();

        // z-dot: thread (part, e_id->token) partial over e in [part*16, +16)
        {
            float d = 0.0f;
            #pragma unroll
            for (int e = 0; e < 16; e++)
                d += sq[e_id][part * 16 + e] * sks[part * 16 + e];
            szp[part][e_id] = d;
        }
        __syncthreads();
        if (tid < 64)
            sz[tid] = 1.0f / (szp[0][tid] + szp[1][tid] + szp[2][tid] + szp[3][tid] + EPS_V);
        __syncthreads();

        unsigned long long acc2[4][4] = {};
        #pragma unroll 2
        for (int e = 0; e < 64; e += 2) {
            unsigned long long a2[4], b2[4];
            #pragma unroll
            for (int i = 0; i < 4; i++)
                a2[i] = *(const unsigned long long*)&sq[ty * 4 + i][e];
            #pragma unroll
            for (int j = 0; j < 4; j++)
                b2[j] = *(const unsigned long long*)&skvt[j * 16 + tx][e];
            #pragma unroll
            for (int i = 0; i < 4; i++)
                #pragma unroll
                for (int j = 0; j < 4; j++)
                    FMA2(acc2[i][j], a2[i], b2[j]);
        }

        #pragma unroll
        for (int i = 0; i < 4; i++) {
            float z = sz[ty * 4 + i];
            float v0 = (ull_lo(acc2[i][0]) + ull_hi(acc2[i][0])) * z;
            float v1 = (ull_lo(acc2[i][1]) + ull_hi(acc2[i][1])) * z;
            float v2 = (ull_lo(acc2[i][2]) + ull_hi(acc2[i][2])) * z;
            float v3 = (ull_lo(acc2[i][3]) + ull_hi(acc2[i][3])) * z;
            __half2 h01 = __floats2half2_rn(v0, v1);
            __half2 h23 = __floats2half2_rn(v2, v3);
            size_t g = ((size_t)bb * Lseq + n0 + ty * 4 + i) * Cdim + h * En + tx * 4;
            *(uint2*)&g_ah[g] = make_uint2(*(uint32_t*)&h01, *(uint32_t*)&h23);
        }
    }
}

// ---------------------------------------------------------------------------
extern "C" void kernel_launch(void* const* d_in, const int* in_sizes, int n_in,
                              void* d_out, int out_size)
{
    const float* x      = (const float*)d_in[0];
    const float* w_qkv  = (const float*)d_in[1];
    const float* w_proj = (const float*)d_in[2];
    const float* b_proj = (const float*)d_in[3];
    float* out = (float*)d_out;

    cudaFuncSetAttribute(gemm_tc<0>, cudaFuncAttributeMaxDynamicSharedMemorySize, GEMM_SMEM);
    cudaFuncSetAttribute(gemm_tc<1>, cudaFuncAttributeMaxDynamicSharedMemorySize, GEMM_SMEM);

    __half *xh, *ah, *wqh, *wph;
    cudaGetSymbolAddress((void**)&xh,  g_xh);
    cudaGetSymbolAddress((void**)&ah,  g_ah);
    cudaGetSymbolAddress((void**)&wqh, g_wqh);
    cudaGetSymbolAddress((void**)&wph, g_wph);

    // 0) fused fp32 -> fp16 conversions (one launch)
    {
        int total = N4X + N4WQ + N4WP;
        conv_all<<<(total + 255) / 256, 256>>>(
            (const float4*)x, (const float4*)w_qkv, (const float4*)w_proj);
    }

    // 1) qkv = x @ w_qkv^T (fp16 tensor cores), fused q/k/v split + relu+scale
    gemm_tc<0><<<dim3(24, 196), 128, GEMM_SMEM>>>(xh, wqh, nullptr, nullptr);
    // 2) partial kv (+ partial k_sum), then wide reduce
    kvp_kernel<<<dim3(128, KVP), 256>>>();
    kvred_kernel<<<512, 256>>>();
    // 3) out = (q_ @ kv) * z  -> fp16 (2 tiles per block)
    attn_kernel<<<dim3(25, 128), 256>>>();
    // 4) final = attn @ w_proj^T + b_proj
    gemm_tc<1><<<dim3(8, 196), 128, GEMM_SMEM>>>(ah, wph, b_proj, out);
}

// round 13
// speedup vs baseline: 7.8889x; 1.1260x over previous
#include <cuda_runtime.h>
#include <cuda_fp16.h>
#include <cstdint>

// Problem constants
#define Cdim 1024
#define Hn   16
#define En   64
#define Mtok 25088          // B*N
#define Lseq 3136           // f*N
#define NBGRP 8
#define SCALE_Q 0.125f
#define EPS_V   1e-6f
#define KVP  7              // kv sequence partitions

#define N4X  (Mtok * (Cdim / 4))
#define N4WQ (3072 * Cdim / 4)
#define N4WP (Cdim * Cdim / 4)

// Scratch (static device memory)
__device__ float g_kv  [NBGRP * Hn * En * En];
__device__ float g_ksum[NBGRP * Hn * En];
__device__ float g_kvp [KVP][NBGRP * Hn * En * En];
__device__ float g_ksp [KVP][NBGRP * Hn * En];
// fp16 tensors
__device__ __half g_xh[(size_t)Mtok * Cdim];
__device__ __half g_qh[(size_t)Mtok * Cdim];
__device__ __half g_kh[(size_t)Mtok * Cdim];
__device__ __half g_vh[(size_t)Mtok * Cdim];
__device__ __half g_ah[(size_t)Mtok * Cdim];
__device__ __half g_wqh[3072 * Cdim];
__device__ __half g_wph[Cdim * Cdim];

// ---------------------------------------------------------------------------
// Helpers
// ---------------------------------------------------------------------------
__device__ __forceinline__ uint32_t smem_u32(const void* p) {
    uint32_t a;
    asm("{ .reg .u64 t; cvta.to.shared.u64 t, %1; cvt.u32.u64 %0, t; }" : "=r"(a) : "l"(p));
    return a;
}

__device__ __forceinline__ void mma16816(float* d, const uint32_t* a,
                                         uint32_t b0, uint32_t b1) {
    asm volatile(
        "mma.sync.aligned.m16n8k16.row.col.f32.f16.f16.f32 "
        "{%0,%1,%2,%3}, {%4,%5,%6,%7}, {%8,%9}, {%0,%1,%2,%3};"
        : "+f"(d[0]), "+f"(d[1]), "+f"(d[2]), "+f"(d[3])
        : "r"(a[0]), "r"(a[1]), "r"(a[2]), "r"(a[3]), "r"(b0), "r"(b1));
}

__device__ __forceinline__ void ldsm4(uint32_t addr, uint32_t* r) {
    asm volatile("ldmatrix.sync.aligned.m8n8.x4.shared.b16 {%0,%1,%2,%3}, [%4];"
                 : "=r"(r[0]), "=r"(r[1]), "=r"(r[2]), "=r"(r[3]) : "r"(addr));
}

#define CP16(dst, src) \
    asm volatile("cp.async.cg.shared.global [%0], [%1], 16;" :: "r"(dst), "l"(src))
#define CP_COMMIT() asm volatile("cp.async.commit_group;" ::: "memory")
#define CP_WAIT1()  asm volatile("cp.async.wait_group 1;" ::: "memory")

// Swizzled byte offset for 128-byte rows: quad (16B) XOR row&7
__device__ __forceinline__ uint32_t swz(uint32_t row, uint32_t quad) {
    return (row << 7) + ((quad ^ (row & 7)) << 4);
}

// ---------------------------------------------------------------------------
// Fused fp32 -> fp16 conversion (x, w_qkv, w_proj in one launch)
// ---------------------------------------------------------------------------
__global__ __launch_bounds__(256)
void conv_all(const float4* __restrict__ x, const float4* __restrict__ wq,
              const float4* __restrict__ wp)
{
    int i = blockIdx.x * 256 + threadIdx.x;
    const float4* src; __half* dst; int j;
    if (i < N4X)                { src = x;  dst = g_xh;  j = i; }
    else if (i < N4X + N4WQ)    { src = wq; dst = g_wqh; j = i - N4X; }
    else if (i < N4X + N4WQ + N4WP) { src = wp; dst = g_wph; j = i - N4X - N4WQ; }
    else return;
    float4 v = src[j];
    __half2 h01 = __floats2half2_rn(v.x, v.y);
    __half2 h23 = __floats2half2_rn(v.z, v.w);
    *(uint2*)&dst[(size_t)j * 4] = make_uint2(*(uint32_t*)&h01, *(uint32_t*)&h23);
}

// ---------------------------------------------------------------------------
// FP16 tensor-core NT GEMM (unchanged — proven)
// ---------------------------------------------------------------------------
#define ARR_SZ 16384
#define STG_B (2 * ARR_SZ)
#define NSTG 3
#define GEMM_SMEM (NSTG * STG_B)

template<int MODE>
__global__ __launch_bounds__(128, 2)
void gemm_tc(const __half* __restrict__ A_g,
             const __half* __restrict__ W_g,
             const float* __restrict__ bias, float* __restrict__ out)
{
    extern __shared__ __align__(128) char smem[];
    const uint32_t sbase = smem_u32(smem);
    const int tid  = threadIdx.x;
    const int lane = tid & 31;
    const int w    = tid >> 5;
    const int wm   = w & 1;
    const int wn   = w >> 1;
    const int m0 = blockIdx.y * 128;
    const int n0 = blockIdx.x * 128;

    const int a_row = (lane & 7) + ((lane >> 3) & 1) * 8;
    const int a_kq  = (lane >> 4) & 1;
    const int b_row = (lane & 7) + (lane >> 4) * 8;
    const int b_kq  = (lane >> 3) & 1;

    auto issue = [&](int c) {
        const uint32_t st = sbase + (c % NSTG) * STG_B;
        const int k0 = c * 64;
        #pragma unroll
        for (int p = 0; p < 8; p++) {
            int id = tid + p * 128;
            int row = id >> 3, quad = id & 7;
            uint32_t so = swz(row, quad);
            CP16(st + so, A_g + (size_t)(m0 + row) * Cdim + k0 + quad * 8);
            CP16(st + ARR_SZ + so, W_g + (size_t)(n0 + row) * Cdim + k0 + quad * 8);
        }
    };

    float acc[4][8][4];
    #pragma unroll
    for (int mt = 0; mt < 4; mt++)
        #pragma unroll
        for (int nt = 0; nt < 8; nt++)
            #pragma unroll
            for (int r = 0; r < 4; r++) acc[mt][nt][r] = 0.0f;

    issue(0); CP_COMMIT();
    issue(1); CP_COMMIT();

    for (int c = 0; c < 16; c++) {
        CP_WAIT1();
        __syncthreads();
        if (c + 2 < 16) { issue(c + 2); CP_COMMIT(); }

        const uint32_t st = sbase + (c % NSTG) * STG_B;
        const uint32_t sA = st, sB = st + ARR_SZ;

        uint32_t ah[4][4][4];
        #pragma unroll
        for (int ks = 0; ks < 4; ks++)
            #pragma unroll
            for (int mt = 0; mt < 4; mt++) {
                uint32_t row = wm * 64 + mt * 16 + a_row;
                ldsm4(sA + swz(row, ks * 2 + a_kq), ah[ks][mt]);
            }

        uint32_t bf[2][4];
        {
            uint32_t row = wn * 64 + 0 * 16 + b_row;
            ldsm4(sB + swz(row, 0 * 2 + b_kq), bf[0]);
        }
        #pragma unroll
        for (int it = 0; it < 16; it++) {
            const int ks = it >> 2, bt = it & 3;
            if (it + 1 < 16) {
                const int ks2 = (it + 1) >> 2, bt2 = (it + 1) & 3;
                uint32_t row = wn * 64 + bt2 * 16 + b_row;
                ldsm4(sB + swz(row, ks2 * 2 + b_kq), bf[(it + 1) & 1]);
            }
            const uint32_t* bh = bf[it & 1];
            #pragma unroll
            for (int half = 0; half < 2; half++) {
                const int nt = bt * 2 + half;
                #pragma unroll
                for (int mt = 0; mt < 4; mt++)
                    mma16816(acc[mt][nt], ah[ks][mt], bh[half * 2], bh[half * 2 + 1]);
            }
        }
    }

    const int r4 = lane >> 2, c4 = lane & 3;
    if (MODE == 0) {
        const int sN = n0 >> 10;                 // 0:q 1:k 2:v
        __half* dst = (sN == 0) ? g_qh : (sN == 1) ? g_kh : g_vh;
        const int colb = (n0 & 1023) + wn * 64;
        #pragma unroll
        for (int mt = 0; mt < 4; mt++) {
            #pragma unroll
            for (int nt = 0; nt < 8; nt++) {
                float v0 = acc[mt][nt][0], v1 = acc[mt][nt][1];
                float v2 = acc[mt][nt][2], v3 = acc[mt][nt][3];
                if (sN < 2) {
                    v0 = fmaxf(v0, 0.0f) + SCALE_Q;
                    v1 = fmaxf(v1, 0.0f) + SCALE_Q;
                    v2 = fmaxf(v2, 0.0f) + SCALE_Q;
                    v3 = fmaxf(v3, 0.0f) + SCALE_Q;
                }
                int m = m0 + wm * 64 + mt * 16 + r4;
                int col = colb + nt * 8 + c4 * 2;
                __half2 h01 = __floats2half2_rn(v0, v1);
                __half2 h23 = __floats2half2_rn(v2, v3);
                *(uint32_t*)(dst + (size_t)m * Cdim + col)       = *(uint32_t*)&h01;
                *(uint32_t*)(dst + (size_t)(m + 8) * Cdim + col) = *(uint32_t*)&h23;
            }
        }
    } else {
        #pragma unroll
        for (int mt = 0; mt < 4; mt++) {
            #pragma unroll
            for (int nt = 0; nt < 8; nt++) {
                int m = m0 + wm * 64 + mt * 16 + r4;
                int col = n0 + wn * 64 + nt * 8 + c4 * 2;
                float b0 = __ldg(bias + col), b1 = __ldg(bias + col + 1);
                *(float2*)(out + (size_t)m * Cdim + col) =
                    make_float2(acc[mt][nt][0] + b0, acc[mt][nt][1] + b1);
                *(float2*)(out + (size_t)(m + 8) * Cdim + col) =
                    make_float2(acc[mt][nt][2] + b0, acc[mt][nt][3] + b1);
            }
        }
    }
}

// ---------------------------------------------------------------------------
// Tensor-core partial kv: kv[e][d] = sum_seq k[seq][e] * v[seq][d].
// Tiles STS-transposed to [e][seq] / [d][seq] fp16 (row stride 72 halves,
// 144B = 16B-aligned rows), then the PROVEN non-trans ldmatrix GEMM pattern
// (M=64 e, N=64 d, K=64 seq). Fused partial k_sum. Plain loads (no cp.async);
// latency hidden by high block co-residency.
// grid (128 bh, KVP), 128 threads.
// ---------------------------------------------------------------------------
#define TROW 72

__global__ __launch_bounds__(128)
void kvp_tc()
{
    __shared__ __half skT[64][TROW];   // [e][seq]
    __shared__ __half svT[64][TROW];   // [d][seq]
    __shared__ float red[2][64];
    const int bh = blockIdx.x;
    const int prt = blockIdx.y;
    const int bb = bh >> 4, h = bh & 15;
    const int tid = threadIdx.x;
    const int lane = tid & 31;
    const int w = tid >> 5;
    const size_t base = (size_t)bb * Lseq * Cdim + h * En;
    const uint32_t skb = smem_u32(&skT[0][0]);
    const uint32_t svb = smem_u32(&svT[0][0]);

    // proven GEMM lane patterns (row in elements, col-octet in k)
    const int a_row = (lane & 7) + ((lane >> 3) & 1) * 8;
    const int a_kq  = (lane >> 4) & 1;
    const int b_row = (lane & 7) + (lane >> 4) * 8;
    const int b_kq  = (lane >> 3) & 1;

    float acc[8][4] = {};
    float ks0 = 0.0f;
    const int e_id = tid & 63, zp = tid >> 6;    // ksum: 2 parts of 32 seq

    for (int t = 0; t < 7; t++) {
        const int n0 = (prt * 7 + t) * 64;
        __syncthreads();
        #pragma unroll
        for (int p = 0; p < 4; p++) {
            int id = tid + p * 128;          // 512 = 64 seq x 8 octets
            int seq = id & 63, oct = id >> 6;
            size_t g = base + (size_t)(n0 + seq) * Cdim + oct * 8;
            uint4 uk = *(const uint4*)(g_kh + g);
            uint4 uv = *(const uint4*)(g_vh + g);
            const __half* hk = (const __half*)&uk;
            const __half* hv = (const __half*)&uv;
            #pragma unroll
            for (int j = 0; j < 8; j++) {
                skT[oct * 8 + j][seq] = hk[j];
                svT[oct * 8 + j][seq] = hv[j];
            }
        }
        __syncthreads();

        #pragma unroll
        for (int ks = 0; ks < 4; ks++) {     // seq chunks of 16
            uint32_t ah[4];
            ldsm4(skb + (w * 16 + a_row) * (TROW * 2) + ks * 32 + a_kq * 16, ah);
            #pragma unroll
            for (int bt = 0; bt < 4; bt++) {
                uint32_t bh4[4];
                ldsm4(svb + (bt * 16 + b_row) * (TROW * 2) + ks * 32 + b_kq * 16, bh4);
                mma16816(acc[bt * 2],     ah, bh4[0], bh4[1]);
                mma16816(acc[bt * 2 + 1], ah, bh4[2], bh4[3]);
            }
        }
        // partial k_sum over seq of skT[e_id][*]
        #pragma unroll
        for (int s = 0; s < 32; s++)
            ks0 += __half2float(skT[e_id][zp * 32 + s]);
    }

    const int r4 = lane >> 2, c4 = lane & 3;
    float* dst = g_kvp[prt] + bh * (En * En);
    #pragma unroll
    for (int nt = 0; nt < 8; nt++) {
        int e = w * 16 + r4;
        int d = nt * 8 + c4 * 2;
        *(float2*)&dst[e * En + d]       = make_float2(acc[nt][0], acc[nt][1]);
        *(float2*)&dst[(e + 8) * En + d] = make_float2(acc[nt][2], acc[nt][3]);
    }

    __syncthreads();
    red[zp][e_id] = ks0;
    __syncthreads();
    if (tid < 64)
        g_ksp[prt][bh * En + tid] = red[0][tid] + red[1][tid];
}

// ---------------------------------------------------------------------------
// Wide reduce of partial kv/ksum (unchanged)
// ---------------------------------------------------------------------------
__global__ __launch_bounds__(256)
void kvred_kernel()
{
    const int gid = blockIdx.x * 256 + threadIdx.x;
    {
        int idx = gid * 4;
        float4 s = *(const float4*)&g_kvp[0][idx];
        #pragma unroll
        for (int p = 1; p < KVP; p++) {
            float4 t = *(const float4*)&g_kvp[p][idx];
            s.x += t.x; s.y += t.y; s.z += t.z; s.w += t.w;
        }
        *(float4*)&g_kv[idx] = s;
    }
    if (gid < 2048) {
        int idx = gid * 4;
        float4 s = *(const float4*)&g_ksp[0][idx];
        #pragma unroll
        for (int p = 1; p < KVP; p++) {
            float4 t = *(const float4*)&g_ksp[p][idx];
            s.x += t.x; s.y += t.y; s.z += t.z; s.w += t.w;
        }
        *(float4*)&g_ksum[idx] = s;
    }
}

// ---------------------------------------------------------------------------
// Tensor-core attn: out = (q_ @ kv) * z -> fp16.
// A = q [token][e] (layout matches, direct uint4 STS); B = kv transposed to
// [d][e] fp16 once per block (2 token tiles share it). Proven non-trans
// ldmatrix patterns. grid (25, 128), 128 threads.
// ---------------------------------------------------------------------------
__global__ __launch_bounds__(128)
void attn_tc()
{
    __shared__ __half sq  [64][TROW];   // [token][e]
    __shared__ __half skvT[64][TROW];   // [d][e]
    __shared__ float sks[64];
    __shared__ float szp[2][64];
    __shared__ float sz[64];
    const int bh = blockIdx.y;
    const int bb = bh >> 4, h = bh & 15;
    const int tid = threadIdx.x;
    const int lane = tid & 31;
    const int w = tid >> 5;
    const uint32_t sqb = smem_u32(&sq[0][0]);
    const uint32_t skb = smem_u32(&skvT[0][0]);

    const int a_row = (lane & 7) + ((lane >> 3) & 1) * 8;
    const int a_kq  = (lane >> 4) & 1;
    const int b_row = (lane & 7) + (lane >> 4) * 8;
    const int b_kq  = (lane >> 3) & 1;

    // kv fp32 [e][d] -> fp16 transposed [d][e]
    #pragma unroll
    for (int p = 0; p < 8; p++) {
        int id = tid + p * 128;          // 1024 float4 = 64 e x 16
        int e = id >> 4;
        int d0 = (id & 15) * 4;
        float4 v = *(const float4*)&g_kv[bh * (En * En) + e * En + d0];
        skvT[d0 + 0][e] = __float2half_rn(v.x);
        skvT[d0 + 1][e] = __float2half_rn(v.y);
        skvT[d0 + 2][e] = __float2half_rn(v.z);
        skvT[d0 + 3][e] = __float2half_rn(v.w);
    }
    if (tid < 16)
        *(float4*)&sks[tid * 4] = *(const float4*)&g_ksum[bh * En + tid * 4];

    const int tok_z = tid & 63, zp = tid >> 6;

    for (int t = 0; t < 2; t++) {
        const int tile = blockIdx.x * 2 + t;
        if (tile >= 49) break;
        const int n0 = tile * 64;

        __syncthreads();
        #pragma unroll
        for (int p = 0; p < 4; p++) {
            int id = tid + p * 128;      // 512 = 64 tok x 8 octets
            int tok = id >> 3, oct = id & 7;
            size_t g = ((size_t)bb * Lseq + n0 + tok) * Cdim + h * En + oct * 8;
            *(uint4*)&sq[tok][oct * 8] = *(const uint4*)(g_qh + g);
        }
        __syncthreads();

        // z-dot (fp16 q from smem, fp32 sum); 2 parts of 32 e
        {
            float d = 0.0f;
            #pragma unroll
            for (int s = 0; s < 32; s++)
                d += __half2float(sq[tok_z][zp * 32 + s]) * sks[zp * 32 + s];
            szp[zp][tok_z] = d;
        }
        __syncthreads();
        if (tid < 64)
            sz[tid] = 1.0f / (szp[0][tid] + szp[1][tid] + EPS_V);
        __syncthreads();

        float acc[8][4] = {};
        #pragma unroll
        for (int ks = 0; ks < 4; ks++) {     // e chunks of 16
            uint32_t ah[4];
            ldsm4(sqb + (w * 16 + a_row) * (TROW * 2) + ks * 32 + a_kq * 16, ah);
            #pragma unroll
            for (int bt = 0; bt < 4; bt++) {
                uint32_t bh4[4];
                ldsm4(skb + (bt * 16 + b_row) * (TROW * 2) + ks * 32 + b_kq * 16, bh4);
                mma16816(acc[bt * 2],     ah, bh4[0], bh4[1]);
                mma16816(acc[bt * 2 + 1], ah, bh4[2], bh4[3]);
            }
        }

        const int r4 = lane >> 2, c4 = lane & 3;
        #pragma unroll
        for (int nt = 0; nt < 8; nt++) {
            int trow = w * 16 + r4;
            int d = nt * 8 + c4 * 2;
            float z0 = sz[trow], z1 = sz[trow + 8];
            __half2 h01 = __floats2half2_rn(acc[nt][0] * z0, acc[nt][1] * z0);
            __half2 h23 = __floats2half2_rn(acc[nt][2] * z1, acc[nt][3] * z1);
            size_t g0 = ((size_t)bb * Lseq + n0 + trow) * Cdim + h * En + d;
            *(uint32_t*)(g_ah + g0)            = *(uint32_t*)&h01;
            *(uint32_t*)(g_ah + g0 + 8 * Cdim) = *(uint32_t*)&h23;
        }
    }
}

// ---------------------------------------------------------------------------
extern "C" void kernel_launch(void* const* d_in, const int* in_sizes, int n_in,
                              void* d_out, int out_size)
{
    const float* x      = (const float*)d_in[0];
    const float* w_qkv  = (const float*)d_in[1];
    const float* w_proj = (const float*)d_in[2];
    const float* b_proj = (const float*)d_in[3];
    float* out = (float*)d_out;

    cudaFuncSetAttribute(gemm_tc<0>, cudaFuncAttributeMaxDynamicSharedMemorySize, GEMM_SMEM);
    cudaFuncSetAttribute(gemm_tc<1>, cudaFuncAttributeMaxDynamicSharedMemorySize, GEMM_SMEM);

    __half *xh, *ah, *wqh, *wph;
    cudaGetSymbolAddress((void**)&xh,  g_xh);
    cudaGetSymbolAddress((void**)&ah,  g_ah);
    cudaGetSymbolAddress((void**)&wqh, g_wqh);
    cudaGetSymbolAddress((void**)&wph, g_wph);

    // 0) fused fp32 -> fp16 conversions
    {
        int total = N4X + N4WQ + N4WP;
        conv_all<<<(total + 255) / 256, 256>>>(
            (const float4*)x, (const float4*)w_qkv, (const float4*)w_proj);
    }

    // 1) qkv = x @ w_qkv^T, fused q/k/v split + relu+scale
    gemm_tc<0><<<dim3(24, 196), 128, GEMM_SMEM>>>(xh, wqh, nullptr, nullptr);
    // 2) partial kv (+ k_sum) on tensor cores, then wide reduce
    kvp_tc<<<dim3(128, KVP), 128>>>();
    kvred_kernel<<<512, 256>>>();
    // 3) out = (q_ @ kv) * z on tensor cores -> fp16
    attn_tc<<<dim3(25, 128), 128>>>();
    // 4) final = attn @ w_proj^T + b_proj
    gemm_tc<1><<<dim3(8, 196), 128, GEMM_SMEM>>>(ah, wph, b_proj, out);
}

// round 14
// speedup vs baseline: 7.9145x; 1.0032x over previous
#include <cuda_runtime.h>
#include <cuda_fp16.h>
#include <cstdint>

// Problem constants
#define Cdim 1024
#define Hn   16
#define En   64
#define Mtok 25088          // B*N
#define Lseq 3136           // f*N
#define NBGRP 8
#define SCALE_Q 0.125f
#define EPS_V   1e-6f
#define KVP  7              // kv sequence partitions

#define N4X  (Mtok * (Cdim / 4))
#define N4WQ (3072 * Cdim / 4)
#define N4WP (Cdim * Cdim / 4)

// Scratch (static device memory)
__device__ float g_kv  [NBGRP * Hn * En * En];
__device__ float g_ksum[NBGRP * Hn * En];
__device__ float g_kvp [KVP][NBGRP * Hn * En * En];
__device__ float g_ksp [KVP][NBGRP * Hn * En];
// fp16 tensors
__device__ __half g_xh[(size_t)Mtok * Cdim];
__device__ __half g_qh[(size_t)Mtok * Cdim];
__device__ __half g_kh[(size_t)Mtok * Cdim];
__device__ __half g_vh[(size_t)Mtok * Cdim];
__device__ __half g_ah[(size_t)Mtok * Cdim];
__device__ __half g_wqh[3072 * Cdim];
__device__ __half g_wph[Cdim * Cdim];

// ---------------------------------------------------------------------------
// Helpers
// ---------------------------------------------------------------------------
__device__ __forceinline__ uint32_t smem_u32(const void* p) {
    uint32_t a;
    asm("{ .reg .u64 t; cvta.to.shared.u64 t, %1; cvt.u32.u64 %0, t; }" : "=r"(a) : "l"(p));
    return a;
}

__device__ __forceinline__ void mma16816(float* d, const uint32_t* a,
                                         uint32_t b0, uint32_t b1) {
    asm volatile(
        "mma.sync.aligned.m16n8k16.row.col.f32.f16.f16.f32 "
        "{%0,%1,%2,%3}, {%4,%5,%6,%7}, {%8,%9}, {%0,%1,%2,%3};"
        : "+f"(d[0]), "+f"(d[1]), "+f"(d[2]), "+f"(d[3])
        : "r"(a[0]), "r"(a[1]), "r"(a[2]), "r"(a[3]), "r"(b0), "r"(b1));
}

__device__ __forceinline__ void ldsm4(uint32_t addr, uint32_t* r) {
    asm volatile("ldmatrix.sync.aligned.m8n8.x4.shared.b16 {%0,%1,%2,%3}, [%4];"
                 : "=r"(r[0]), "=r"(r[1]), "=r"(r[2]), "=r"(r[3]) : "r"(addr));
}

#define CP16(dst, src) \
    asm volatile("cp.async.cg.shared.global [%0], [%1], 16;" :: "r"(dst), "l"(src))
#define CP_COMMIT() asm volatile("cp.async.commit_group;" ::: "memory")
#define CP_WAIT1()  asm volatile("cp.async.wait_group 1;" ::: "memory")

// Swizzled byte offset for 128-byte rows: quad (16B) XOR row&7
__device__ __forceinline__ uint32_t swz(uint32_t row, uint32_t quad) {
    return (row << 7) + ((quad ^ (row & 7)) << 4);
}

// ---------------------------------------------------------------------------
// Fused fp32 -> fp16 conversion (x, w_qkv, w_proj in one launch)
// ---------------------------------------------------------------------------
__global__ __launch_bounds__(256)
void conv_all(const float4* __restrict__ x, const float4* __restrict__ wq,
              const float4* __restrict__ wp)
{
    int i = blockIdx.x * 256 + threadIdx.x;
    const float4* src; __half* dst; int j;
    if (i < N4X)                { src = x;  dst = g_xh;  j = i; }
    else if (i < N4X + N4WQ)    { src = wq; dst = g_wqh; j = i - N4X; }
    else if (i < N4X + N4WQ + N4WP) { src = wp; dst = g_wph; j = i - N4X - N4WQ; }
    else return;
    float4 v = src[j];
    __half2 h01 = __floats2half2_rn(v.x, v.y);
    __half2 h23 = __floats2half2_rn(v.z, v.w);
    *(uint2*)&dst[(size_t)j * 4] = make_uint2(*(uint32_t*)&h01, *(uint32_t*)&h23);
}

// ---------------------------------------------------------------------------
// FP16 tensor-core NT GEMM. Block 128x128, K-chunk 64, 4 warps (2m x 2n),
// warp tile 64x64. A fragments double-buffered at k-step granularity (4 LDSM
// spread into the B-iteration stream — no chunk-start LDSM burst); B
// fragments double-buffered per iteration. cp.async 3-stage, wait_group 1.
// ---------------------------------------------------------------------------
#define ARR_SZ 16384
#define STG_B (2 * ARR_SZ)
#define NSTG 3
#define GEMM_SMEM (NSTG * STG_B)

template<int MODE>
__global__ __launch_bounds__(128, 2)
void gemm_tc(const __half* __restrict__ A_g,
             const __half* __restrict__ W_g,
             const float* __restrict__ bias, float* __restrict__ out)
{
    extern __shared__ __align__(128) char smem[];
    const uint32_t sbase = smem_u32(smem);
    const int tid  = threadIdx.x;
    const int lane = tid & 31;
    const int w    = tid >> 5;
    const int wm   = w & 1;
    const int wn   = w >> 1;
    const int m0 = blockIdx.y * 128;
    const int n0 = blockIdx.x * 128;

    const int a_row = (lane & 7) + ((lane >> 3) & 1) * 8;
    const int a_kq  = (lane >> 4) & 1;
    const int b_row = (lane & 7) + (lane >> 4) * 8;
    const int b_kq  = (lane >> 3) & 1;

    auto issue = [&](int c) {
        const uint32_t st = sbase + (c % NSTG) * STG_B;
        const int k0 = c * 64;
        #pragma unroll
        for (int p = 0; p < 8; p++) {
            int id = tid + p * 128;
            int row = id >> 3, quad = id & 7;
            uint32_t so = swz(row, quad);
            CP16(st + so, A_g + (size_t)(m0 + row) * Cdim + k0 + quad * 8);
            CP16(st + ARR_SZ + so, W_g + (size_t)(n0 + row) * Cdim + k0 + quad * 8);
        }
    };

    float acc[4][8][4];
    #pragma unroll
    for (int mt = 0; mt < 4; mt++)
        #pragma unroll
        for (int nt = 0; nt < 8; nt++)
            #pragma unroll
            for (int r = 0; r < 4; r++) acc[mt][nt][r] = 0.0f;

    issue(0); CP_COMMIT();
    issue(1); CP_COMMIT();

    for (int c = 0; c < 16; c++) {
        CP_WAIT1();
        __syncthreads();
        if (c + 2 < 16) { issue(c + 2); CP_COMMIT(); }

        const uint32_t st = sbase + (c % NSTG) * STG_B;
        const uint32_t sA = st, sB = st + ARR_SZ;

        // A double-buffer at ks granularity; B double-buffer per iteration
        uint32_t ah[2][4][4];
        #pragma unroll
        for (int mt = 0; mt < 4; mt++) {
            uint32_t row = wm * 64 + mt * 16 + a_row;
            ldsm4(sA + swz(row, 0 * 2 + a_kq), ah[0][mt]);
        }
        uint32_t bf[2][4];
        {
            uint32_t row = wn * 64 + 0 * 16 + b_row;
            ldsm4(sB + swz(row, 0 * 2 + b_kq), bf[0]);
        }
        #pragma unroll
        for (int it = 0; it < 16; it++) {
            const int ks = it >> 2, bt = it & 3;
            // prefetch next B fragment
            if (it + 1 < 16) {
                const int ks2 = (it + 1) >> 2, bt2 = (it + 1) & 3;
                uint32_t row = wn * 64 + bt2 * 16 + b_row;
                ldsm4(sB + swz(row, ks2 * 2 + b_kq), bf[(it + 1) & 1]);
            }
            // prefetch one A fragment of ks+1 per iteration (spread 4 over 4 its)
            if (ks < 3) {
                const int mt = bt;
                uint32_t row = wm * 64 + mt * 16 + a_row;
                ldsm4(sA + swz(row, (ks + 1) * 2 + a_kq), ah[(ks + 1) & 1][mt]);
            }
            const uint32_t* bh = bf[it & 1];
            #pragma unroll
            for (int half = 0; half < 2; half++) {
                const int nt = bt * 2 + half;
                #pragma unroll
                for (int mt = 0; mt < 4; mt++)
                    mma16816(acc[mt][nt], ah[ks & 1][mt], bh[half * 2], bh[half * 2 + 1]);
            }
        }
    }

    const int r4 = lane >> 2, c4 = lane & 3;
    if (MODE == 0) {
        const int sN = n0 >> 10;                 // 0:q 1:k 2:v
        __half* dst = (sN == 0) ? g_qh : (sN == 1) ? g_kh : g_vh;
        const int colb = (n0 & 1023) + wn * 64;
        #pragma unroll
        for (int mt = 0; mt < 4; mt++) {
            #pragma unroll
            for (int nt = 0; nt < 8; nt++) {
                float v0 = acc[mt][nt][0], v1 = acc[mt][nt][1];
                float v2 = acc[mt][nt][2], v3 = acc[mt][nt][3];
                if (sN < 2) {
                    v0 = fmaxf(v0, 0.0f) + SCALE_Q;
                    v1 = fmaxf(v1, 0.0f) + SCALE_Q;
                    v2 = fmaxf(v2, 0.0f) + SCALE_Q;
                    v3 = fmaxf(v3, 0.0f) + SCALE_Q;
                }
                int m = m0 + wm * 64 + mt * 16 + r4;
                int col = colb + nt * 8 + c4 * 2;
                __half2 h01 = __floats2half2_rn(v0, v1);
                __half2 h23 = __floats2half2_rn(v2, v3);
                *(uint32_t*)(dst + (size_t)m * Cdim + col)       = *(uint32_t*)&h01;
                *(uint32_t*)(dst + (size_t)(m + 8) * Cdim + col) = *(uint32_t*)&h23;
            }
        }
    } else {
        #pragma unroll
        for (int mt = 0; mt < 4; mt++) {
            #pragma unroll
            for (int nt = 0; nt < 8; nt++) {
                int m = m0 + wm * 64 + mt * 16 + r4;
                int col = n0 + wn * 64 + nt * 8 + c4 * 2;
                float b0 = __ldg(bias + col), b1 = __ldg(bias + col + 1);
                *(float2*)(out + (size_t)m * Cdim + col) =
                    make_float2(acc[mt][nt][0] + b0, acc[mt][nt][1] + b1);
                *(float2*)(out + (size_t)(m + 8) * Cdim + col) =
                    make_float2(acc[mt][nt][2] + b0, acc[mt][nt][3] + b1);
            }
        }
    }
}

// ---------------------------------------------------------------------------
// Tensor-core partial kv with register-double-buffered global loads.
// Tiles STS-transposed to [e][seq]/[d][seq] fp16 then proven non-trans
// ldmatrix GEMM (M=64 e, N=64 d, K=64 seq). Fused partial k_sum.
// ---------------------------------------------------------------------------
#define TROW 72

__global__ __launch_bounds__(128)
void kvp_tc()
{
    __shared__ __half skT[64][TROW];   // [e][seq]
    __shared__ __half svT[64][TROW];   // [d][seq]
    __shared__ float red[2][64];
    const int bh = blockIdx.x;
    const int prt = blockIdx.y;
    const int bb = bh >> 4, h = bh & 15;
    const int tid = threadIdx.x;
    const int lane = tid & 31;
    const int w = tid >> 5;
    const size_t base = (size_t)bb * Lseq * Cdim + h * En;
    const uint32_t skb = smem_u32(&skT[0][0]);
    const uint32_t svb = smem_u32(&svT[0][0]);

    const int a_row = (lane & 7) + ((lane >> 3) & 1) * 8;
    const int a_kq  = (lane >> 4) & 1;
    const int b_row = (lane & 7) + (lane >> 4) * 8;
    const int b_kq  = (lane >> 3) & 1;

    float acc[8][4] = {};
    float ks0 = 0.0f;
    const int e_id = tid & 63, zp = tid >> 6;

    // per-thread load coords (4 loads of uint4 per operand per tile)
    int lseq[4], loct[4];
    #pragma unroll
    for (int p = 0; p < 4; p++) {
        int id = tid + p * 128;
        lseq[p] = id & 63;
        loct[p] = id >> 6;
    }

    uint4 pk[4], pv[4];
    {
        const int n0 = (prt * 7) * 64;
        #pragma unroll
        for (int p = 0; p < 4; p++) {
            size_t g = base + (size_t)(n0 + lseq[p]) * Cdim + loct[p] * 8;
            pk[p] = *(const uint4*)(g_kh + g);
            pv[p] = *(const uint4*)(g_vh + g);
        }
    }

    for (int t = 0; t < 7; t++) {
        __syncthreads();
        #pragma unroll
        for (int p = 0; p < 4; p++) {
            const __half* hk = (const __half*)&pk[p];
            const __half* hv = (const __half*)&pv[p];
            #pragma unroll
            for (int j = 0; j < 8; j++) {
                skT[loct[p] * 8 + j][lseq[p]] = hk[j];
                svT[loct[p] * 8 + j][lseq[p]] = hv[j];
            }
        }
        __syncthreads();

        if (t + 1 < 7) {   // prefetch next tile
            const int n0 = (prt * 7 + t + 1) * 64;
            #pragma unroll
            for (int p = 0; p < 4; p++) {
                size_t g = base + (size_t)(n0 + lseq[p]) * Cdim + loct[p] * 8;
                pk[p] = *(const uint4*)(g_kh + g);
                pv[p] = *(const uint4*)(g_vh + g);
            }
        }

        #pragma unroll
        for (int ks = 0; ks < 4; ks++) {
            uint32_t ah[4];
            ldsm4(skb + (w * 16 + a_row) * (TROW * 2) + ks * 32 + a_kq * 16, ah);
            #pragma unroll
            for (int bt = 0; bt < 4; bt++) {
                uint32_t bh4[4];
                ldsm4(svb + (bt * 16 + b_row) * (TROW * 2) + ks * 32 + b_kq * 16, bh4);
                mma16816(acc[bt * 2],     ah, bh4[0], bh4[1]);
                mma16816(acc[bt * 2 + 1], ah, bh4[2], bh4[3]);
            }
        }
        #pragma unroll
        for (int s = 0; s < 32; s++)
            ks0 += __half2float(skT[e_id][zp * 32 + s]);
    }

    const int r4 = lane >> 2, c4 = lane & 3;
    float* dst = g_kvp[prt] + bh * (En * En);
    #pragma unroll
    for (int nt = 0; nt < 8; nt++) {
        int e = w * 16 + r4;
        int d = nt * 8 + c4 * 2;
        *(float2*)&dst[e * En + d]       = make_float2(acc[nt][0], acc[nt][1]);
        *(float2*)&dst[(e + 8) * En + d] = make_float2(acc[nt][2], acc[nt][3]);
    }

    __syncthreads();
    red[zp][e_id] = ks0;
    __syncthreads();
    if (tid < 64)
        g_ksp[prt][bh * En + tid] = red[0][tid] + red[1][tid];
}

// ---------------------------------------------------------------------------
// Wide reduce of partial kv/ksum (unchanged)
// ---------------------------------------------------------------------------
__global__ __launch_bounds__(256)
void kvred_kernel()
{
    const int gid = blockIdx.x * 256 + threadIdx.x;
    {
        int idx = gid * 4;
        float4 s = *(const float4*)&g_kvp[0][idx];
        #pragma unroll
        for (int p = 1; p < KVP; p++) {
            float4 t = *(const float4*)&g_kvp[p][idx];
            s.x += t.x; s.y += t.y; s.z += t.z; s.w += t.w;
        }
        *(float4*)&g_kv[idx] = s;
    }
    if (gid < 2048) {
        int idx = gid * 4;
        float4 s = *(const float4*)&g_ksp[0][idx];
        #pragma unroll
        for (int p = 1; p < KVP; p++) {
            float4 t = *(const float4*)&g_ksp[p][idx];
            s.x += t.x; s.y += t.y; s.z += t.z; s.w += t.w;
        }
        *(float4*)&g_ksum[idx] = s;
    }
}

// ---------------------------------------------------------------------------
// Tensor-core attn: out = (q_ @ kv) * z -> fp16. 4 token-tiles per block
// share one kv transpose. Proven non-trans ldmatrix patterns.
// grid (13, 128), 128 threads.
// ---------------------------------------------------------------------------
__global__ __launch_bounds__(128)
void attn_tc()
{
    __shared__ __half sq  [64][TROW];   // [token][e]
    __shared__ __half skvT[64][TROW];   // [d][e]
    __shared__ float sks[64];
    __shared__ float szp[2][64];
    __shared__ float sz[64];
    const int bh = blockIdx.y;
    const int bb = bh >> 4, h = bh & 15;
    const int tid = threadIdx.x;
    const int lane = tid & 31;
    const int w = tid >> 5;
    const uint32_t sqb = smem_u32(&sq[0][0]);
    const uint32_t skb = smem_u32(&skvT[0][0]);

    const int a_row = (lane & 7) + ((lane >> 3) & 1) * 8;
    const int a_kq  = (lane >> 4) & 1;
    const int b_row = (lane & 7) + (lane >> 4) * 8;
    const int b_kq  = (lane >> 3) & 1;

    // kv fp32 [e][d] -> fp16 transposed [d][e]
    #pragma unroll
    for (int p = 0; p < 8; p++) {
        int id = tid + p * 128;
        int e = id >> 4;
        int d0 = (id & 15) * 4;
        float4 v = *(const float4*)&g_kv[bh * (En * En) + e * En + d0];
        skvT[d0 + 0][e] = __float2half_rn(v.x);
        skvT[d0 + 1][e] = __float2half_rn(v.y);
        skvT[d0 + 2][e] = __float2half_rn(v.z);
        skvT[d0 + 3][e] = __float2half_rn(v.w);
    }
    if (tid < 16)
        *(float4*)&sks[tid * 4] = *(const float4*)&g_ksum[bh * En + tid * 4];

    const int tok_z = tid & 63, zp = tid >> 6;

    for (int t = 0; t < 4; t++) {
        const int tile = blockIdx.x * 4 + t;
        if (tile >= 49) break;
        const int n0 = tile * 64;

        __syncthreads();
        #pragma unroll
        for (int p = 0; p < 4; p++) {
            int id = tid + p * 128;
            int tok = id >> 3, oct = id & 7;
            size_t g = ((size_t)bb * Lseq + n0 + tok) * Cdim + h * En + oct * 8;
            *(uint4*)&sq[tok][oct * 8] = *(const uint4*)(g_qh + g);
        }
        __syncthreads();

        {
            float d = 0.0f;
            #pragma unroll
            for (int s = 0; s < 32; s++)
                d += __half2float(sq[tok_z][zp * 32 + s]) * sks[zp * 32 + s];
            szp[zp][tok_z] = d;
        }
        __syncthreads();
        if (tid < 64)
            sz[tid] = 1.0f / (szp[0][tid] + szp[1][tid] + EPS_V);
        __syncthreads();

        float acc[8][4] = {};
        #pragma unroll
        for (int ks = 0; ks < 4; ks++) {
            uint32_t ah[4];
            ldsm4(sqb + (w * 16 + a_row) * (TROW * 2) + ks * 32 + a_kq * 16, ah);
            #pragma unroll
            for (int bt = 0; bt < 4; bt++) {
                uint32_t bh4[4];
                ldsm4(skb + (bt * 16 + b_row) * (TROW * 2) + ks * 32 + b_kq * 16, bh4);
                mma16816(acc[bt * 2],     ah, bh4[0], bh4[1]);
                mma16816(acc[bt * 2 + 1], ah, bh4[2], bh4[3]);
            }
        }

        const int r4 = lane >> 2, c4 = lane & 3;
        #pragma unroll
        for (int nt = 0; nt < 8; nt++) {
            int trow = w * 16 + r4;
            int d = nt * 8 + c4 * 2;
            float z0 = sz[trow], z1 = sz[trow + 8];
            __half2 h01 = __floats2half2_rn(acc[nt][0] * z0, acc[nt][1] * z0);
            __half2 h23 = __floats2half2_rn(acc[nt][2] * z1, acc[nt][3] * z1);
            size_t g0 = ((size_t)bb * Lseq + n0 + trow) * Cdim + h * En + d;
            *(uint32_t*)(g_ah + g0)            = *(uint32_t*)&h01;
            *(uint32_t*)(g_ah + g0 + 8 * Cdim) = *(uint32_t*)&h23;
        }
    }
}

// ---------------------------------------------------------------------------
extern "C" void kernel_launch(void* const* d_in, const int* in_sizes, int n_in,
                              void* d_out, int out_size)
{
    const float* x      = (const float*)d_in[0];
    const float* w_qkv  = (const float*)d_in[1];
    const float* w_proj = (const float*)d_in[2];
    const float* b_proj = (const float*)d_in[3];
    float* out = (float*)d_out;

    cudaFuncSetAttribute(gemm_tc<0>, cudaFuncAttributeMaxDynamicSharedMemorySize, GEMM_SMEM);
    cudaFuncSetAttribute(gemm_tc<1>, cudaFuncAttributeMaxDynamicSharedMemorySize, GEMM_SMEM);

    __half *xh, *ah, *wqh, *wph;
    cudaGetSymbolAddress((void**)&xh,  g_xh);
    cudaGetSymbolAddress((void**)&ah,  g_ah);
    cudaGetSymbolAddress((void**)&wqh, g_wqh);
    cudaGetSymbolAddress((void**)&wph, g_wph);

    // 0) fused fp32 -> fp16 conversions
    {
        int total = N4X + N4WQ + N4WP;
        conv_all<<<(total + 255) / 256, 256>>>(
            (const float4*)x, (const float4*)w_qkv, (const float4*)w_proj);
    }

    // 1) qkv = x @ w_qkv^T, fused q/k/v split + relu+scale
    gemm_tc<0><<<dim3(24, 196), 128, GEMM_SMEM>>>(xh, wqh, nullptr, nullptr);
    // 2) partial kv (+ k_sum) on tensor cores, then wide reduce
    kvp_tc<<<dim3(128, KVP), 128>>>();
    kvred_kernel<<<512, 256>>>();
    // 3) out = (q_ @ kv) * z on tensor cores -> fp16
    attn_tc<<<dim3(13, 128), 128>>>();
    // 4) final = attn @ w_proj^T + b_proj
    gemm_tc<1><<<dim3(8, 196), 128, GEMM_SMEM>>>(ah, wph, b_proj, out);
}

// round 15
// speedup vs baseline: 8.2169x; 1.0382x over previous
#include <cuda_runtime.h>
#include <cuda_fp16.h>
#include <cstdint>

// Problem constants
#define Cdim 1024
#define Hn   16
#define En   64
#define Mtok 25088          // B*N
#define Lseq 3136           // f*N
#define NBGRP 8
#define SCALE_Q 0.125f
#define EPS_V   1e-6f
#define KVP  7              // kv sequence partitions

#define N4X  (Mtok * (Cdim / 4))
#define N4WQ (3072 * Cdim / 4)
#define N4WP (Cdim * Cdim / 4)

// Scratch (static device memory)
__device__ float g_kv  [NBGRP * Hn * En * En];
__device__ float g_ksum[NBGRP * Hn * En];
__device__ float g_kvp [KVP][NBGRP * Hn * En * En];
__device__ float g_ksp [KVP][NBGRP * Hn * En];
// fp16 tensors
__device__ __half g_xh[(size_t)Mtok * Cdim];
__device__ __half g_qh[(size_t)Mtok * Cdim];
__device__ __half g_kh[(size_t)Mtok * Cdim];
__device__ __half g_vh[(size_t)Mtok * Cdim];
__device__ __half g_ah[(size_t)Mtok * Cdim];
__device__ __half g_wqh[3072 * Cdim];
__device__ __half g_wph[Cdim * Cdim];

// ---------------------------------------------------------------------------
// Helpers
// ---------------------------------------------------------------------------
__device__ __forceinline__ uint32_t smem_u32(const void* p) {
    uint32_t a;
    asm("{ .reg .u64 t; cvta.to.shared.u64 t, %1; cvt.u32.u64 %0, t; }" : "=r"(a) : "l"(p));
    return a;
}

__device__ __forceinline__ void mma16816(float* d, const uint32_t* a,
                                         uint32_t b0, uint32_t b1) {
    asm volatile(
        "mma.sync.aligned.m16n8k16.row.col.f32.f16.f16.f32 "
        "{%0,%1,%2,%3}, {%4,%5,%6,%7}, {%8,%9}, {%0,%1,%2,%3};"
        : "+f"(d[0]), "+f"(d[1]), "+f"(d[2]), "+f"(d[3])
        : "r"(a[0]), "r"(a[1]), "r"(a[2]), "r"(a[3]), "r"(b0), "r"(b1));
}

__device__ __forceinline__ void ldsm4(uint32_t addr, uint32_t* r) {
    asm volatile("ldmatrix.sync.aligned.m8n8.x4.shared.b16 {%0,%1,%2,%3}, [%4];"
                 : "=r"(r[0]), "=r"(r[1]), "=r"(r[2]), "=r"(r[3]) : "r"(addr));
}

#define CP16(dst, src) \
    asm volatile("cp.async.cg.shared.global [%0], [%1], 16;" :: "r"(dst), "l"(src))
#define CP_COMMIT() asm volatile("cp.async.commit_group;" ::: "memory")
#define CP_WAIT1()  asm volatile("cp.async.wait_group 1;" ::: "memory")

// Swizzled byte offset for 128-byte rows: quad (16B) XOR row&7
__device__ __forceinline__ uint32_t swz(uint32_t row, uint32_t quad) {
    return (row << 7) + ((quad ^ (row & 7)) << 4);
}

// ---------------------------------------------------------------------------
// Fused fp32 -> fp16 conversion (x, w_qkv, w_proj in one launch)
// ---------------------------------------------------------------------------
__global__ __launch_bounds__(256)
void conv_all(const float4* __restrict__ x, const float4* __restrict__ wq,
              const float4* __restrict__ wp)
{
    int i = blockIdx.x * 256 + threadIdx.x;
    const float4* src; __half* dst; int j;
    if (i < N4X)                { src = x;  dst = g_xh;  j = i; }
    else if (i < N4X + N4WQ)    { src = wq; dst = g_wqh; j = i - N4X; }
    else if (i < N4X + N4WQ + N4WP) { src = wp; dst = g_wph; j = i - N4X - N4WQ; }
    else return;
    float4 v = src[j];
    __half2 h01 = __floats2half2_rn(v.x, v.y);
    __half2 h23 = __floats2half2_rn(v.z, v.w);
    *(uint2*)&dst[(size_t)j * 4] = make_uint2(*(uint32_t*)&h01, *(uint32_t*)&h23);
}

// ---------------------------------------------------------------------------
// FP16 tensor-core NT GEMM. Block 128x128, K-chunk 64, 4 warps (2m x 2n),
// warp tile 64x64. cp.async for chunk c+2 SPREAD one pair per MMA iteration
// (no post-sync LSU burst); A frags double-buffered per k-step, B per
// iteration. NSTG=3, wait_group 1, 2 CTAs/SM.
// ---------------------------------------------------------------------------
#define ARR_SZ 16384
#define STG_B (2 * ARR_SZ)
#define NSTG 3
#define GEMM_SMEM (NSTG * STG_B)

template<int MODE>
__global__ __launch_bounds__(128, 2)
void gemm_tc(const __half* __restrict__ A_g,
             const __half* __restrict__ W_g,
             const float* __restrict__ bias, float* __restrict__ out)
{
    extern __shared__ __align__(128) char smem[];
    const uint32_t sbase = smem_u32(smem);
    const int tid  = threadIdx.x;
    const int lane = tid & 31;
    const int w    = tid >> 5;
    const int wm   = w & 1;
    const int wn   = w >> 1;
    const int m0 = blockIdx.y * 128;
    const int n0 = blockIdx.x * 128;

    const int a_row = (lane & 7) + ((lane >> 3) & 1) * 8;
    const int a_kq  = (lane >> 4) & 1;
    const int b_row = (lane & 7) + (lane >> 4) * 8;
    const int b_kq  = (lane >> 3) & 1;

    auto issue = [&](int c) {
        const uint32_t st = sbase + (c % NSTG) * STG_B;
        const int k0 = c * 64;
        #pragma unroll
        for (int p = 0; p < 8; p++) {
            int id = tid + p * 128;
            int row = id >> 3, quad = id & 7;
            uint32_t so = swz(row, quad);
            CP16(st + so, A_g + (size_t)(m0 + row) * Cdim + k0 + quad * 8);
            CP16(st + ARR_SZ + so, W_g + (size_t)(n0 + row) * Cdim + k0 + quad * 8);
        }
    };

    float acc[4][8][4];
    #pragma unroll
    for (int mt = 0; mt < 4; mt++)
        #pragma unroll
        for (int nt = 0; nt < 8; nt++)
            #pragma unroll
            for (int r = 0; r < 4; r++) acc[mt][nt][r] = 0.0f;

    issue(0); CP_COMMIT();
    issue(1); CP_COMMIT();

    for (int c = 0; c < 16; c++) {
        CP_WAIT1();
        __syncthreads();

        const bool pf = (c + 2 < 16);
        const uint32_t st2 = sbase + ((c + 2) % NSTG) * STG_B;
        const int k02 = (c + 2) * 64;

        const uint32_t st = sbase + (c % NSTG) * STG_B;
        const uint32_t sA = st, sB = st + ARR_SZ;

        // A double-buffer at ks granularity; B double-buffer per iteration
        uint32_t ah[2][4][4];
        #pragma unroll
        for (int mt = 0; mt < 4; mt++) {
            uint32_t row = wm * 64 + mt * 16 + a_row;
            ldsm4(sA + swz(row, 0 * 2 + a_kq), ah[0][mt]);
        }
        uint32_t bf[2][4];
        {
            uint32_t row = wn * 64 + 0 * 16 + b_row;
            ldsm4(sB + swz(row, 0 * 2 + b_kq), bf[0]);
        }
        #pragma unroll
        for (int it = 0; it < 16; it++) {
            const int ks = it >> 2, bt = it & 3;
            // spread next-chunk cp.async: one A/B pair per iteration (8 total)
            if (pf && it < 8) {
                int id = tid + it * 128;
                int row = id >> 3, quad = id & 7;
                uint32_t so = swz(row, quad);
                CP16(st2 + so, A_g + (size_t)(m0 + row) * Cdim + k02 + quad * 8);
                CP16(st2 + ARR_SZ + so, W_g + (size_t)(n0 + row) * Cdim + k02 + quad * 8);
            }
            // prefetch next B fragment
            if (it + 1 < 16) {
                const int ks2 = (it + 1) >> 2, bt2 = (it + 1) & 3;
                uint32_t row = wn * 64 + bt2 * 16 + b_row;
                ldsm4(sB + swz(row, ks2 * 2 + b_kq), bf[(it + 1) & 1]);
            }
            // prefetch one A fragment of ks+1 per iteration
            if (ks < 3) {
                const int mt = bt;
                uint32_t row = wm * 64 + mt * 16 + a_row;
                ldsm4(sA + swz(row, (ks + 1) * 2 + a_kq), ah[(ks + 1) & 1][mt]);
            }
            const uint32_t* bh = bf[it & 1];
            #pragma unroll
            for (int half = 0; half < 2; half++) {
                const int nt = bt * 2 + half;
                #pragma unroll
                for (int mt = 0; mt < 4; mt++)
                    mma16816(acc[mt][nt], ah[ks & 1][mt], bh[half * 2], bh[half * 2 + 1]);
            }
        }
        CP_COMMIT();
    }

    const int r4 = lane >> 2, c4 = lane & 3;
    if (MODE == 0) {
        const int sN = n0 >> 10;                 // 0:q 1:k 2:v
        __half* dst = (sN == 0) ? g_qh : (sN == 1) ? g_kh : g_vh;
        const int colb = (n0 & 1023) + wn * 64;
        #pragma unroll
        for (int mt = 0; mt < 4; mt++) {
            #pragma unroll
            for (int nt = 0; nt < 8; nt++) {
                float v0 = acc[mt][nt][0], v1 = acc[mt][nt][1];
                float v2 = acc[mt][nt][2], v3 = acc[mt][nt][3];
                if (sN < 2) {
                    v0 = fmaxf(v0, 0.0f) + SCALE_Q;
                    v1 = fmaxf(v1, 0.0f) + SCALE_Q;
                    v2 = fmaxf(v2, 0.0f) + SCALE_Q;
                    v3 = fmaxf(v3, 0.0f) + SCALE_Q;
                }
                int m = m0 + wm * 64 + mt * 16 + r4;
                int col = colb + nt * 8 + c4 * 2;
                __half2 h01 = __floats2half2_rn(v0, v1);
                __half2 h23 = __floats2half2_rn(v2, v3);
                *(uint32_t*)(dst + (size_t)m * Cdim + col)       = *(uint32_t*)&h01;
                *(uint32_t*)(dst + (size_t)(m + 8) * Cdim + col) = *(uint32_t*)&h23;
            }
        }
    } else {
        #pragma unroll
        for (int mt = 0; mt < 4; mt++) {
            #pragma unroll
            for (int nt = 0; nt < 8; nt++) {
                int m = m0 + wm * 64 + mt * 16 + r4;
                int col = n0 + wn * 64 + nt * 8 + c4 * 2;
                float b0 = __ldg(bias + col), b1 = __ldg(bias + col + 1);
                *(float2*)(out + (size_t)m * Cdim + col) =
                    make_float2(acc[mt][nt][0] + b0, acc[mt][nt][1] + b1);
                *(float2*)(out + (size_t)(m + 8) * Cdim + col) =
                    make_float2(acc[mt][nt][2] + b0, acc[mt][nt][3] + b1);
            }
        }
    }
}

// ---------------------------------------------------------------------------
// Tensor-core partial kv with register-double-buffered global loads.
// ---------------------------------------------------------------------------
#define TROW 72

__global__ __launch_bounds__(128)
void kvp_tc()
{
    __shared__ __half skT[64][TROW];   // [e][seq]
    __shared__ __half svT[64][TROW];   // [d][seq]
    __shared__ float red[2][64];
    const int bh = blockIdx.x;
    const int prt = blockIdx.y;
    const int bb = bh >> 4, h = bh & 15;
    const int tid = threadIdx.x;
    const int lane = tid & 31;
    const int w = tid >> 5;
    const size_t base = (size_t)bb * Lseq * Cdim + h * En;
    const uint32_t skb = smem_u32(&skT[0][0]);
    const uint32_t svb = smem_u32(&svT[0][0]);

    const int a_row = (lane & 7) + ((lane >> 3) & 1) * 8;
    const int a_kq  = (lane >> 4) & 1;
    const int b_row = (lane & 7) + (lane >> 4) * 8;
    const int b_kq  = (lane >> 3) & 1;

    float acc[8][4] = {};
    float ks0 = 0.0f;
    const int e_id = tid & 63, zp = tid >> 6;

    int lseq[4], loct[4];
    #pragma unroll
    for (int p = 0; p < 4; p++) {
        int id = tid + p * 128;
        lseq[p] = id & 63;
        loct[p] = id >> 6;
    }

    uint4 pk[4], pv[4];
    {
        const int n0 = (prt * 7) * 64;
        #pragma unroll
        for (int p = 0; p < 4; p++) {
            size_t g = base + (size_t)(n0 + lseq[p]) * Cdim + loct[p] * 8;
            pk[p] = *(const uint4*)(g_kh + g);
            pv[p] = *(const uint4*)(g_vh + g);
        }
    }

    for (int t = 0; t < 7; t++) {
        __syncthreads();
        #pragma unroll
        for (int p = 0; p < 4; p++) {
            const __half* hk = (const __half*)&pk[p];
            const __half* hv = (const __half*)&pv[p];
            #pragma unroll
            for (int j = 0; j < 8; j++) {
                skT[loct[p] * 8 + j][lseq[p]] = hk[j];
                svT[loct[p] * 8 + j][lseq[p]] = hv[j];
            }
        }
        __syncthreads();

        if (t + 1 < 7) {
            const int n0 = (prt * 7 + t + 1) * 64;
            #pragma unroll
            for (int p = 0; p < 4; p++) {
                size_t g = base + (size_t)(n0 + lseq[p]) * Cdim + loct[p] * 8;
                pk[p] = *(const uint4*)(g_kh + g);
                pv[p] = *(const uint4*)(g_vh + g);
            }
        }

        #pragma unroll
        for (int ks = 0; ks < 4; ks++) {
            uint32_t ah[4];
            ldsm4(skb + (w * 16 + a_row) * (TROW * 2) + ks * 32 + a_kq * 16, ah);
            #pragma unroll
            for (int bt = 0; bt < 4; bt++) {
                uint32_t bh4[4];
                ldsm4(svb + (bt * 16 + b_row) * (TROW * 2) + ks * 32 + b_kq * 16, bh4);
                mma16816(acc[bt * 2],     ah, bh4[0], bh4[1]);
                mma16816(acc[bt * 2 + 1], ah, bh4[2], bh4[3]);
            }
        }
        #pragma unroll
        for (int s = 0; s < 32; s++)
            ks0 += __half2float(skT[e_id][zp * 32 + s]);
    }

    const int r4 = lane >> 2, c4 = lane & 3;
    float* dst = g_kvp[prt] + bh * (En * En);
    #pragma unroll
    for (int nt = 0; nt < 8; nt++) {
        int e = w * 16 + r4;
        int d = nt * 8 + c4 * 2;
        *(float2*)&dst[e * En + d]       = make_float2(acc[nt][0], acc[nt][1]);
        *(float2*)&dst[(e + 8) * En + d] = make_float2(acc[nt][2], acc[nt][3]);
    }

    __syncthreads();
    red[zp][e_id] = ks0;
    __syncthreads();
    if (tid < 64)
        g_ksp[prt][bh * En + tid] = red[0][tid] + red[1][tid];
}

// ---------------------------------------------------------------------------
// Wide reduce of partial kv/ksum (unchanged)
// ---------------------------------------------------------------------------
__global__ __launch_bounds__(256)
void kvred_kernel()
{
    const int gid = blockIdx.x * 256 + threadIdx.x;
    {
        int idx = gid * 4;
        float4 s = *(const float4*)&g_kvp[0][idx];
        #pragma unroll
        for (int p = 1; p < KVP; p++) {
            float4 t = *(const float4*)&g_kvp[p][idx];
            s.x += t.x; s.y += t.y; s.z += t.z; s.w += t.w;
        }
        *(float4*)&g_kv[idx] = s;
    }
    if (gid < 2048) {
        int idx = gid * 4;
        float4 s = *(const float4*)&g_ksp[0][idx];
        #pragma unroll
        for (int p = 1; p < KVP; p++) {
            float4 t = *(const float4*)&g_ksp[p][idx];
            s.x += t.x; s.y += t.y; s.z += t.z; s.w += t.w;
        }
        *(float4*)&g_ksum[idx] = s;
    }
}

// ---------------------------------------------------------------------------
// Tensor-core attn: out = (q_ @ kv) * z -> fp16. 4 token-tiles per block.
// ---------------------------------------------------------------------------
__global__ __launch_bounds__(128)
void attn_tc()
{
    __shared__ __half sq  [64][TROW];   // [token][e]
    __shared__ __half skvT[64][TROW];   // [d][e]
    __shared__ float sks[64];
    __shared__ float szp[2][64];
    __shared__ float sz[64];
    const int bh = blockIdx.y;
    const int bb = bh >> 4, h = bh & 15;
    const int tid = threadIdx.x;
    const int lane = tid & 31;
    const int w = tid >> 5;
    const uint32_t sqb = smem_u32(&sq[0][0]);
    const uint32_t skb = smem_u32(&skvT[0][0]);

    const int a_row = (lane & 7) + ((lane >> 3) & 1) * 8;
    const int a_kq  = (lane >> 4) & 1;
    const int b_row = (lane & 7) + (lane >> 4) * 8;
    const int b_kq  = (lane >> 3) & 1;

    #pragma unroll
    for (int p = 0; p < 8; p++) {
        int id = tid + p * 128;
        int e = id >> 4;
        int d0 = (id & 15) * 4;
        float4 v = *(const float4*)&g_kv[bh * (En * En) + e * En + d0];
        skvT[d0 + 0][e] = __float2half_rn(v.x);
        skvT[d0 + 1][e] = __float2half_rn(v.y);
        skvT[d0 + 2][e] = __float2half_rn(v.z);
        skvT[d0 + 3][e] = __float2half_rn(v.w);
    }
    if (tid < 16)
        *(float4*)&sks[tid * 4] = *(const float4*)&g_ksum[bh * En + tid * 4];

    const int tok_z = tid & 63, zp = tid >> 6;

    for (int t = 0; t < 4; t++) {
        const int tile = blockIdx.x * 4 + t;
        if (tile >= 49) break;
        const int n0 = tile * 64;

        __syncthreads();
        #pragma unroll
        for (int p = 0; p < 4; p++) {
            int id = tid + p * 128;
            int tok = id >> 3, oct = id & 7;
            size_t g = ((size_t)bb * Lseq + n0 + tok) * Cdim + h * En + oct * 8;
            *(uint4*)&sq[tok][oct * 8] = *(const uint4*)(g_qh + g);
        }
        __syncthreads();

        {
            float d = 0.0f;
            #pragma unroll
            for (int s = 0; s < 32; s++)
                d += __half2float(sq[tok_z][zp * 32 + s]) * sks[zp * 32 + s];
            szp[zp][tok_z] = d;
        }
        __syncthreads();
        if (tid < 64)
            sz[tid] = 1.0f / (szp[0][tid] + szp[1][tid] + EPS_V);
        __syncthreads();

        float acc[8][4] = {};
        #pragma unroll
        for (int ks = 0; ks < 4; ks++) {
            uint32_t ah[4];
            ldsm4(sqb + (w * 16 + a_row) * (TROW * 2) + ks * 32 + a_kq * 16, ah);
            #pragma unroll
            for (int bt = 0; bt < 4; bt++) {
                uint32_t bh4[4];
                ldsm4(skb + (bt * 16 + b_row) * (TROW * 2) + ks * 32 + b_kq * 16, bh4);
                mma16816(acc[bt * 2],     ah, bh4[0], bh4[1]);
                mma16816(acc[bt * 2 + 1], ah, bh4[2], bh4[3]);
            }
        }

        const int r4 = lane >> 2, c4 = lane & 3;
        #pragma unroll
        for (int nt = 0; nt < 8; nt++) {
            int trow = w * 16 + r4;
            int d = nt * 8 + c4 * 2;
            float z0 = sz[trow], z1 = sz[trow + 8];
            __half2 h01 = __floats2half2_rn(acc[nt][0] * z0, acc[nt][1] * z0);
            __half2 h23 = __floats2half2_rn(acc[nt][2] * z1, acc[nt][3] * z1);
            size_t g0 = ((size_t)bb * Lseq + n0 + trow) * Cdim + h * En + d;
            *(uint32_t*)(g_ah + g0)            = *(uint32_t*)&h01;
            *(uint32_t*)(g_ah + g0 + 8 * Cdim) = *(uint32_t*)&h23;
        }
    }
}

// ---------------------------------------------------------------------------
extern "C" void kernel_launch(void* const* d_in, const int* in_sizes, int n_in,
                              void* d_out, int out_size)
{
    const float* x      = (const float*)d_in[0];
    const float* w_qkv  = (const float*)d_in[1];
    const float* w_proj = (const float*)d_in[2];
    const float* b_proj = (const float*)d_in[3];
    float* out = (float*)d_out;

    cudaFuncSetAttribute(gemm_tc<0>, cudaFuncAttributeMaxDynamicSharedMemorySize, GEMM_SMEM);
    cudaFuncSetAttribute(gemm_tc<1>, cudaFuncAttributeMaxDynamicSharedMemorySize, GEMM_SMEM);

    __half *xh, *ah, *wqh, *wph;
    cudaGetSymbolAddress((void**)&xh,  g_xh);
    cudaGetSymbolAddress((void**)&ah,  g_ah);
    cudaGetSymbolAddress((void**)&wqh, g_wqh);
    cudaGetSymbolAddress((void**)&wph, g_wph);

    // 0) fused fp32 -> fp16 conversions
    {
        int total = N4X + N4WQ + N4WP;
        conv_all<<<(total + 255) / 256, 256>>>(
            (const float4*)x, (const float4*)w_qkv, (const float4*)w_proj);
    }

    // 1) qkv = x @ w_qkv^T, fused q/k/v split + relu+scale
    gemm_tc<0><<<dim3(24, 196), 128, GEMM_SMEM>>>(xh, wqh, nullptr, nullptr);
    // 2) partial kv (+ k_sum) on tensor cores, then wide reduce
    kvp_tc<<<dim3(128, KVP), 128>>>();
    kvred_kernel<<<512, 256>>>();
    // 3) out = (q_ @ kv) * z on tensor cores -> fp16
    attn_tc<<<dim3(13, 128), 128>>>();
    // 4) final = attn @ w_proj^T + b_proj
    gemm_tc<1><<<dim3(8, 196), 128, GEMM_SMEM>>>(ah, wph, b_proj, out);
}